// round 12
// baseline (speedup 1.0000x reference)
#include <cuda_runtime.h>
#include <cuda_bf16.h>
#include <math.h>
#include <stdint.h>

#define BSZ 4
#define HDIM 256
#define WDIM 256
#define HW 65536

// ---------------- scratch (device globals) ----------------
__device__ float g_fre1[(size_t)BSZ * 64 * HW];
__device__ float g_spa1[(size_t)BSZ * 64 * HW];
__device__ float g_tmp [(size_t)BSZ * 64 * HW];
__device__ float g_q   [(size_t)BSZ * 64 * HW];
__device__ float g_fre2[(size_t)BSZ * 64 * HW];
__device__ float g_spa2[(size_t)BSZ * 64 * HW];
__device__ float g_kv0 [(size_t)BSZ * 128 * HW];
__device__ float g_kv  [(size_t)BSZ * 128 * HW];
__device__ float g_stats[2560];
__device__ float g_Meff[BSZ * 64 * 64];
// NHWC bf16 hi/lo slots: 0=fre 1=spa 2=fre2 3=spa2 4=t1
__device__ __nv_bfloat16 g_nh_hi[5][(size_t)BSZ * HW * 64];
__device__ __nv_bfloat16 g_nh_lo[5][(size_t)BSZ * HW * 64];
// packed weights (hi-pair, lo-pair)
__device__ uint2 g_wpk2[110592];

// ---------------- mma.sync / cp.async helpers (baseline sm_80+, no 'a' arch) ----------------
__device__ __forceinline__ uint32_t smem_u32(const void* p) {
    uint32_t a;
    asm("{ .reg .u64 t; cvta.to.shared.u64 t, %1; cvt.u32.u64 %0, t; }" : "=r"(a) : "l"(p));
    return a;
}
__device__ __forceinline__ void ldmA(uint32_t r[4], uint32_t a) {
    asm volatile("ldmatrix.sync.aligned.m8n8.x4.shared.b16 {%0,%1,%2,%3}, [%4];"
                 : "=r"(r[0]), "=r"(r[1]), "=r"(r[2]), "=r"(r[3]) : "r"(a));
}
__device__ __forceinline__ void ldmT(uint32_t r[4], uint32_t a) {
    asm volatile("ldmatrix.sync.aligned.m8n8.x4.trans.shared.b16 {%0,%1,%2,%3}, [%4];"
                 : "=r"(r[0]), "=r"(r[1]), "=r"(r[2]), "=r"(r[3]) : "r"(a));
}
__device__ __forceinline__ void mma16816(float* c, const uint32_t* a, const uint32_t* b) {
    asm volatile(
        "mma.sync.aligned.m16n8k16.row.col.f32.bf16.bf16.f32 "
        "{%0,%1,%2,%3}, {%4,%5,%6,%7}, {%8,%9}, {%0,%1,%2,%3};"
        : "+f"(c[0]), "+f"(c[1]), "+f"(c[2]), "+f"(c[3])
        : "r"(a[0]), "r"(a[1]), "r"(a[2]), "r"(a[3]), "r"(b[0]), "r"(b[1]));
}
__device__ __forceinline__ void cpa16(uint32_t d, const void* s, int pb) {
    asm volatile("cp.async.cg.shared.global [%0], [%1], 16, %2;"
                 :: "r"(d), "l"(s), "r"(pb) : "memory");
}
__device__ __forceinline__ void cpa_commit() {
    asm volatile("cp.async.commit_group;" ::: "memory");
}
__device__ __forceinline__ void cpa_wait1() {
    asm volatile("cp.async.wait_group 1;" ::: "memory");
}
__device__ __forceinline__ void cpa_wait0() {
    asm volatile("cp.async.wait_group 0;" ::: "memory");
}
__device__ __forceinline__ void split4(float4 v, uint2& hi, uint2& lo) {
    __nv_bfloat16 h0 = __float2bfloat16(v.x), h1 = __float2bfloat16(v.y);
    __nv_bfloat16 h2 = __float2bfloat16(v.z), h3 = __float2bfloat16(v.w);
    __nv_bfloat16 l0 = __float2bfloat16(v.x - __bfloat162float(h0));
    __nv_bfloat16 l1 = __float2bfloat16(v.y - __bfloat162float(h1));
    __nv_bfloat16 l2 = __float2bfloat16(v.z - __bfloat162float(h2));
    __nv_bfloat16 l3 = __float2bfloat16(v.w - __bfloat162float(h3));
    hi.x = ((uint32_t)__bfloat16_as_ushort(h1) << 16) | __bfloat16_as_ushort(h0);
    hi.y = ((uint32_t)__bfloat16_as_ushort(h3) << 16) | __bfloat16_as_ushort(h2);
    lo.x = ((uint32_t)__bfloat16_as_ushort(l1) << 16) | __bfloat16_as_ushort(l0);
    lo.y = ((uint32_t)__bfloat16_as_ushort(l3) << 16) | __bfloat16_as_ushort(l2);
}

__global__ void zero_k(float* p, int n) {
    int i = blockIdx.x * 256 + threadIdx.x;
    if (i < n) p[i] = 0.f;
}
__device__ __forceinline__ float fix_nan(float x) { return isfinite(x) ? x : 1e-5f; }
__device__ __forceinline__ float sigm(float x) { return 1.f / (1.f + expf(-x)); }

// ---------------- NCHW fp32 -> NHWC bf16 hi/lo ----------------
__global__ void nchw2nhwc_k(const float* __restrict__ in,
                            __nv_bfloat16* __restrict__ ohi,
                            __nv_bfloat16* __restrict__ olo) {
    __shared__ float s[32][33];
    const int b = blockIdx.z, ch0 = blockIdx.y * 32, p0 = blockIdx.x * 32;
    const int lx = threadIdx.x & 31, ly = threadIdx.x >> 5;
#pragma unroll
    for (int i = 0; i < 4; ++i) {
        int c = ly + i * 8;
        s[c][lx] = in[((size_t)(b * 64 + ch0 + c)) * HW + p0 + lx];
    }
    __syncthreads();
#pragma unroll
    for (int i = 0; i < 4; ++i) {
        int p = ly + i * 8;
        float v = s[lx][p];
        __nv_bfloat16 h = __float2bfloat16(v);
        size_t idx = ((size_t)b * HW + p0 + p) * 64 + ch0 + lx;
        ohi[idx] = h;
        olo[idx] = __float2bfloat16(v - __bfloat162float(h));
    }
}

// ---------------- weight pack: OIHW -> [tap][chunk16][co][8] uint2 {hi2, lo2} ----------------
__global__ void wpack_k(const float* __restrict__ W, uint2* __restrict__ pk, int CIN, int CO) {
    int NCH = CIN >> 4;
    int n = 9 * NCH * CO * 8;
    int i = blockIdx.x * 256 + threadIdx.x;
    if (i >= n) return;
    int j = i & 7;
    int t2 = i >> 3;
    int co = t2 % CO;
    int t3 = t2 / CO;
    int chv = t3 % NCH, tap = t3 / NCH;
    int ci = chv * 16 + 2 * j;
    float w0 = W[((size_t)co * CIN + ci) * 9 + tap];
    float w1 = W[((size_t)co * CIN + ci + 1) * 9 + tap];
    __nv_bfloat16 h0 = __float2bfloat16(w0), h1 = __float2bfloat16(w1);
    __nv_bfloat16 l0 = __float2bfloat16(w0 - __bfloat162float(h0));
    __nv_bfloat16 l1 = __float2bfloat16(w1 - __bfloat162float(h1));
    uint2 o;
    o.x = ((uint32_t)__bfloat16_as_ushort(h1) << 16) | (uint32_t)__bfloat16_as_ushort(h0);
    o.y = ((uint32_t)__bfloat16_as_ushort(l1) << 16) | (uint32_t)__bfloat16_as_ushort(l0);
    pk[i] = o;
}

// ---------------- mma.sync bf16 3-term implicit-GEMM 3x3 conv ----------------
// Tile: M=128 px, N=CO. A staged per (dy, ch-group) via cp.async into a
// 2-deep smem ring; dx via ldmatrix offset. Each warp owns 64 couts and a
// 16*NWN px slice (2 ldmatrix feed 24 MMAs — halves LDS traffic).
#define GC_BUF 37440                 // 130 px * 144 B * 2 (hi+lo)
#define GC_SMEM (2 * GC_BUF)         // 74880
#define LOOFF 18720                  // 130 * 144

__device__ __forceinline__ void gc_stage(const __nv_bfloat16* __restrict__ shi,
                                         const __nv_bfloat16* __restrict__ slo,
                                         int b, int gy, bool yok, int xbase,
                                         uint32_t dst, int tid) {
    const int gyc = yok ? gy : 0;
    for (int idx = tid; idx < 260; idx += 256) {
        const int px = idx >> 1, q = idx & 1;
        const int gx = xbase + px - 1;
        const bool ok = yok && gx >= 0 && gx < WDIM;
        const int gxc = (gx >= 0 && gx < WDIM) ? gx : 0;
        const int pb = ok ? 16 : 0;
        size_t off = ((size_t)b * HW + (size_t)gyc * WDIM + gxc) * 64 + q * 32;
        const char* ph = (const char*)(shi + off);
        const char* pl = (const char*)(slo + off);
        uint32_t dh = dst + px * 144 + q * 64;
        uint32_t dl = dst + LOOFF + px * 144 + q * 64;
#pragma unroll
        for (int i = 0; i < 4; ++i) {
            cpa16(dh + i * 16, ph + i * 16, pb);
            cpa16(dl + i * 16, pl + i * 16, pb);
        }
    }
    cpa_commit();
}

template <int CIN, int CO, bool SIG, bool FINAL, bool NCHWOUT, bool NHWCOUT, int MINB>
__global__ void __launch_bounds__(256, MINB)
gconv_k(const __nv_bfloat16* __restrict__ sAhi, const __nv_bfloat16* __restrict__ sAlo,
        const __nv_bfloat16* __restrict__ sBhi, const __nv_bfloat16* __restrict__ sBlo,
        const uint2* __restrict__ wb, const float* __restrict__ bias,
        float* __restrict__ outc,
        __nv_bfloat16* __restrict__ onhi, __nv_bfloat16* __restrict__ onlo,
        const float* __restrict__ resA, const float* __restrict__ resB) {
    extern __shared__ char smem[];
    constexpr int NGRP = CIN / 64;
    constexpr int NWN = CO / 64;        // 1 or 2 warps along N
    constexpr int NWM = 8 / NWN;        // 8 or 4 warps along M
    constexpr int MPW = 128 / NWM;      // 16 or 32 px per warp
    constexpr int MT  = MPW / 16;       // 1 or 2
    const int NSTG = 3 * NGRP;

    const int tid = threadIdx.x, wid = tid >> 5, lane = tid & 31;
    const int warpN = wid % NWN, warpM = wid / NWN;
    const int b = blockIdx.z, y = blockIdx.y, xbase = blockIdx.x * 128;
    const int g = lane >> 2, tig = lane & 3;
    const uint32_t sb = smem_u32(smem);

    float acc[MT][8][4];
#pragma unroll
    for (int mt = 0; mt < MT; ++mt)
#pragma unroll
        for (int nt = 0; nt < 8; ++nt)
#pragma unroll
            for (int q = 0; q < 4; ++q) acc[mt][nt][q] = 0.f;

    // prologue: issue stage 0 into buf 0
    {
        const int gy = y - 1;
        gc_stage(sAhi, sAlo, b, gy, (gy >= 0) && (gy < HDIM), xbase, sb, tid);
    }

    for (int st = 0; st < NSTG; ++st) {
        __syncthreads();   // all warps done with buf[(st+1)&1] (computed at st-1)
        if (st + 1 < NSTG) {
            const int dyN = (st + 1) / NGRP, grpN = (st + 1) % NGRP;
            const int gyN = y + dyN - 1;
            gc_stage(grpN ? sBhi : sAhi, grpN ? sBlo : sAlo, b, gyN,
                     (gyN >= 0) && (gyN < HDIM), xbase,
                     sb + ((st + 1) & 1) * GC_BUF, tid);
            cpa_wait1();
        } else {
            cpa_wait0();
        }
        __syncthreads();   // staged data for st visible

        const int dyI = st / NGRP, grp = st % NGRP;
        const uint32_t sbuf = sb + (st & 1) * GC_BUF;
#pragma unroll
        for (int dxI = 0; dxI < 3; ++dxI) {
            const int tap = dyI * 3 + dxI;
            const uint2* wt = wb + (size_t)(tap * (CIN / 16) + grp * 4) * CO * 8;
#pragma unroll
            for (int ch = 0; ch < 4; ++ch) {
                const uint2* wc = wt + (size_t)ch * CO * 8;
                uint32_t ah[MT][4], al[MT][4];
#pragma unroll
                for (int mt = 0; mt < MT; ++mt) {
                    const int pxl = warpM * MPW + mt * 16 + (lane & 15) + dxI;
                    uint32_t addr = sbuf + pxl * 144 + ch * 32 + ((lane >> 4) & 1) * 16;
                    ldmA(ah[mt], addr);
                    ldmA(al[mt], addr + LOOFF);
                }
#pragma unroll
                for (int half = 0; half < 2; ++half) {
                    uint32_t bh[4][2], bl[4][2];
#pragma unroll
                    for (int k = 0; k < 4; ++k) {
                        int n = warpN * 64 + (half * 4 + k) * 8 + g;
                        uint2 v0 = __ldg(&wc[n * 8 + tig]);
                        uint2 v1 = __ldg(&wc[n * 8 + tig + 4]);
                        bh[k][0] = v0.x; bl[k][0] = v0.y;
                        bh[k][1] = v1.x; bl[k][1] = v1.y;
                    }
#pragma unroll
                    for (int mt = 0; mt < MT; ++mt)
#pragma unroll
                        for (int k = 0; k < 4; ++k) {
                            float* a = acc[mt][half * 4 + k];
                            mma16816(a, ah[mt], bh[k]);
                            mma16816(a, al[mt], bh[k]);
                            mma16816(a, ah[mt], bl[k]);
                        }
                }
            }
        }
    }

    // ---------------- epilogue through smem ----------------
    float* s_out = (float*)smem;  // [32 co][132 px]
    for (int co0 = 0; co0 < CO; co0 += 32) {
        __syncthreads();
        if (NWN == 1 || warpN == (co0 >> 6)) {
            const int ntb = (co0 & 63) >> 3;
#pragma unroll
            for (int mt = 0; mt < MT; ++mt) {
                const int px = warpM * MPW + mt * 16 + g;
#pragma unroll
                for (int k = 0; k < 4; ++k) {
                    const int cl = k * 8 + tig * 2;
                    const float* a = acc[mt][ntb + k];
                    s_out[cl * 132 + px]           = a[0];
                    s_out[(cl + 1) * 132 + px]     = a[1];
                    s_out[cl * 132 + px + 8]       = a[2];
                    s_out[(cl + 1) * 132 + px + 8] = a[3];
                }
            }
        }
        __syncthreads();
        if (FINAL) {
            const int cl = tid >> 3, px0 = (tid & 7) * 16;
            const int c = (co0 + cl) & 63;
            const bool second = (co0 + cl) >= 64;
            const float bv = __ldg(&bias[co0 + cl]);
            const float* res = second ? resB : resA;
            size_t off = ((size_t)(b * 64 + c)) * HW + (size_t)y * WDIM + xbase + px0;
#pragma unroll
            for (int i = 0; i < 16; i += 4) {
                float4 rv = *(const float4*)(res + off + i);
                float4 o;
                o.x = sigm(s_out[cl * 132 + px0 + i]     + bv) * rv.x;
                o.y = sigm(s_out[cl * 132 + px0 + i + 1] + bv) * rv.y;
                o.z = sigm(s_out[cl * 132 + px0 + i + 2] + bv) * rv.z;
                o.w = sigm(s_out[cl * 132 + px0 + i + 3] + bv) * rv.w;
                if (!second) {
                    *(float4*)(outc + off + i) = o;
                } else {
                    float4 prev = *(const float4*)(outc + off + i);
                    o.x = fix_nan(prev.x + o.x);
                    o.y = fix_nan(prev.y + o.y);
                    o.z = fix_nan(prev.z + o.z);
                    o.w = fix_nan(prev.w + o.w);
                    *(float4*)(outc + off + i) = o;
                }
            }
        } else {
            if (NCHWOUT) {
                const int cl = tid >> 3, px0 = (tid & 7) * 16;
                const float bv = __ldg(&bias[co0 + cl]);
                float v[16];
#pragma unroll
                for (int i = 0; i < 16; ++i) {
                    float x = s_out[cl * 132 + px0 + i] + bv;
                    if (SIG) x = sigm(x);
                    v[i] = x;
                }
                float* op = outc + ((size_t)(b * CO + co0 + cl)) * HW + (size_t)y * WDIM + xbase + px0;
#pragma unroll
                for (int i = 0; i < 4; ++i)
                    *(float4*)(op + i * 4) = make_float4(v[i*4], v[i*4+1], v[i*4+2], v[i*4+3]);
            }
            if (NHWCOUT) {
                const int px = tid >> 1, cg = (tid & 1) * 16;
                const size_t pix = (size_t)b * HW + (size_t)y * WDIM + xbase + px;
                ushort hb[16], lb[16];
#pragma unroll
                for (int i = 0; i < 16; ++i) {
                    int cl = cg + i;
                    float x = s_out[cl * 132 + px] + __ldg(&bias[co0 + cl]);
                    if (SIG) x = sigm(x);
                    __nv_bfloat16 h = __float2bfloat16(x);
                    hb[i] = __bfloat16_as_ushort(h);
                    lb[i] = __bfloat16_as_ushort(__float2bfloat16(x - __bfloat162float(h)));
                }
                uint4* oh = (uint4*)(onhi + pix * 64 + co0 + cg);
                uint4* ol = (uint4*)(onlo + pix * 64 + co0 + cg);
                oh[0] = *(uint4*)&hb[0]; oh[1] = *(uint4*)&hb[8];
                ol[0] = *(uint4*)&lb[0]; ol[1] = *(uint4*)&lb[8];
            }
        }
    }
}

// ---------------- conv 1x1 via mma.sync (3-term bf16) ----------------
template <int CO, bool RESID, bool NHWCOUT>
__global__ void __launch_bounds__(256)
c1mma_k(const float* __restrict__ in, int in_cs, int in_off,
        const float* __restrict__ W, int w_bs,
        const float* __restrict__ resid,
        float* __restrict__ out, int out_cs,
        __nv_bfloat16* __restrict__ onhi, __nv_bfloat16* __restrict__ onlo) {
    extern __shared__ char smem[];
    constexpr int BLO = 17408, WHI = 34816;
    constexpr int WLO = WHI + CO * 144;
    constexpr int MCO = CO / 4;
    constexpr int MT  = MCO / 16;

    const int tid = threadIdx.x, lane = tid & 31, wid = tid >> 5;
    const int warpN = wid & 1, warpM = wid >> 1;
    const int b = blockIdx.y;
    const int pxbase = blockIdx.x * 128;
    const uint32_t sb = smem_u32(smem);

    const float* ip = in + ((size_t)b * in_cs + in_off) * HW + pxbase;
#pragma unroll
    for (int pass = 0; pass < 8; ++pass) {
        const int ci = pass * 8 + (tid >> 5);
        const int px = (tid & 31) * 4;
        float4 v = *(const float4*)(ip + (size_t)ci * HW + px);
        uint2 hi, lo;
        split4(v, hi, lo);
        *(uint2*)(smem + ci * 272 + px * 2)       = hi;
        *(uint2*)(smem + BLO + ci * 272 + px * 2) = lo;
    }
    const float* wp = W + (size_t)b * w_bs;
    for (int i = tid; i < CO * 16; i += 256) {
        const int co = i >> 4, c4 = (i & 15) * 4;
        float4 v = *(const float4*)(wp + co * 64 + c4);
        uint2 hi, lo;
        split4(v, hi, lo);
        *(uint2*)(smem + WHI + co * 144 + c4 * 2) = hi;
        *(uint2*)(smem + WLO + co * 144 + c4 * 2) = lo;
    }
    __syncthreads();

    float acc[MT][8][4];
#pragma unroll
    for (int mt = 0; mt < MT; ++mt)
#pragma unroll
        for (int j = 0; j < 8; ++j)
#pragma unroll
            for (int q = 0; q < 4; ++q) acc[mt][j][q] = 0.f;

#pragma unroll
    for (int k = 0; k < 4; ++k) {
        uint32_t ah[MT][4], al[MT][4];
#pragma unroll
        for (int mt = 0; mt < MT; ++mt) {
            uint32_t addr = sb + WHI + (warpM * MCO + mt * 16 + (lane & 15)) * 144
                          + k * 32 + (lane >> 4) * 16;
            ldmA(ah[mt], addr);
            ldmA(al[mt], addr + CO * 144);
        }
        uint32_t bh[8][2], bl[8][2];
#pragma unroll
        for (int j = 0; j < 4; ++j) {
            uint32_t addr = sb + (k * 16 + (lane & 15)) * 272
                          + (warpN * 64 + j * 16 + (lane >> 4) * 8) * 2;
            uint32_t r[4];
            ldmT(r, addr);
            bh[2*j][0] = r[0]; bh[2*j][1] = r[1];
            bh[2*j+1][0] = r[2]; bh[2*j+1][1] = r[3];
            ldmT(r, addr + BLO);
            bl[2*j][0] = r[0]; bl[2*j][1] = r[1];
            bl[2*j+1][0] = r[2]; bl[2*j+1][1] = r[3];
        }
#pragma unroll
        for (int mt = 0; mt < MT; ++mt)
#pragma unroll
            for (int j = 0; j < 8; ++j) {
                mma16816(acc[mt][j], ah[mt], bh[j]);
                mma16816(acc[mt][j], al[mt], bh[j]);
                mma16816(acc[mt][j], ah[mt], bl[j]);
            }
    }

    if (!NHWCOUT) {
#pragma unroll
        for (int mt = 0; mt < MT; ++mt)
#pragma unroll
            for (int j = 0; j < 8; ++j) {
                const int co = warpM * MCO + mt * 16 + (lane >> 2);
                const int px = warpN * 64 + j * 8 + (lane & 3) * 2;
                size_t o1 = ((size_t)b * out_cs + co) * HW + pxbase + px;
                size_t o2 = o1 + (size_t)8 * HW;
                float2 r1 = make_float2(acc[mt][j][0], acc[mt][j][1]);
                float2 r2 = make_float2(acc[mt][j][2], acc[mt][j][3]);
                if (RESID) {
                    float2 q1 = *(const float2*)(resid + o1);
                    float2 q2 = *(const float2*)(resid + o2);
                    r1.x += q1.x; r1.y += q1.y; r2.x += q2.x; r2.y += q2.y;
                }
                *(float2*)(out + o1) = r1;
                *(float2*)(out + o2) = r2;
            }
    } else {
        __syncthreads();
        float* s_out = (float*)smem;  // [64 co][132 px]
#pragma unroll
        for (int mt = 0; mt < MT; ++mt)
#pragma unroll
            for (int j = 0; j < 8; ++j) {
                const int co = warpM * MCO + mt * 16 + (lane >> 2);
                const int px = warpN * 64 + j * 8 + (lane & 3) * 2;
                s_out[co * 132 + px]           = acc[mt][j][0];
                s_out[co * 132 + px + 1]       = acc[mt][j][1];
                s_out[(co + 8) * 132 + px]     = acc[mt][j][2];
                s_out[(co + 8) * 132 + px + 1] = acc[mt][j][3];
            }
        __syncthreads();
        {
            const int co = tid >> 2, px0 = (tid & 3) * 32;
            size_t off = ((size_t)b * out_cs + co) * HW + pxbase + px0;
#pragma unroll
            for (int i = 0; i < 32; i += 4) {
                float4 a = *(float4*)&s_out[co * 132 + px0 + i];
                float4 rv = *(const float4*)(resid + off + i);
                a.x += rv.x; a.y += rv.y; a.z += rv.z; a.w += rv.w;
                *(float4*)(out + off + i) = a;
                *(float4*)&s_out[co * 132 + px0 + i] = a;
            }
        }
        __syncthreads();
        {
            const int px = tid >> 1, cg = (tid & 1) * 32;
            const size_t pix = (size_t)b * HW + pxbase + px;
#pragma unroll
            for (int gi = 0; gi < 4; ++gi) {
                ushort hb[8], lb[8];
#pragma unroll
                for (int i = 0; i < 8; ++i) {
                    float x = s_out[(cg + gi * 8 + i) * 132 + px];
                    __nv_bfloat16 h = __float2bfloat16(x);
                    hb[i] = __bfloat16_as_ushort(h);
                    lb[i] = __bfloat16_as_ushort(__float2bfloat16(x - __bfloat162float(h)));
                }
                *(uint4*)(onhi + pix * 64 + cg + gi * 8) = *(uint4*)hb;
                *(uint4*)(onlo + pix * 64 + cg + gi * 8) = *(uint4*)lb;
            }
        }
    }
}

// ---------------- depthwise 3x3: full-row tiles, smem staging ----------------
__global__ void __launch_bounds__(256)
dw3x3_k(const float* __restrict__ in, const float* __restrict__ wt,
        float* __restrict__ out, int C) {
    __shared__ float s[10][260];
    const int y0 = blockIdx.x * 8;
    const int zc = blockIdx.y;
    const int c = zc % C;
    const int tid = threadIdx.x;
    const float* ip = in + (size_t)zc * HW;

    float w[9];
#pragma unroll
    for (int i = 0; i < 9; ++i) w[i] = __ldg(&wt[c * 9 + i]);

#pragma unroll
    for (int pass = 0; pass < 3; ++pass) {
        int idx = tid + pass * 256;
        if (idx < 640) {
            int r = idx >> 6, c4 = (idx & 63) * 4;
            int gy = y0 + r - 1;
            float4 v = make_float4(0.f, 0.f, 0.f, 0.f);
            if (gy >= 0 && gy < HDIM) v = *(const float4*)(ip + gy * WDIM + c4);
            *(float4*)&s[r][c4] = v;
        }
    }
    __syncthreads();

#pragma unroll
    for (int pass = 0; pass < 2; ++pass) {
        const int r = (tid >> 6) + pass * 4;
        const int px0 = (tid & 63) * 4;
        float acc[4] = {0.f, 0.f, 0.f, 0.f};
#pragma unroll
        for (int ky = 0; ky < 3; ++ky) {
            const float* row = s[r + ky];
            float4 m = *(const float4*)&row[px0];
            float v0 = (px0 == 0) ? 0.f : row[px0 - 1];
            float v5 = (px0 == 252) ? 0.f : row[px0 + 4];
            float v[6] = {v0, m.x, m.y, m.z, m.w, v5};
#pragma unroll
            for (int kx = 0; kx < 3; ++kx)
#pragma unroll
                for (int p = 0; p < 4; ++p)
                    acc[p] += w[ky * 3 + kx] * v[kx + p];
        }
        *(float4*)&out[(size_t)zc * HW + (y0 + r) * WDIM + px0] =
            make_float4(acc[0], acc[1], acc[2], acc[3]);
    }
}

// ---------------- Gram + norms ----------------
__global__ void gramnorm_k(const float* __restrict__ q, int qcs,
                           const float* __restrict__ k, int kcs,
                           float* __restrict__ G, float* __restrict__ nq,
                           float* __restrict__ nk) {
    const int b = blockIdx.z, h = blockIdx.y;
    const int p0 = blockIdx.x * 4096 + threadIdx.x;
    const float* qb = q + ((size_t)b * qcs + h * 8) * HW;
    const float* kb = k + ((size_t)b * kcs + h * 8) * HW;
    float acc[80];
#pragma unroll
    for (int i = 0; i < 80; ++i) acc[i] = 0.f;
    for (int it = 0; it < 16; ++it) {
        int p = p0 + it * 256;
        float qv[8], kv[8];
#pragma unroll
        for (int c = 0; c < 8; ++c) {
            qv[c] = qb[(size_t)c * HW + p];
            kv[c] = kb[(size_t)c * HW + p];
        }
#pragma unroll
        for (int c = 0; c < 8; ++c) {
            acc[64 + c] += qv[c] * qv[c];
            acc[72 + c] += kv[c] * kv[c];
#pragma unroll
            for (int d = 0; d < 8; ++d) acc[c * 8 + d] += qv[c] * kv[d];
        }
    }
    __shared__ float red[80][8];
    const int lane = threadIdx.x & 31, warp = threadIdx.x >> 5;
#pragma unroll
    for (int i = 0; i < 80; ++i) {
        float v = acc[i];
        v += __shfl_down_sync(0xffffffffu, v, 16);
        v += __shfl_down_sync(0xffffffffu, v, 8);
        v += __shfl_down_sync(0xffffffffu, v, 4);
        v += __shfl_down_sync(0xffffffffu, v, 2);
        v += __shfl_down_sync(0xffffffffu, v, 1);
        if (lane == 0) red[i][warp] = v;
    }
    __syncthreads();
    if (threadIdx.x < 80) {
        float s = 0.f;
#pragma unroll
        for (int w = 0; w < 8; ++w) s += red[threadIdx.x][w];
        int i = threadIdx.x;
        if (i < 64)
            atomicAdd(&G[(((size_t)b * 8 + h) * 8 + (i >> 3)) * 8 + (i & 7)], s);
        else if (i < 72)
            atomicAdd(&nq[b * 64 + h * 8 + (i - 64)], s);
        else
            atomicAdd(&nk[b * 64 + h * 8 + (i - 72)], s);
    }
}

// ---------------- softmax + proj fold ----------------
__global__ void softmax_meff_k(const float* __restrict__ temp, const float* __restrict__ Wproj,
                               const float* __restrict__ G, const float* __restrict__ nq,
                               const float* __restrict__ nk, float* __restrict__ Meff) {
    const int b = blockIdx.x;
    const int t = threadIdx.x;
    __shared__ float attn[8][8][8];
    {
        int h = t >> 3, c = t & 7;
        float nqc = fmaxf(sqrtf(nq[b * 64 + h * 8 + c]), 1e-12f);
        float row[8];
        float m = -1e30f;
#pragma unroll
        for (int d = 0; d < 8; ++d) {
            float nkd = fmaxf(sqrtf(nk[b * 64 + h * 8 + d]), 1e-12f);
            row[d] = temp[h] * G[(((size_t)b * 8 + h) * 8 + c) * 8 + d] / (nqc * nkd);
            m = fmaxf(m, row[d]);
        }
        float sum = 0.f;
#pragma unroll
        for (int d = 0; d < 8; ++d) { row[d] = expf(row[d] - m); sum += row[d]; }
        float inv = 1.f / sum;
#pragma unroll
        for (int d = 0; d < 8; ++d) attn[h][c][d] = row[d] * inv;
    }
    __syncthreads();
    const int o = t;
    for (int dg = 0; dg < 64; ++dg) {
        int hh = dg >> 3, j = dg & 7;
        float s = 0.f;
#pragma unroll
        for (int i = 0; i < 8; ++i) s += Wproj[o * 64 + hh * 8 + i] * attn[hh][i][j];
        Meff[((size_t)b * 64 + o) * 64 + dg] = s;
    }
}

// ---------------- host orchestration ----------------
extern "C" void kernel_launch(void* const* d_in, const int* in_sizes, int n_in,
                              void* d_out, int out_size) {
    const float* spa    = (const float*)d_in[0];
    const float* fre    = (const float*)d_in[1];
    const float* W_fre  = (const float*)d_in[2];
    const float* b_fre  = (const float*)d_in[3];
    const float* W_spa  = (const float*)d_in[4];
    const float* b_spa  = (const float*)d_in[5];
    const float* temp   = (const float*)d_in[6];
    const float* Wq     = (const float*)d_in[7];
    const float* Wq_dw  = (const float*)d_in[8];
    const float* Wkv    = (const float*)d_in[9];
    const float* Wkv_dw = (const float*)d_in[10];
    const float* Wproj  = (const float*)d_in[11];
    const float* Wf1    = (const float*)d_in[12];
    const float* bf1    = (const float*)d_in[13];
    const float* Wf2    = (const float*)d_in[14];
    const float* bf2    = (const float*)d_in[15];
    float* out = (float*)d_out;

    float *pfre1, *pspa1, *ptmp, *pq, *pfre2, *pspa2, *pkv0, *pkv, *pstats, *pmeff;
    __nv_bfloat16 *phi, *plo;
    uint2* pwk;
    cudaGetSymbolAddress((void**)&pfre1, g_fre1);
    cudaGetSymbolAddress((void**)&pspa1, g_spa1);
    cudaGetSymbolAddress((void**)&ptmp,  g_tmp);
    cudaGetSymbolAddress((void**)&pq,    g_q);
    cudaGetSymbolAddress((void**)&pfre2, g_fre2);
    cudaGetSymbolAddress((void**)&pspa2, g_spa2);
    cudaGetSymbolAddress((void**)&pkv0,  g_kv0);
    cudaGetSymbolAddress((void**)&pkv,   g_kv);
    cudaGetSymbolAddress((void**)&pstats, g_stats);
    cudaGetSymbolAddress((void**)&pmeff, g_Meff);
    cudaGetSymbolAddress((void**)&phi,   g_nh_hi);
    cudaGetSymbolAddress((void**)&plo,   g_nh_lo);
    cudaGetSymbolAddress((void**)&pwk,   g_wpk2);
    float* pG  = pstats;
    float* pnq = pstats + 2048;
    float* pnk = pstats + 2304;
    const size_t NHN = (size_t)BSZ * HW * 64;
    __nv_bfloat16 *h0 = phi, *h1 = phi + NHN, *h2 = phi + 2*NHN, *h3 = phi + 3*NHN, *h4 = phi + 4*NHN;
    __nv_bfloat16 *l0 = plo, *l1 = plo + NHN, *l2 = plo + 2*NHN, *l3 = plo + 3*NHN, *l4 = plo + 4*NHN;
    uint2 *w0 = pwk, *w1 = pwk + 18432, *wF1 = pwk + 36864, *wF2 = pwk + 73728;

    cudaFuncSetAttribute(gconv_k<64, 64, false, false, true, false, 3>,
                         cudaFuncAttributeMaxDynamicSharedMemorySize, GC_SMEM);
    cudaFuncSetAttribute(gconv_k<128, 64, false, false, false, true, 3>,
                         cudaFuncAttributeMaxDynamicSharedMemorySize, GC_SMEM);
    cudaFuncSetAttribute(gconv_k<64, 128, true, true, false, false, 2>,
                         cudaFuncAttributeMaxDynamicSharedMemorySize, GC_SMEM);
    const int C1_SMEM_64  = 34816 + 64 * 144 * 2;    // 53248
    const int C1_SMEM_128 = 34816 + 128 * 144 * 2;   // 71680
    cudaFuncSetAttribute(c1mma_k<64, false, false>,
                         cudaFuncAttributeMaxDynamicSharedMemorySize, C1_SMEM_64);
    cudaFuncSetAttribute(c1mma_k<64, true, true>,
                         cudaFuncAttributeMaxDynamicSharedMemorySize, C1_SMEM_64);
    cudaFuncSetAttribute(c1mma_k<128, false, false>,
                         cudaFuncAttributeMaxDynamicSharedMemorySize, C1_SMEM_128);

    const dim3 blk(256);
    const dim3 gt(2048, 2, BSZ);            // transpose
    const dim3 gg(2, 256, BSZ);             // gconv
    const dim3 g1(512, BSZ);                // c1mma
    const dim3 gdw64(32, BSZ * 64);
    const dim3 gdw128(32, BSZ * 128);
    const dim3 ggram(16, 8, BSZ);

    // order: launch #4 = first gconv (empirical ncu capture position)
    wpack_k<<<72,  blk>>>(W_fre, w0, 64, 64);
    wpack_k<<<72,  blk>>>(W_spa, w1, 64, 64);
    nchw2nhwc_k<<<gt, blk>>>(fre, h0, l0);
    gconv_k<64, 64, false, false, true, false, 3><<<gg, blk, GC_SMEM>>>(
        h0, l0, h0, l0, w0, b_fre, pfre1, nullptr, nullptr, nullptr, nullptr);
    nchw2nhwc_k<<<gt, blk>>>(spa, h1, l1);
    gconv_k<64, 64, false, false, true, false, 3><<<gg, blk, GC_SMEM>>>(
        h1, l1, h1, l1, w1, b_spa, pspa1, nullptr, nullptr, nullptr, nullptr);
    wpack_k<<<144, blk>>>(Wf1, wF1, 128, 64);
    wpack_k<<<144, blk>>>(Wf2, wF2, 64, 128);

    // attention 1: q from fre1, kv from spa1, residual fre1 -> fre2 (+NHWC h2,l2)
    c1mma_k<128, false, false><<<g1, blk, C1_SMEM_128>>>(pspa1, 64, 0, Wkv, 0, nullptr, pkv0, 128, nullptr, nullptr);
    dw3x3_k<<<gdw128, blk>>>(pkv0, Wkv_dw, pkv, 128);
    c1mma_k<64, false, false><<<g1, blk, C1_SMEM_64>>>(pfre1, 64, 0, Wq, 0, nullptr, ptmp, 64, nullptr, nullptr);
    dw3x3_k<<<gdw64, blk>>>(ptmp, Wq_dw, pq, 64);
    zero_k<<<10, blk>>>(pstats, 2560);
    gramnorm_k<<<ggram, blk>>>(pq, 64, pkv, 128, pG, pnq, pnk);
    softmax_meff_k<<<BSZ, 64>>>(temp, Wproj, pG, pnq, pnk, pmeff);
    c1mma_k<64, true, true><<<g1, blk, C1_SMEM_64>>>(pkv, 128, 64, pmeff, 64 * 64, pfre1, pfre2, 64, h2, l2);

    // attention 2: q from spa1, kv from fre2, residual spa1 -> spa2 (+NHWC h3,l3)
    c1mma_k<128, false, false><<<g1, blk, C1_SMEM_128>>>(pfre2, 64, 0, Wkv, 0, nullptr, pkv0, 128, nullptr, nullptr);
    dw3x3_k<<<gdw128, blk>>>(pkv0, Wkv_dw, pkv, 128);
    c1mma_k<64, false, false><<<g1, blk, C1_SMEM_64>>>(pspa1, 64, 0, Wq, 0, nullptr, ptmp, 64, nullptr, nullptr);
    dw3x3_k<<<gdw64, blk>>>(ptmp, Wq_dw, pq, 64);
    zero_k<<<10, blk>>>(pstats, 2560);
    gramnorm_k<<<ggram, blk>>>(pq, 64, pkv, 128, pG, pnq, pnk);
    softmax_meff_k<<<BSZ, 64>>>(temp, Wproj, pG, pnq, pnk, pmeff);
    c1mma_k<64, true, true><<<g1, blk, C1_SMEM_64>>>(pkv, 128, 64, pmeff, 64 * 64, pspa1, pspa2, 64, h3, l3);

    // fuse path: F1 (concat -> t1 NHWC), F2 + final gate fused
    gconv_k<128, 64, false, false, false, true, 3><<<gg, blk, GC_SMEM>>>(
        h2, l2, h3, l3, wF1, bf1, nullptr, h4, l4, nullptr, nullptr);
    gconv_k<64, 128, true, true, false, false, 2><<<gg, blk, GC_SMEM>>>(
        h4, l4, h4, l4, wF2, bf2, out, nullptr, nullptr, pfre2, pspa2);
}

// round 13
// speedup vs baseline: 1.3531x; 1.3531x over previous
#include <cuda_runtime.h>
#include <cuda_bf16.h>
#include <math.h>
#include <stdint.h>

#define BSZ 4
#define HDIM 256
#define WDIM 256
#define HW 65536

// ---------------- scratch (device globals) ----------------
__device__ float g_fre1[(size_t)BSZ * 64 * HW];
__device__ float g_spa1[(size_t)BSZ * 64 * HW];
__device__ float g_tmp [(size_t)BSZ * 64 * HW];
__device__ float g_q   [(size_t)BSZ * 64 * HW];
__device__ float g_fre2[(size_t)BSZ * 64 * HW];
__device__ float g_spa2[(size_t)BSZ * 64 * HW];
__device__ float g_kv0 [(size_t)BSZ * 128 * HW];
__device__ float g_kv  [(size_t)BSZ * 128 * HW];
__device__ float g_stats[2560];
__device__ float g_Meff[BSZ * 64 * 64];
// NHWC bf16 hi/lo slots: 0=fre 1=spa 2=fre2 3=spa2 4=t1
__device__ __nv_bfloat16 g_nh_hi[5][(size_t)BSZ * HW * 64];
__device__ __nv_bfloat16 g_nh_lo[5][(size_t)BSZ * HW * 64];
// packed weights (hi-pair, lo-pair)
__device__ uint2 g_wpk2[110592];

// ---------------- mma.sync / cp.async helpers (baseline sm_80+, no 'a' arch) ----------------
__device__ __forceinline__ uint32_t smem_u32(const void* p) {
    uint32_t a;
    asm("{ .reg .u64 t; cvta.to.shared.u64 t, %1; cvt.u32.u64 %0, t; }" : "=r"(a) : "l"(p));
    return a;
}
__device__ __forceinline__ void ldmA(uint32_t r[4], uint32_t a) {
    asm volatile("ldmatrix.sync.aligned.m8n8.x4.shared.b16 {%0,%1,%2,%3}, [%4];"
                 : "=r"(r[0]), "=r"(r[1]), "=r"(r[2]), "=r"(r[3]) : "r"(a));
}
__device__ __forceinline__ void ldmT(uint32_t r[4], uint32_t a) {
    asm volatile("ldmatrix.sync.aligned.m8n8.x4.trans.shared.b16 {%0,%1,%2,%3}, [%4];"
                 : "=r"(r[0]), "=r"(r[1]), "=r"(r[2]), "=r"(r[3]) : "r"(a));
}
__device__ __forceinline__ void mma16816(float* c, const uint32_t* a, const uint32_t* b) {
    asm volatile(
        "mma.sync.aligned.m16n8k16.row.col.f32.bf16.bf16.f32 "
        "{%0,%1,%2,%3}, {%4,%5,%6,%7}, {%8,%9}, {%0,%1,%2,%3};"
        : "+f"(c[0]), "+f"(c[1]), "+f"(c[2]), "+f"(c[3])
        : "r"(a[0]), "r"(a[1]), "r"(a[2]), "r"(a[3]), "r"(b[0]), "r"(b[1]));
}
__device__ __forceinline__ void cpa16(uint32_t d, const void* s, int pb) {
    asm volatile("cp.async.cg.shared.global [%0], [%1], 16, %2;"
                 :: "r"(d), "l"(s), "r"(pb) : "memory");
}
__device__ __forceinline__ void cpa_commit() {
    asm volatile("cp.async.commit_group;" ::: "memory");
}
__device__ __forceinline__ void cpa_wait1() {
    asm volatile("cp.async.wait_group 1;" ::: "memory");
}
__device__ __forceinline__ void cpa_wait0() {
    asm volatile("cp.async.wait_group 0;" ::: "memory");
}
__device__ __forceinline__ void split4(float4 v, uint2& hi, uint2& lo) {
    __nv_bfloat16 h0 = __float2bfloat16(v.x), h1 = __float2bfloat16(v.y);
    __nv_bfloat16 h2 = __float2bfloat16(v.z), h3 = __float2bfloat16(v.w);
    __nv_bfloat16 l0 = __float2bfloat16(v.x - __bfloat162float(h0));
    __nv_bfloat16 l1 = __float2bfloat16(v.y - __bfloat162float(h1));
    __nv_bfloat16 l2 = __float2bfloat16(v.z - __bfloat162float(h2));
    __nv_bfloat16 l3 = __float2bfloat16(v.w - __bfloat162float(h3));
    hi.x = ((uint32_t)__bfloat16_as_ushort(h1) << 16) | __bfloat16_as_ushort(h0);
    hi.y = ((uint32_t)__bfloat16_as_ushort(h3) << 16) | __bfloat16_as_ushort(h2);
    lo.x = ((uint32_t)__bfloat16_as_ushort(l1) << 16) | __bfloat16_as_ushort(l0);
    lo.y = ((uint32_t)__bfloat16_as_ushort(l3) << 16) | __bfloat16_as_ushort(l2);
}

__global__ void zero_k(float* p, int n) {
    int i = blockIdx.x * 256 + threadIdx.x;
    if (i < n) p[i] = 0.f;
}
__device__ __forceinline__ float fix_nan(float x) { return isfinite(x) ? x : 1e-5f; }
__device__ __forceinline__ float sigm(float x) { return 1.f / (1.f + expf(-x)); }

// ---------------- NCHW fp32 -> NHWC bf16 hi/lo ----------------
__global__ void nchw2nhwc_k(const float* __restrict__ in,
                            __nv_bfloat16* __restrict__ ohi,
                            __nv_bfloat16* __restrict__ olo) {
    __shared__ float s[32][33];
    const int b = blockIdx.z, ch0 = blockIdx.y * 32, p0 = blockIdx.x * 32;
    const int lx = threadIdx.x & 31, ly = threadIdx.x >> 5;
#pragma unroll
    for (int i = 0; i < 4; ++i) {
        int c = ly + i * 8;
        s[c][lx] = in[((size_t)(b * 64 + ch0 + c)) * HW + p0 + lx];
    }
    __syncthreads();
#pragma unroll
    for (int i = 0; i < 4; ++i) {
        int p = ly + i * 8;
        float v = s[lx][p];
        __nv_bfloat16 h = __float2bfloat16(v);
        size_t idx = ((size_t)b * HW + p0 + p) * 64 + ch0 + lx;
        ohi[idx] = h;
        olo[idx] = __float2bfloat16(v - __bfloat162float(h));
    }
}

// ---------------- weight pack: OIHW -> [tap][chunk16][co][8] uint2 {hi2, lo2} ----------------
__global__ void wpack_k(const float* __restrict__ W, uint2* __restrict__ pk, int CIN, int CO) {
    int NCH = CIN >> 4;
    int n = 9 * NCH * CO * 8;
    int i = blockIdx.x * 256 + threadIdx.x;
    if (i >= n) return;
    int j = i & 7;
    int t2 = i >> 3;
    int co = t2 % CO;
    int t3 = t2 / CO;
    int chv = t3 % NCH, tap = t3 / NCH;
    int ci = chv * 16 + 2 * j;
    float w0 = W[((size_t)co * CIN + ci) * 9 + tap];
    float w1 = W[((size_t)co * CIN + ci + 1) * 9 + tap];
    __nv_bfloat16 h0 = __float2bfloat16(w0), h1 = __float2bfloat16(w1);
    __nv_bfloat16 l0 = __float2bfloat16(w0 - __bfloat162float(h0));
    __nv_bfloat16 l1 = __float2bfloat16(w1 - __bfloat162float(h1));
    uint2 o;
    o.x = ((uint32_t)__bfloat16_as_ushort(h1) << 16) | (uint32_t)__bfloat16_as_ushort(h0);
    o.y = ((uint32_t)__bfloat16_as_ushort(l1) << 16) | (uint32_t)__bfloat16_as_ushort(l0);
    pk[i] = o;
}

// ---------------- mma.sync bf16 3-term implicit-GEMM 3x3 conv (R11 tiling) ----------------
#define GC_BUF 37440                 // 130 px * 144 B * 2 (hi+lo)
#define GC_SMEM (2 * GC_BUF)         // 74880
#define LOOFF 18720                  // 130 * 144

__device__ __forceinline__ void gc_stage(const __nv_bfloat16* __restrict__ shi,
                                         const __nv_bfloat16* __restrict__ slo,
                                         int b, int gy, bool yok, int xbase,
                                         uint32_t dst, int tid) {
    const int gyc = yok ? gy : 0;
    for (int idx = tid; idx < 260; idx += 256) {
        const int px = idx >> 1, q = idx & 1;
        const int gx = xbase + px - 1;
        const bool ok = yok && gx >= 0 && gx < WDIM;
        const int gxc = (gx >= 0 && gx < WDIM) ? gx : 0;
        const int pb = ok ? 16 : 0;
        size_t off = ((size_t)b * HW + (size_t)gyc * WDIM + gxc) * 64 + q * 32;
        const char* ph = (const char*)(shi + off);
        const char* pl = (const char*)(slo + off);
        uint32_t dh = dst + px * 144 + q * 64;
        uint32_t dl = dst + LOOFF + px * 144 + q * 64;
#pragma unroll
        for (int i = 0; i < 4; ++i) {
            cpa16(dh + i * 16, ph + i * 16, pb);
            cpa16(dl + i * 16, pl + i * 16, pb);
        }
    }
    cpa_commit();
}

template <int CIN, int CO, bool SIG, bool FINAL, bool NCHWOUT, bool NHWCOUT, int MINB>
__global__ void __launch_bounds__(256, MINB)
gconv_k(const __nv_bfloat16* __restrict__ sAhi, const __nv_bfloat16* __restrict__ sAlo,
        const __nv_bfloat16* __restrict__ sBhi, const __nv_bfloat16* __restrict__ sBlo,
        const uint2* __restrict__ wb, const float* __restrict__ bias,
        float* __restrict__ outc,
        __nv_bfloat16* __restrict__ onhi, __nv_bfloat16* __restrict__ onlo,
        const float* __restrict__ resA, const float* __restrict__ resB) {
    extern __shared__ char smem[];
    constexpr int NGRP = CIN / 64;
    constexpr int NWN = CO / 32;
    constexpr int NWM = 8 / NWN;
    constexpr int MPW = 128 / NWM;
    constexpr int MT  = MPW / 16;
    const int NSTG = 3 * NGRP;

    const int tid = threadIdx.x, wid = tid >> 5, lane = tid & 31;
    const int warpN = wid % NWN, warpM = wid / NWN;
    const int b = blockIdx.z, y = blockIdx.y, xbase = blockIdx.x * 128;
    const int g = lane >> 2, tig = lane & 3;
    const uint32_t sb = smem_u32(smem);

    float acc[MT][4][4];
#pragma unroll
    for (int mt = 0; mt < MT; ++mt)
#pragma unroll
        for (int nt = 0; nt < 4; ++nt)
#pragma unroll
            for (int q = 0; q < 4; ++q) acc[mt][nt][q] = 0.f;

    // prologue: issue stage 0 into buf 0
    {
        const int gy = y - 1;
        gc_stage(sAhi, sAlo, b, gy, (gy >= 0) && (gy < HDIM), xbase, sb, tid);
    }

    for (int st = 0; st < NSTG; ++st) {
        __syncthreads();   // all warps done with buf[(st+1)&1] (computed at st-1)
        if (st + 1 < NSTG) {
            const int dyN = (st + 1) / NGRP, grpN = (st + 1) % NGRP;
            const int gyN = y + dyN - 1;
            gc_stage(grpN ? sBhi : sAhi, grpN ? sBlo : sAlo, b, gyN,
                     (gyN >= 0) && (gyN < HDIM), xbase,
                     sb + ((st + 1) & 1) * GC_BUF, tid);
            cpa_wait1();
        } else {
            cpa_wait0();
        }
        __syncthreads();   // staged data for st visible

        const int dyI = st / NGRP, grp = st % NGRP;
        const uint32_t sbuf = sb + (st & 1) * GC_BUF;
#pragma unroll
        for (int dxI = 0; dxI < 3; ++dxI) {
            const int tap = dyI * 3 + dxI;
            const uint2* wt = wb + (size_t)(tap * (CIN / 16) + grp * 4) * CO * 8;
#pragma unroll
            for (int ch = 0; ch < 4; ++ch) {
                uint32_t bh[4][2], bl[4][2];
                const uint2* wc = wt + (size_t)ch * CO * 8;
#pragma unroll
                for (int nt = 0; nt < 4; ++nt) {
                    int n = warpN * 32 + nt * 8 + g;
                    uint2 v0 = __ldg(&wc[n * 8 + tig]);
                    uint2 v1 = __ldg(&wc[n * 8 + tig + 4]);
                    bh[nt][0] = v0.x; bl[nt][0] = v0.y;
                    bh[nt][1] = v1.x; bl[nt][1] = v1.y;
                }
#pragma unroll
                for (int mt = 0; mt < MT; ++mt) {
                    const int pxl = warpM * MPW + mt * 16 + (lane & 15) + dxI;
                    uint32_t addr = sbuf + pxl * 144 + ch * 32 + ((lane >> 4) & 1) * 16;
                    uint32_t ah[4], al[4];
                    ldmA(ah, addr);
                    ldmA(al, addr + LOOFF);
#pragma unroll
                    for (int nt = 0; nt < 4; ++nt) {
                        mma16816(acc[mt][nt], ah, bh[nt]);
                        mma16816(acc[mt][nt], al, bh[nt]);
                        mma16816(acc[mt][nt], ah, bl[nt]);
                    }
                }
            }
        }
    }

    // ---------------- epilogue through smem ----------------
    float* s_out = (float*)smem;  // [32 co][132 px]
    for (int co0 = 0; co0 < CO; co0 += 32) {
        __syncthreads();
        if (warpN == (co0 >> 5)) {
#pragma unroll
            for (int mt = 0; mt < MT; ++mt) {
                const int px = warpM * MPW + mt * 16 + g;
#pragma unroll
                for (int nt = 0; nt < 4; ++nt) {
                    const int cl = nt * 8 + tig * 2;
                    s_out[cl * 132 + px]           = acc[mt][nt][0];
                    s_out[(cl + 1) * 132 + px]     = acc[mt][nt][1];
                    s_out[cl * 132 + px + 8]       = acc[mt][nt][2];
                    s_out[(cl + 1) * 132 + px + 8] = acc[mt][nt][3];
                }
            }
        }
        __syncthreads();
        if (FINAL) {
            const int cl = tid >> 3, px0 = (tid & 7) * 16;
            const int c = (co0 + cl) & 63;
            const bool second = (co0 + cl) >= 64;
            const float bv = __ldg(&bias[co0 + cl]);
            const float* res = second ? resB : resA;
            size_t off = ((size_t)(b * 64 + c)) * HW + (size_t)y * WDIM + xbase + px0;
#pragma unroll
            for (int i = 0; i < 16; i += 4) {
                float4 rv = *(const float4*)(res + off + i);
                float4 o;
                o.x = sigm(s_out[cl * 132 + px0 + i]     + bv) * rv.x;
                o.y = sigm(s_out[cl * 132 + px0 + i + 1] + bv) * rv.y;
                o.z = sigm(s_out[cl * 132 + px0 + i + 2] + bv) * rv.z;
                o.w = sigm(s_out[cl * 132 + px0 + i + 3] + bv) * rv.w;
                if (!second) {
                    *(float4*)(outc + off + i) = o;
                } else {
                    float4 prev = *(const float4*)(outc + off + i);
                    o.x = fix_nan(prev.x + o.x);
                    o.y = fix_nan(prev.y + o.y);
                    o.z = fix_nan(prev.z + o.z);
                    o.w = fix_nan(prev.w + o.w);
                    *(float4*)(outc + off + i) = o;
                }
            }
        } else {
            if (NCHWOUT) {
                const int cl = tid >> 3, px0 = (tid & 7) * 16;
                const float bv = __ldg(&bias[co0 + cl]);
                float v[16];
#pragma unroll
                for (int i = 0; i < 16; ++i) {
                    float x = s_out[cl * 132 + px0 + i] + bv;
                    if (SIG) x = sigm(x);
                    v[i] = x;
                }
                float* op = outc + ((size_t)(b * CO + co0 + cl)) * HW + (size_t)y * WDIM + xbase + px0;
#pragma unroll
                for (int i = 0; i < 4; ++i)
                    *(float4*)(op + i * 4) = make_float4(v[i*4], v[i*4+1], v[i*4+2], v[i*4+3]);
            }
            if (NHWCOUT) {
                const int px = tid >> 1, cg = (tid & 1) * 16;
                const size_t pix = (size_t)b * HW + (size_t)y * WDIM + xbase + px;
                ushort hb[16], lb[16];
#pragma unroll
                for (int i = 0; i < 16; ++i) {
                    int cl = cg + i;
                    float x = s_out[cl * 132 + px] + __ldg(&bias[co0 + cl]);
                    if (SIG) x = sigm(x);
                    __nv_bfloat16 h = __float2bfloat16(x);
                    hb[i] = __bfloat16_as_ushort(h);
                    lb[i] = __bfloat16_as_ushort(__float2bfloat16(x - __bfloat162float(h)));
                }
                uint4* oh = (uint4*)(onhi + pix * 64 + co0 + cg);
                uint4* ol = (uint4*)(onlo + pix * 64 + co0 + cg);
                oh[0] = *(uint4*)&hb[0]; oh[1] = *(uint4*)&hb[8];
                ol[0] = *(uint4*)&lb[0]; ol[1] = *(uint4*)&lb[8];
            }
        }
    }
}

// ---------------- conv 1x1 via mma.sync (3-term bf16) ----------------
template <int CO, bool RESID, bool NHWCOUT>
__global__ void __launch_bounds__(256)
c1mma_k(const float* __restrict__ in, int in_cs, int in_off,
        const float* __restrict__ W, int w_bs,
        const float* __restrict__ resid,
        float* __restrict__ out, int out_cs,
        __nv_bfloat16* __restrict__ onhi, __nv_bfloat16* __restrict__ onlo) {
    extern __shared__ char smem[];
    constexpr int BLO = 17408, WHI = 34816;
    constexpr int WLO = WHI + CO * 144;
    constexpr int MCO = CO / 4;
    constexpr int MT  = MCO / 16;

    const int tid = threadIdx.x, lane = tid & 31, wid = tid >> 5;
    const int warpN = wid & 1, warpM = wid >> 1;
    const int b = blockIdx.y;
    const int pxbase = blockIdx.x * 128;
    const uint32_t sb = smem_u32(smem);

    const float* ip = in + ((size_t)b * in_cs + in_off) * HW + pxbase;
#pragma unroll
    for (int pass = 0; pass < 8; ++pass) {
        const int ci = pass * 8 + (tid >> 5);
        const int px = (tid & 31) * 4;
        float4 v = *(const float4*)(ip + (size_t)ci * HW + px);
        uint2 hi, lo;
        split4(v, hi, lo);
        *(uint2*)(smem + ci * 272 + px * 2)       = hi;
        *(uint2*)(smem + BLO + ci * 272 + px * 2) = lo;
    }
    const float* wp = W + (size_t)b * w_bs;
    for (int i = tid; i < CO * 16; i += 256) {
        const int co = i >> 4, c4 = (i & 15) * 4;
        float4 v = *(const float4*)(wp + co * 64 + c4);
        uint2 hi, lo;
        split4(v, hi, lo);
        *(uint2*)(smem + WHI + co * 144 + c4 * 2) = hi;
        *(uint2*)(smem + WLO + co * 144 + c4 * 2) = lo;
    }
    __syncthreads();

    float acc[MT][8][4];
#pragma unroll
    for (int mt = 0; mt < MT; ++mt)
#pragma unroll
        for (int j = 0; j < 8; ++j)
#pragma unroll
            for (int q = 0; q < 4; ++q) acc[mt][j][q] = 0.f;

#pragma unroll
    for (int k = 0; k < 4; ++k) {
        uint32_t ah[MT][4], al[MT][4];
#pragma unroll
        for (int mt = 0; mt < MT; ++mt) {
            uint32_t addr = sb + WHI + (warpM * MCO + mt * 16 + (lane & 15)) * 144
                          + k * 32 + (lane >> 4) * 16;
            ldmA(ah[mt], addr);
            ldmA(al[mt], addr + CO * 144);
        }
        uint32_t bh[8][2], bl[8][2];
#pragma unroll
        for (int j = 0; j < 4; ++j) {
            uint32_t addr = sb + (k * 16 + (lane & 15)) * 272
                          + (warpN * 64 + j * 16 + (lane >> 4) * 8) * 2;
            uint32_t r[4];
            ldmT(r, addr);
            bh[2*j][0] = r[0]; bh[2*j][1] = r[1];
            bh[2*j+1][0] = r[2]; bh[2*j+1][1] = r[3];
            ldmT(r, addr + BLO);
            bl[2*j][0] = r[0]; bl[2*j][1] = r[1];
            bl[2*j+1][0] = r[2]; bl[2*j+1][1] = r[3];
        }
#pragma unroll
        for (int mt = 0; mt < MT; ++mt)
#pragma unroll
            for (int j = 0; j < 8; ++j) {
                mma16816(acc[mt][j], ah[mt], bh[j]);
                mma16816(acc[mt][j], al[mt], bh[j]);
                mma16816(acc[mt][j], ah[mt], bl[j]);
            }
    }

    if (!NHWCOUT) {
#pragma unroll
        for (int mt = 0; mt < MT; ++mt)
#pragma unroll
            for (int j = 0; j < 8; ++j) {
                const int co = warpM * MCO + mt * 16 + (lane >> 2);
                const int px = warpN * 64 + j * 8 + (lane & 3) * 2;
                size_t o1 = ((size_t)b * out_cs + co) * HW + pxbase + px;
                size_t o2 = o1 + (size_t)8 * HW;
                float2 r1 = make_float2(acc[mt][j][0], acc[mt][j][1]);
                float2 r2 = make_float2(acc[mt][j][2], acc[mt][j][3]);
                if (RESID) {
                    float2 q1 = *(const float2*)(resid + o1);
                    float2 q2 = *(const float2*)(resid + o2);
                    r1.x += q1.x; r1.y += q1.y; r2.x += q2.x; r2.y += q2.y;
                }
                *(float2*)(out + o1) = r1;
                *(float2*)(out + o2) = r2;
            }
    } else {
        __syncthreads();
        float* s_out = (float*)smem;  // [64 co][132 px]
#pragma unroll
        for (int mt = 0; mt < MT; ++mt)
#pragma unroll
            for (int j = 0; j < 8; ++j) {
                const int co = warpM * MCO + mt * 16 + (lane >> 2);
                const int px = warpN * 64 + j * 8 + (lane & 3) * 2;
                s_out[co * 132 + px]           = acc[mt][j][0];
                s_out[co * 132 + px + 1]       = acc[mt][j][1];
                s_out[(co + 8) * 132 + px]     = acc[mt][j][2];
                s_out[(co + 8) * 132 + px + 1] = acc[mt][j][3];
            }
        __syncthreads();
        {
            const int co = tid >> 2, px0 = (tid & 3) * 32;
            size_t off = ((size_t)b * out_cs + co) * HW + pxbase + px0;
#pragma unroll
            for (int i = 0; i < 32; i += 4) {
                float4 a = *(float4*)&s_out[co * 132 + px0 + i];
                float4 rv = *(const float4*)(resid + off + i);
                a.x += rv.x; a.y += rv.y; a.z += rv.z; a.w += rv.w;
                *(float4*)(out + off + i) = a;
                *(float4*)&s_out[co * 132 + px0 + i] = a;
            }
        }
        __syncthreads();
        {
            const int px = tid >> 1, cg = (tid & 1) * 32;
            const size_t pix = (size_t)b * HW + pxbase + px;
#pragma unroll
            for (int gi = 0; gi < 4; ++gi) {
                ushort hb[8], lb[8];
#pragma unroll
                for (int i = 0; i < 8; ++i) {
                    float x = s_out[(cg + gi * 8 + i) * 132 + px];
                    __nv_bfloat16 h = __float2bfloat16(x);
                    hb[i] = __bfloat16_as_ushort(h);
                    lb[i] = __bfloat16_as_ushort(__float2bfloat16(x - __bfloat162float(h)));
                }
                *(uint4*)(onhi + pix * 64 + cg + gi * 8) = *(uint4*)hb;
                *(uint4*)(onlo + pix * 64 + cg + gi * 8) = *(uint4*)lb;
            }
        }
    }
}

// ---------------- depthwise 3x3: full-row tiles, smem staging ----------------
__global__ void __launch_bounds__(256)
dw3x3_k(const float* __restrict__ in, const float* __restrict__ wt,
        float* __restrict__ out, int C) {
    __shared__ float s[10][260];
    const int y0 = blockIdx.x * 8;
    const int zc = blockIdx.y;
    const int c = zc % C;
    const int tid = threadIdx.x;
    const float* ip = in + (size_t)zc * HW;

    float w[9];
#pragma unroll
    for (int i = 0; i < 9; ++i) w[i] = __ldg(&wt[c * 9 + i]);

#pragma unroll
    for (int pass = 0; pass < 3; ++pass) {
        int idx = tid + pass * 256;
        if (idx < 640) {
            int r = idx >> 6, c4 = (idx & 63) * 4;
            int gy = y0 + r - 1;
            float4 v = make_float4(0.f, 0.f, 0.f, 0.f);
            if (gy >= 0 && gy < HDIM) v = *(const float4*)(ip + gy * WDIM + c4);
            *(float4*)&s[r][c4] = v;
        }
    }
    __syncthreads();

#pragma unroll
    for (int pass = 0; pass < 2; ++pass) {
        const int r = (tid >> 6) + pass * 4;
        const int px0 = (tid & 63) * 4;
        float acc[4] = {0.f, 0.f, 0.f, 0.f};
#pragma unroll
        for (int ky = 0; ky < 3; ++ky) {
            const float* row = s[r + ky];
            float4 m = *(const float4*)&row[px0];
            float v0 = (px0 == 0) ? 0.f : row[px0 - 1];
            float v5 = (px0 == 252) ? 0.f : row[px0 + 4];
            float v[6] = {v0, m.x, m.y, m.z, m.w, v5};
#pragma unroll
            for (int kx = 0; kx < 3; ++kx)
#pragma unroll
                for (int p = 0; p < 4; ++p)
                    acc[p] += w[ky * 3 + kx] * v[kx + p];
        }
        *(float4*)&out[(size_t)zc * HW + (y0 + r) * WDIM + px0] =
            make_float4(acc[0], acc[1], acc[2], acc[3]);
    }
}

// ---------------- Gram + norms ----------------
__global__ void gramnorm_k(const float* __restrict__ q, int qcs,
                           const float* __restrict__ k, int kcs,
                           float* __restrict__ G, float* __restrict__ nq,
                           float* __restrict__ nk) {
    const int b = blockIdx.z, h = blockIdx.y;
    const int p0 = blockIdx.x * 4096 + threadIdx.x;
    const float* qb = q + ((size_t)b * qcs + h * 8) * HW;
    const float* kb = k + ((size_t)b * kcs + h * 8) * HW;
    float acc[80];
#pragma unroll
    for (int i = 0; i < 80; ++i) acc[i] = 0.f;
    for (int it = 0; it < 16; ++it) {
        int p = p0 + it * 256;
        float qv[8], kv[8];
#pragma unroll
        for (int c = 0; c < 8; ++c) {
            qv[c] = qb[(size_t)c * HW + p];
            kv[c] = kb[(size_t)c * HW + p];
        }
#pragma unroll
        for (int c = 0; c < 8; ++c) {
            acc[64 + c] += qv[c] * qv[c];
            acc[72 + c] += kv[c] * kv[c];
#pragma unroll
            for (int d = 0; d < 8; ++d) acc[c * 8 + d] += qv[c] * kv[d];
        }
    }
    __shared__ float red[80][8];
    const int lane = threadIdx.x & 31, warp = threadIdx.x >> 5;
#pragma unroll
    for (int i = 0; i < 80; ++i) {
        float v = acc[i];
        v += __shfl_down_sync(0xffffffffu, v, 16);
        v += __shfl_down_sync(0xffffffffu, v, 8);
        v += __shfl_down_sync(0xffffffffu, v, 4);
        v += __shfl_down_sync(0xffffffffu, v, 2);
        v += __shfl_down_sync(0xffffffffu, v, 1);
        if (lane == 0) red[i][warp] = v;
    }
    __syncthreads();
    if (threadIdx.x < 80) {
        float s = 0.f;
#pragma unroll
        for (int w = 0; w < 8; ++w) s += red[threadIdx.x][w];
        int i = threadIdx.x;
        if (i < 64)
            atomicAdd(&G[(((size_t)b * 8 + h) * 8 + (i >> 3)) * 8 + (i & 7)], s);
        else if (i < 72)
            atomicAdd(&nq[b * 64 + h * 8 + (i - 64)], s);
        else
            atomicAdd(&nk[b * 64 + h * 8 + (i - 72)], s);
    }
}

// ---------------- softmax + proj fold ----------------
__global__ void softmax_meff_k(const float* __restrict__ temp, const float* __restrict__ Wproj,
                               const float* __restrict__ G, const float* __restrict__ nq,
                               const float* __restrict__ nk, float* __restrict__ Meff) {
    const int b = blockIdx.x;
    const int t = threadIdx.x;
    __shared__ float attn[8][8][8];
    {
        int h = t >> 3, c = t & 7;
        float nqc = fmaxf(sqrtf(nq[b * 64 + h * 8 + c]), 1e-12f);
        float row[8];
        float m = -1e30f;
#pragma unroll
        for (int d = 0; d < 8; ++d) {
            float nkd = fmaxf(sqrtf(nk[b * 64 + h * 8 + d]), 1e-12f);
            row[d] = temp[h] * G[(((size_t)b * 8 + h) * 8 + c) * 8 + d] / (nqc * nkd);
            m = fmaxf(m, row[d]);
        }
        float sum = 0.f;
#pragma unroll
        for (int d = 0; d < 8; ++d) { row[d] = expf(row[d] - m); sum += row[d]; }
        float inv = 1.f / sum;
#pragma unroll
        for (int d = 0; d < 8; ++d) attn[h][c][d] = row[d] * inv;
    }
    __syncthreads();
    const int o = t;
    for (int dg = 0; dg < 64; ++dg) {
        int hh = dg >> 3, j = dg & 7;
        float s = 0.f;
#pragma unroll
        for (int i = 0; i < 8; ++i) s += Wproj[o * 64 + hh * 8 + i] * attn[hh][i][j];
        Meff[((size_t)b * 64 + o) * 64 + dg] = s;
    }
}

// ---------------- host orchestration (two-stream fork/join, graph-capturable) ----------------
extern "C" void kernel_launch(void* const* d_in, const int* in_sizes, int n_in,
                              void* d_out, int out_size) {
    const float* spa    = (const float*)d_in[0];
    const float* fre    = (const float*)d_in[1];
    const float* W_fre  = (const float*)d_in[2];
    const float* b_fre  = (const float*)d_in[3];
    const float* W_spa  = (const float*)d_in[4];
    const float* b_spa  = (const float*)d_in[5];
    const float* temp   = (const float*)d_in[6];
    const float* Wq     = (const float*)d_in[7];
    const float* Wq_dw  = (const float*)d_in[8];
    const float* Wkv    = (const float*)d_in[9];
    const float* Wkv_dw = (const float*)d_in[10];
    const float* Wproj  = (const float*)d_in[11];
    const float* Wf1    = (const float*)d_in[12];
    const float* bf1    = (const float*)d_in[13];
    const float* Wf2    = (const float*)d_in[14];
    const float* bf2    = (const float*)d_in[15];
    float* out = (float*)d_out;

    float *pfre1, *pspa1, *ptmp, *pq, *pfre2, *pspa2, *pkv0, *pkv, *pstats, *pmeff;
    __nv_bfloat16 *phi, *plo;
    uint2* pwk;
    cudaGetSymbolAddress((void**)&pfre1, g_fre1);
    cudaGetSymbolAddress((void**)&pspa1, g_spa1);
    cudaGetSymbolAddress((void**)&ptmp,  g_tmp);
    cudaGetSymbolAddress((void**)&pq,    g_q);
    cudaGetSymbolAddress((void**)&pfre2, g_fre2);
    cudaGetSymbolAddress((void**)&pspa2, g_spa2);
    cudaGetSymbolAddress((void**)&pkv0,  g_kv0);
    cudaGetSymbolAddress((void**)&pkv,   g_kv);
    cudaGetSymbolAddress((void**)&pstats, g_stats);
    cudaGetSymbolAddress((void**)&pmeff, g_Meff);
    cudaGetSymbolAddress((void**)&phi,   g_nh_hi);
    cudaGetSymbolAddress((void**)&plo,   g_nh_lo);
    cudaGetSymbolAddress((void**)&pwk,   g_wpk2);
    float* pG  = pstats;
    float* pnq = pstats + 2048;
    float* pnk = pstats + 2304;
    const size_t NHN = (size_t)BSZ * HW * 64;
    __nv_bfloat16 *h0 = phi, *h1 = phi + NHN, *h2 = phi + 2*NHN, *h3 = phi + 3*NHN, *h4 = phi + 4*NHN;
    __nv_bfloat16 *l0 = plo, *l1 = plo + NHN, *l2 = plo + 2*NHN, *l3 = plo + 3*NHN, *l4 = plo + 4*NHN;
    uint2 *w0 = pwk, *w1 = pwk + 18432, *wF1 = pwk + 36864, *wF2 = pwk + 73728;

    // one-time stream/event setup (outside graph capture on first call)
    static cudaStream_t s1 = nullptr;
    static cudaEvent_t evF0, evSpa, evFork1, evQ1, evFork2, evQ2;
    if (s1 == nullptr) {
        cudaStreamCreateWithFlags(&s1, cudaStreamNonBlocking);
        cudaEventCreateWithFlags(&evF0,    cudaEventDisableTiming);
        cudaEventCreateWithFlags(&evSpa,   cudaEventDisableTiming);
        cudaEventCreateWithFlags(&evFork1, cudaEventDisableTiming);
        cudaEventCreateWithFlags(&evQ1,    cudaEventDisableTiming);
        cudaEventCreateWithFlags(&evFork2, cudaEventDisableTiming);
        cudaEventCreateWithFlags(&evQ2,    cudaEventDisableTiming);
    }

    cudaFuncSetAttribute(gconv_k<64, 64, false, false, true, false, 3>,
                         cudaFuncAttributeMaxDynamicSharedMemorySize, GC_SMEM);
    cudaFuncSetAttribute(gconv_k<128, 64, false, false, false, true, 3>,
                         cudaFuncAttributeMaxDynamicSharedMemorySize, GC_SMEM);
    cudaFuncSetAttribute(gconv_k<64, 128, true, true, false, false, 2>,
                         cudaFuncAttributeMaxDynamicSharedMemorySize, GC_SMEM);
    const int C1_SMEM_64  = 34816 + 64 * 144 * 2;    // 53248
    const int C1_SMEM_128 = 34816 + 128 * 144 * 2;   // 71680
    cudaFuncSetAttribute(c1mma_k<64, false, false>,
                         cudaFuncAttributeMaxDynamicSharedMemorySize, C1_SMEM_64);
    cudaFuncSetAttribute(c1mma_k<64, true, true>,
                         cudaFuncAttributeMaxDynamicSharedMemorySize, C1_SMEM_64);
    cudaFuncSetAttribute(c1mma_k<128, false, false>,
                         cudaFuncAttributeMaxDynamicSharedMemorySize, C1_SMEM_128);

    const dim3 blk(256);
    const dim3 gt(2048, 2, BSZ);            // transpose
    const dim3 gg(2, 256, BSZ);             // gconv
    const dim3 g1(512, BSZ);                // c1mma
    const dim3 gdw64(32, BSZ * 64);
    const dim3 gdw128(32, BSZ * 128);
    const dim3 ggram(16, 8, BSZ);

    // ---- fork s1 from default stream ----
    cudaEventRecord(evF0, 0);
    cudaStreamWaitEvent(s1, evF0, 0);

    // prep: fre branch on s0, spa branch on s1 (launch #4 = first gconv)
    wpack_k<<<72,  blk>>>(W_fre, w0, 64, 64);
    wpack_k<<<72,  blk, 0, s1>>>(W_spa, w1, 64, 64);
    nchw2nhwc_k<<<gt, blk>>>(fre, h0, l0);
    gconv_k<64, 64, false, false, true, false, 3><<<gg, blk, GC_SMEM>>>(
        h0, l0, h0, l0, w0, b_fre, pfre1, nullptr, nullptr, nullptr, nullptr);
    nchw2nhwc_k<<<gt, blk, 0, s1>>>(spa, h1, l1);
    gconv_k<64, 64, false, false, true, false, 3><<<gg, blk, GC_SMEM, s1>>>(
        h1, l1, h1, l1, w1, b_spa, pspa1, nullptr, nullptr, nullptr, nullptr);
    wpack_k<<<144, blk, 0, s1>>>(Wf1, wF1, 128, 64);
    wpack_k<<<144, blk, 0, s1>>>(Wf2, wF2, 64, 128);
    cudaEventRecord(evSpa, s1);

    // ---- attention 1 ----
    // q chain (needs fre1, ready on s0) -> s1
    cudaEventRecord(evFork1, 0);
    cudaStreamWaitEvent(s1, evFork1, 0);
    c1mma_k<64, false, false><<<g1, blk, C1_SMEM_64, s1>>>(pfre1, 64, 0, Wq, 0, nullptr, ptmp, 64, nullptr, nullptr);
    dw3x3_k<<<gdw64, blk, 0, s1>>>(ptmp, Wq_dw, pq, 64);
    zero_k<<<10, blk, 0, s1>>>(pstats, 2560);
    cudaEventRecord(evQ1, s1);
    // kv chain (needs spa1 from s1) -> s0
    cudaStreamWaitEvent(0, evSpa, 0);
    c1mma_k<128, false, false><<<g1, blk, C1_SMEM_128>>>(pspa1, 64, 0, Wkv, 0, nullptr, pkv0, 128, nullptr, nullptr);
    dw3x3_k<<<gdw128, blk>>>(pkv0, Wkv_dw, pkv, 128);
    cudaStreamWaitEvent(0, evQ1, 0);
    gramnorm_k<<<ggram, blk>>>(pq, 64, pkv, 128, pG, pnq, pnk);
    softmax_meff_k<<<BSZ, 64>>>(temp, Wproj, pG, pnq, pnk, pmeff);
    cudaEventRecord(evFork2, 0);   // pq/pstats free after this point
    c1mma_k<64, true, true><<<g1, blk, C1_SMEM_64>>>(pkv, 128, 64, pmeff, 64 * 64, pfre1, pfre2, 64, h2, l2);

    // ---- attention 2 ----
    // q chain (needs spa1 + gram1/softmax1 done) -> s1
    cudaStreamWaitEvent(s1, evFork2, 0);
    c1mma_k<64, false, false><<<g1, blk, C1_SMEM_64, s1>>>(pspa1, 64, 0, Wq, 0, nullptr, ptmp, 64, nullptr, nullptr);
    dw3x3_k<<<gdw64, blk, 0, s1>>>(ptmp, Wq_dw, pq, 64);
    zero_k<<<10, blk, 0, s1>>>(pstats, 2560);
    cudaEventRecord(evQ2, s1);
    // kv chain (needs fre2) -> s0
    c1mma_k<128, false, false><<<g1, blk, C1_SMEM_128>>>(pfre2, 64, 0, Wkv, 0, nullptr, pkv0, 128, nullptr, nullptr);
    dw3x3_k<<<gdw128, blk>>>(pkv0, Wkv_dw, pkv, 128);
    cudaStreamWaitEvent(0, evQ2, 0);
    gramnorm_k<<<ggram, blk>>>(pq, 64, pkv, 128, pG, pnq, pnk);
    softmax_meff_k<<<BSZ, 64>>>(temp, Wproj, pG, pnq, pnk, pmeff);
    c1mma_k<64, true, true><<<g1, blk, C1_SMEM_64>>>(pkv, 128, 64, pmeff, 64 * 64, pspa1, pspa2, 64, h3, l3);

    // ---- fuse path: F1 (concat -> t1 NHWC), F2 + final gate fused ----
    gconv_k<128, 64, false, false, false, true, 3><<<gg, blk, GC_SMEM>>>(
        h2, l2, h3, l3, wF1, bf1, nullptr, h4, l4, nullptr, nullptr);
    gconv_k<64, 128, true, true, false, false, 2><<<gg, blk, GC_SMEM>>>(
        h4, l4, h4, l4, wF2, bf2, out, nullptr, nullptr, pfre2, pspa2);
}

// round 14
// speedup vs baseline: 1.4022x; 1.0363x over previous
#include <cuda_runtime.h>
#include <cuda_bf16.h>
#include <math.h>
#include <stdint.h>

#define BSZ 4
#define HDIM 256
#define WDIM 256
#define HW 65536

// ---------------- scratch (device globals) ----------------
__device__ float g_fre1[(size_t)BSZ * 64 * HW];
__device__ float g_spa1[(size_t)BSZ * 64 * HW];
__device__ float g_tmp [(size_t)BSZ * 64 * HW];
__device__ float g_q   [(size_t)BSZ * 64 * HW];
__device__ float g_fre2[(size_t)BSZ * 64 * HW];
__device__ float g_spa2[(size_t)BSZ * 64 * HW];
__device__ float g_kv0 [(size_t)BSZ * 128 * HW];
__device__ float g_kv  [(size_t)BSZ * 128 * HW];
__device__ float g_stats[2560];
__device__ float g_Meff[BSZ * 64 * 64];
// NHWC bf16 hi/lo slots: 0=fre 1=spa 2=fre2 3=spa2 4=t1
__device__ __nv_bfloat16 g_nh_hi[5][(size_t)BSZ * HW * 64];
__device__ __nv_bfloat16 g_nh_lo[5][(size_t)BSZ * HW * 64];
// packed weights uint4 {hi(k0pair), lo(k0pair), hi(k1pair), lo(k1pair)}
__device__ uint4 g_wpk4[55296];

// ---------------- mma.sync / cp.async helpers (baseline sm_80+, no 'a' arch) ----------------
__device__ __forceinline__ uint32_t smem_u32(const void* p) {
    uint32_t a;
    asm("{ .reg .u64 t; cvta.to.shared.u64 t, %1; cvt.u32.u64 %0, t; }" : "=r"(a) : "l"(p));
    return a;
}
__device__ __forceinline__ void ldmA(uint32_t r[4], uint32_t a) {
    asm volatile("ldmatrix.sync.aligned.m8n8.x4.shared.b16 {%0,%1,%2,%3}, [%4];"
                 : "=r"(r[0]), "=r"(r[1]), "=r"(r[2]), "=r"(r[3]) : "r"(a));
}
__device__ __forceinline__ void ldmT(uint32_t r[4], uint32_t a) {
    asm volatile("ldmatrix.sync.aligned.m8n8.x4.trans.shared.b16 {%0,%1,%2,%3}, [%4];"
                 : "=r"(r[0]), "=r"(r[1]), "=r"(r[2]), "=r"(r[3]) : "r"(a));
}
__device__ __forceinline__ void mma16816(float* c, const uint32_t* a, const uint32_t* b) {
    asm volatile(
        "mma.sync.aligned.m16n8k16.row.col.f32.bf16.bf16.f32 "
        "{%0,%1,%2,%3}, {%4,%5,%6,%7}, {%8,%9}, {%0,%1,%2,%3};"
        : "+f"(c[0]), "+f"(c[1]), "+f"(c[2]), "+f"(c[3])
        : "r"(a[0]), "r"(a[1]), "r"(a[2]), "r"(a[3]), "r"(b[0]), "r"(b[1]));
}
__device__ __forceinline__ void cpa16(uint32_t d, const void* s, int pb) {
    asm volatile("cp.async.cg.shared.global [%0], [%1], 16, %2;"
                 :: "r"(d), "l"(s), "r"(pb) : "memory");
}
__device__ __forceinline__ void cpa_commit() {
    asm volatile("cp.async.commit_group;" ::: "memory");
}
__device__ __forceinline__ void cpa_wait1() {
    asm volatile("cp.async.wait_group 1;" ::: "memory");
}
__device__ __forceinline__ void cpa_wait0() {
    asm volatile("cp.async.wait_group 0;" ::: "memory");
}
__device__ __forceinline__ void split4(float4 v, uint2& hi, uint2& lo) {
    __nv_bfloat16 h0 = __float2bfloat16(v.x), h1 = __float2bfloat16(v.y);
    __nv_bfloat16 h2 = __float2bfloat16(v.z), h3 = __float2bfloat16(v.w);
    __nv_bfloat16 l0 = __float2bfloat16(v.x - __bfloat162float(h0));
    __nv_bfloat16 l1 = __float2bfloat16(v.y - __bfloat162float(h1));
    __nv_bfloat16 l2 = __float2bfloat16(v.z - __bfloat162float(h2));
    __nv_bfloat16 l3 = __float2bfloat16(v.w - __bfloat162float(h3));
    hi.x = ((uint32_t)__bfloat16_as_ushort(h1) << 16) | __bfloat16_as_ushort(h0);
    hi.y = ((uint32_t)__bfloat16_as_ushort(h3) << 16) | __bfloat16_as_ushort(h2);
    lo.x = ((uint32_t)__bfloat16_as_ushort(l1) << 16) | __bfloat16_as_ushort(l0);
    lo.y = ((uint32_t)__bfloat16_as_ushort(l3) << 16) | __bfloat16_as_ushort(l2);
}

__global__ void zero_k(float* p, int n) {
    int i = blockIdx.x * 256 + threadIdx.x;
    if (i < n) p[i] = 0.f;
}
__device__ __forceinline__ float fix_nan(float x) { return isfinite(x) ? x : 1e-5f; }
__device__ __forceinline__ float sigm(float x) { return 1.f / (1.f + expf(-x)); }

// ---------------- merged NCHW fp32 -> NHWC bf16 hi/lo (two tensors via z) ----------------
__global__ void nchw2nhwc2_k(const float* __restrict__ inA, const float* __restrict__ inB,
                             __nv_bfloat16* __restrict__ ohiA, __nv_bfloat16* __restrict__ oloA,
                             __nv_bfloat16* __restrict__ ohiB, __nv_bfloat16* __restrict__ oloB) {
    __shared__ float s[32][33];
    const int z = blockIdx.z;
    const float* in = (z < BSZ) ? inA : inB;
    __nv_bfloat16* ohi = (z < BSZ) ? ohiA : ohiB;
    __nv_bfloat16* olo = (z < BSZ) ? oloA : oloB;
    const int b = z & 3, ch0 = blockIdx.y * 32, p0 = blockIdx.x * 32;
    const int lx = threadIdx.x & 31, ly = threadIdx.x >> 5;
#pragma unroll
    for (int i = 0; i < 4; ++i) {
        int c = ly + i * 8;
        s[c][lx] = in[((size_t)(b * 64 + ch0 + c)) * HW + p0 + lx];
    }
    __syncthreads();
#pragma unroll
    for (int i = 0; i < 4; ++i) {
        int p = ly + i * 8;
        float v = s[lx][p];
        __nv_bfloat16 h = __float2bfloat16(v);
        size_t idx = ((size_t)b * HW + p0 + p) * 64 + ch0 + lx;
        ohi[idx] = h;
        olo[idx] = __float2bfloat16(v - __bfloat162float(h));
    }
}

// ---------------- weight pack: OIHW -> [tap][chunk16][co][tig] uint4 ----------------
// uint4 = {hi(ci0,ci0+1), lo(ci0,ci0+1), hi(ci1,ci1+1), lo(ci1,ci1+1)}, ci1=ci0+8
__global__ void wpack_k(const float* __restrict__ W, uint4* __restrict__ pk, int CIN, int CO) {
    int NCH = CIN >> 4;
    int n = 9 * NCH * CO * 4;
    int i = blockIdx.x * 256 + threadIdx.x;
    if (i >= n) return;
    int tig = i & 3;
    int t2 = i >> 2;
    int co = t2 % CO;
    int t3 = t2 / CO;
    int chv = t3 % NCH, tap = t3 / NCH;
    int ci0 = chv * 16 + 2 * tig;
    uint4 o;
#pragma unroll
    for (int half = 0; half < 2; ++half) {
        int ci = ci0 + half * 8;
        float w0 = W[((size_t)co * CIN + ci) * 9 + tap];
        float w1 = W[((size_t)co * CIN + ci + 1) * 9 + tap];
        __nv_bfloat16 h0 = __float2bfloat16(w0), h1 = __float2bfloat16(w1);
        __nv_bfloat16 l0 = __float2bfloat16(w0 - __bfloat162float(h0));
        __nv_bfloat16 l1 = __float2bfloat16(w1 - __bfloat162float(h1));
        uint32_t hp = ((uint32_t)__bfloat16_as_ushort(h1) << 16) | __bfloat16_as_ushort(h0);
        uint32_t lp = ((uint32_t)__bfloat16_as_ushort(l1) << 16) | __bfloat16_as_ushort(l0);
        if (half == 0) { o.x = hp; o.y = lp; } else { o.z = hp; o.w = lp; }
    }
    pk[i] = o;
}

// ---------------- mma.sync bf16 3-term implicit-GEMM 3x3 conv (R11 tiling) ----------------
#define GC_BUF 37440                 // 130 px * 144 B * 2 (hi+lo)
#define GC_SMEM (2 * GC_BUF)         // 74880
#define LOOFF 18720                  // 130 * 144

__device__ __forceinline__ void gc_stage(const __nv_bfloat16* __restrict__ shi,
                                         const __nv_bfloat16* __restrict__ slo,
                                         int b, int gy, bool yok, int xbase,
                                         uint32_t dst, int tid) {
    const int gyc = yok ? gy : 0;
    for (int idx = tid; idx < 260; idx += 256) {
        const int px = idx >> 1, q = idx & 1;
        const int gx = xbase + px - 1;
        const bool ok = yok && gx >= 0 && gx < WDIM;
        const int gxc = (gx >= 0 && gx < WDIM) ? gx : 0;
        const int pb = ok ? 16 : 0;
        size_t off = ((size_t)b * HW + (size_t)gyc * WDIM + gxc) * 64 + q * 32;
        const char* ph = (const char*)(shi + off);
        const char* pl = (const char*)(slo + off);
        uint32_t dh = dst + px * 144 + q * 64;
        uint32_t dl = dst + LOOFF + px * 144 + q * 64;
#pragma unroll
        for (int i = 0; i < 4; ++i) {
            cpa16(dh + i * 16, ph + i * 16, pb);
            cpa16(dl + i * 16, pl + i * 16, pb);
        }
    }
    cpa_commit();
}

template <int CIN, int CO, bool SIG, bool FINAL, bool NCHWOUT, bool NHWCOUT, int MINB, bool MERGED>
__global__ void __launch_bounds__(256, MINB)
gconv_k(const __nv_bfloat16* __restrict__ sAhi, const __nv_bfloat16* __restrict__ sAlo,
        const __nv_bfloat16* __restrict__ sBhi, const __nv_bfloat16* __restrict__ sBlo,
        const uint4* __restrict__ wb, const float* __restrict__ bias,
        float* __restrict__ outc,
        __nv_bfloat16* __restrict__ onhi, __nv_bfloat16* __restrict__ onlo,
        const float* __restrict__ resA, const float* __restrict__ resB,
        const __nv_bfloat16* __restrict__ A2hi, const __nv_bfloat16* __restrict__ A2lo,
        const uint4* __restrict__ wb2, const float* __restrict__ bias2,
        float* __restrict__ outc2) {
    extern __shared__ char smem[];
    constexpr int NGRP = CIN / 64;
    constexpr int NWN = CO / 32;
    constexpr int NWM = 8 / NWN;
    constexpr int MPW = 128 / NWM;
    constexpr int MT  = MPW / 16;
    const int NSTG = 3 * NGRP;

    const int tid = threadIdx.x, wid = tid >> 5, lane = tid & 31;
    const int warpN = wid % NWN, warpM = wid / NWN;
    int b = blockIdx.z;
    const __nv_bfloat16* Ahi = sAhi;
    const __nv_bfloat16* Alo = sAlo;
    const __nv_bfloat16* Bhi = sBhi;
    const __nv_bfloat16* Blo = sBlo;
    const uint4* wbp = wb;
    const float* biasp = bias;
    float* outp = outc;
    if (MERGED && blockIdx.z >= BSZ) {
        b -= BSZ;
        Ahi = A2hi; Alo = A2lo; Bhi = A2hi; Blo = A2lo;
        wbp = wb2; biasp = bias2; outp = outc2;
    }
    const int y = blockIdx.y, xbase = blockIdx.x * 128;
    const int g = lane >> 2, tig = lane & 3;
    const uint32_t sb = smem_u32(smem);

    float acc[MT][4][4];
#pragma unroll
    for (int mt = 0; mt < MT; ++mt)
#pragma unroll
        for (int nt = 0; nt < 4; ++nt)
#pragma unroll
            for (int q = 0; q < 4; ++q) acc[mt][nt][q] = 0.f;

    // prologue: issue stage 0 into buf 0
    {
        const int gy = y - 1;
        gc_stage(Ahi, Alo, b, gy, (gy >= 0) && (gy < HDIM), xbase, sb, tid);
    }

    for (int st = 0; st < NSTG; ++st) {
        __syncthreads();   // all warps done with buf[(st+1)&1] (computed at st-1)
        if (st + 1 < NSTG) {
            const int dyN = (st + 1) / NGRP, grpN = (st + 1) % NGRP;
            const int gyN = y + dyN - 1;
            gc_stage(grpN ? Bhi : Ahi, grpN ? Blo : Alo, b, gyN,
                     (gyN >= 0) && (gyN < HDIM), xbase,
                     sb + ((st + 1) & 1) * GC_BUF, tid);
            cpa_wait1();
        } else {
            cpa_wait0();
        }
        __syncthreads();   // staged data for st visible

        const int dyI = st / NGRP, grp = st % NGRP;
        const uint32_t sbuf = sb + (st & 1) * GC_BUF;
#pragma unroll
        for (int dxI = 0; dxI < 3; ++dxI) {
            const int tap = dyI * 3 + dxI;
#pragma unroll
            for (int ch = 0; ch < 4; ++ch) {
                const uint4* wc = wbp + (size_t)(tap * (CIN / 16) + grp * 4 + ch) * CO * 4;
                uint32_t bh[4][2], bl[4][2];
#pragma unroll
                for (int nt = 0; nt < 4; ++nt) {
                    int n = warpN * 32 + nt * 8 + g;
                    uint4 w4 = __ldg(&wc[n * 4 + tig]);
                    bh[nt][0] = w4.x; bl[nt][0] = w4.y;
                    bh[nt][1] = w4.z; bl[nt][1] = w4.w;
                }
#pragma unroll
                for (int mt = 0; mt < MT; ++mt) {
                    const int pxl = warpM * MPW + mt * 16 + (lane & 15) + dxI;
                    uint32_t addr = sbuf + pxl * 144 + ch * 32 + ((lane >> 4) & 1) * 16;
                    uint32_t ah[4], al[4];
                    ldmA(ah, addr);
                    ldmA(al, addr + LOOFF);
#pragma unroll
                    for (int nt = 0; nt < 4; ++nt) {
                        mma16816(acc[mt][nt], ah, bh[nt]);
                        mma16816(acc[mt][nt], al, bh[nt]);
                        mma16816(acc[mt][nt], ah, bl[nt]);
                    }
                }
            }
        }
    }

    // ---------------- epilogue through smem ----------------
    float* s_out = (float*)smem;  // [32 co][132 px]
    for (int co0 = 0; co0 < CO; co0 += 32) {
        __syncthreads();
        if (warpN == (co0 >> 5)) {
#pragma unroll
            for (int mt = 0; mt < MT; ++mt) {
                const int px = warpM * MPW + mt * 16 + g;
#pragma unroll
                for (int nt = 0; nt < 4; ++nt) {
                    const int cl = nt * 8 + tig * 2;
                    s_out[cl * 132 + px]           = acc[mt][nt][0];
                    s_out[(cl + 1) * 132 + px]     = acc[mt][nt][1];
                    s_out[cl * 132 + px + 8]       = acc[mt][nt][2];
                    s_out[(cl + 1) * 132 + px + 8] = acc[mt][nt][3];
                }
            }
        }
        __syncthreads();
        if (FINAL) {
            const int cl = tid >> 3, px0 = (tid & 7) * 16;
            const int c = (co0 + cl) & 63;
            const bool second = (co0 + cl) >= 64;
            const float bv = __ldg(&biasp[co0 + cl]);
            const float* res = second ? resB : resA;
            size_t off = ((size_t)(b * 64 + c)) * HW + (size_t)y * WDIM + xbase + px0;
#pragma unroll
            for (int i = 0; i < 16; i += 4) {
                float4 rv = *(const float4*)(res + off + i);
                float4 o;
                o.x = sigm(s_out[cl * 132 + px0 + i]     + bv) * rv.x;
                o.y = sigm(s_out[cl * 132 + px0 + i + 1] + bv) * rv.y;
                o.z = sigm(s_out[cl * 132 + px0 + i + 2] + bv) * rv.z;
                o.w = sigm(s_out[cl * 132 + px0 + i + 3] + bv) * rv.w;
                if (!second) {
                    *(float4*)(outp + off + i) = o;
                } else {
                    float4 prev = *(const float4*)(outp + off + i);
                    o.x = fix_nan(prev.x + o.x);
                    o.y = fix_nan(prev.y + o.y);
                    o.z = fix_nan(prev.z + o.z);
                    o.w = fix_nan(prev.w + o.w);
                    *(float4*)(outp + off + i) = o;
                }
            }
        } else {
            if (NCHWOUT) {
                const int cl = tid >> 3, px0 = (tid & 7) * 16;
                const float bv = __ldg(&biasp[co0 + cl]);
                float v[16];
#pragma unroll
                for (int i = 0; i < 16; ++i) {
                    float x = s_out[cl * 132 + px0 + i] + bv;
                    if (SIG) x = sigm(x);
                    v[i] = x;
                }
                float* op = outp + ((size_t)(b * CO + co0 + cl)) * HW + (size_t)y * WDIM + xbase + px0;
#pragma unroll
                for (int i = 0; i < 4; ++i)
                    *(float4*)(op + i * 4) = make_float4(v[i*4], v[i*4+1], v[i*4+2], v[i*4+3]);
            }
            if (NHWCOUT) {
                const int px = tid >> 1, cg = (tid & 1) * 16;
                const size_t pix = (size_t)b * HW + (size_t)y * WDIM + xbase + px;
                ushort hb[16], lb[16];
#pragma unroll
                for (int i = 0; i < 16; ++i) {
                    int cl = cg + i;
                    float x = s_out[cl * 132 + px] + __ldg(&biasp[co0 + cl]);
                    if (SIG) x = sigm(x);
                    __nv_bfloat16 h = __float2bfloat16(x);
                    hb[i] = __bfloat16_as_ushort(h);
                    lb[i] = __bfloat16_as_ushort(__float2bfloat16(x - __bfloat162float(h)));
                }
                uint4* oh = (uint4*)(onhi + pix * 64 + co0 + cg);
                uint4* ol = (uint4*)(onlo + pix * 64 + co0 + cg);
                oh[0] = *(uint4*)&hb[0]; oh[1] = *(uint4*)&hb[8];
                ol[0] = *(uint4*)&lb[0]; ol[1] = *(uint4*)&lb[8];
            }
        }
    }
}

// ---------------- conv 1x1 via mma.sync (3-term bf16) ----------------
template <int CO, bool RESID, bool NHWCOUT>
__global__ void __launch_bounds__(256)
c1mma_k(const float* __restrict__ in, int in_cs, int in_off,
        const float* __restrict__ W, int w_bs,
        const float* __restrict__ resid,
        float* __restrict__ out, int out_cs,
        __nv_bfloat16* __restrict__ onhi, __nv_bfloat16* __restrict__ onlo) {
    extern __shared__ char smem[];
    constexpr int BLO = 17408, WHI = 34816;
    constexpr int WLO = WHI + CO * 144;
    constexpr int MCO = CO / 4;
    constexpr int MT  = MCO / 16;

    const int tid = threadIdx.x, lane = tid & 31, wid = tid >> 5;
    const int warpN = wid & 1, warpM = wid >> 1;
    const int b = blockIdx.y;
    const int pxbase = blockIdx.x * 128;
    const uint32_t sb = smem_u32(smem);

    const float* ip = in + ((size_t)b * in_cs + in_off) * HW + pxbase;
#pragma unroll
    for (int pass = 0; pass < 8; ++pass) {
        const int ci = pass * 8 + (tid >> 5);
        const int px = (tid & 31) * 4;
        float4 v = *(const float4*)(ip + (size_t)ci * HW + px);
        uint2 hi, lo;
        split4(v, hi, lo);
        *(uint2*)(smem + ci * 272 + px * 2)       = hi;
        *(uint2*)(smem + BLO + ci * 272 + px * 2) = lo;
    }
    const float* wp = W + (size_t)b * w_bs;
    for (int i = tid; i < CO * 16; i += 256) {
        const int co = i >> 4, c4 = (i & 15) * 4;
        float4 v = *(const float4*)(wp + co * 64 + c4);
        uint2 hi, lo;
        split4(v, hi, lo);
        *(uint2*)(smem + WHI + co * 144 + c4 * 2) = hi;
        *(uint2*)(smem + WLO + co * 144 + c4 * 2) = lo;
    }
    __syncthreads();

    float acc[MT][8][4];
#pragma unroll
    for (int mt = 0; mt < MT; ++mt)
#pragma unroll
        for (int j = 0; j < 8; ++j)
#pragma unroll
            for (int q = 0; q < 4; ++q) acc[mt][j][q] = 0.f;

#pragma unroll
    for (int k = 0; k < 4; ++k) {
        uint32_t ah[MT][4], al[MT][4];
#pragma unroll
        for (int mt = 0; mt < MT; ++mt) {
            uint32_t addr = sb + WHI + (warpM * MCO + mt * 16 + (lane & 15)) * 144
                          + k * 32 + (lane >> 4) * 16;
            ldmA(ah[mt], addr);
            ldmA(al[mt], addr + CO * 144);
        }
        uint32_t bh[8][2], bl[8][2];
#pragma unroll
        for (int j = 0; j < 4; ++j) {
            uint32_t addr = sb + (k * 16 + (lane & 15)) * 272
                          + (warpN * 64 + j * 16 + (lane >> 4) * 8) * 2;
            uint32_t r[4];
            ldmT(r, addr);
            bh[2*j][0] = r[0]; bh[2*j][1] = r[1];
            bh[2*j+1][0] = r[2]; bh[2*j+1][1] = r[3];
            ldmT(r, addr + BLO);
            bl[2*j][0] = r[0]; bl[2*j][1] = r[1];
            bl[2*j+1][0] = r[2]; bl[2*j+1][1] = r[3];
        }
#pragma unroll
        for (int mt = 0; mt < MT; ++mt)
#pragma unroll
            for (int j = 0; j < 8; ++j) {
                mma16816(acc[mt][j], ah[mt], bh[j]);
                mma16816(acc[mt][j], al[mt], bh[j]);
                mma16816(acc[mt][j], ah[mt], bl[j]);
            }
    }

    if (!NHWCOUT) {
#pragma unroll
        for (int mt = 0; mt < MT; ++mt)
#pragma unroll
            for (int j = 0; j < 8; ++j) {
                const int co = warpM * MCO + mt * 16 + (lane >> 2);
                const int px = warpN * 64 + j * 8 + (lane & 3) * 2;
                size_t o1 = ((size_t)b * out_cs + co) * HW + pxbase + px;
                size_t o2 = o1 + (size_t)8 * HW;
                float2 r1 = make_float2(acc[mt][j][0], acc[mt][j][1]);
                float2 r2 = make_float2(acc[mt][j][2], acc[mt][j][3]);
                if (RESID) {
                    float2 q1 = *(const float2*)(resid + o1);
                    float2 q2 = *(const float2*)(resid + o2);
                    r1.x += q1.x; r1.y += q1.y; r2.x += q2.x; r2.y += q2.y;
                }
                *(float2*)(out + o1) = r1;
                *(float2*)(out + o2) = r2;
            }
    } else {
        __syncthreads();
        float* s_out = (float*)smem;  // [64 co][132 px]
#pragma unroll
        for (int mt = 0; mt < MT; ++mt)
#pragma unroll
            for (int j = 0; j < 8; ++j) {
                const int co = warpM * MCO + mt * 16 + (lane >> 2);
                const int px = warpN * 64 + j * 8 + (lane & 3) * 2;
                s_out[co * 132 + px]           = acc[mt][j][0];
                s_out[co * 132 + px + 1]       = acc[mt][j][1];
                s_out[(co + 8) * 132 + px]     = acc[mt][j][2];
                s_out[(co + 8) * 132 + px + 1] = acc[mt][j][3];
            }
        __syncthreads();
        {
            const int co = tid >> 2, px0 = (tid & 3) * 32;
            size_t off = ((size_t)b * out_cs + co) * HW + pxbase + px0;
#pragma unroll
            for (int i = 0; i < 32; i += 4) {
                float4 a = *(float4*)&s_out[co * 132 + px0 + i];
                float4 rv = *(const float4*)(resid + off + i);
                a.x += rv.x; a.y += rv.y; a.z += rv.z; a.w += rv.w;
                *(float4*)(out + off + i) = a;
                *(float4*)&s_out[co * 132 + px0 + i] = a;
            }
        }
        __syncthreads();
        {
            const int px = tid >> 1, cg = (tid & 1) * 32;
            const size_t pix = (size_t)b * HW + pxbase + px;
#pragma unroll
            for (int gi = 0; gi < 4; ++gi) {
                ushort hb[8], lb[8];
#pragma unroll
                for (int i = 0; i < 8; ++i) {
                    float x = s_out[(cg + gi * 8 + i) * 132 + px];
                    __nv_bfloat16 h = __float2bfloat16(x);
                    hb[i] = __bfloat16_as_ushort(h);
                    lb[i] = __bfloat16_as_ushort(__float2bfloat16(x - __bfloat162float(h)));
                }
                *(uint4*)(onhi + pix * 64 + cg + gi * 8) = *(uint4*)hb;
                *(uint4*)(onlo + pix * 64 + cg + gi * 8) = *(uint4*)lb;
            }
        }
    }
}

// ---------------- depthwise 3x3: full-row tiles, smem staging ----------------
__global__ void __launch_bounds__(256)
dw3x3_k(const float* __restrict__ in, const float* __restrict__ wt,
        float* __restrict__ out, int C) {
    __shared__ float s[10][260];
    const int y0 = blockIdx.x * 8;
    const int zc = blockIdx.y;
    const int c = zc % C;
    const int tid = threadIdx.x;
    const float* ip = in + (size_t)zc * HW;

    float w[9];
#pragma unroll
    for (int i = 0; i < 9; ++i) w[i] = __ldg(&wt[c * 9 + i]);

#pragma unroll
    for (int pass = 0; pass < 3; ++pass) {
        int idx = tid + pass * 256;
        if (idx < 640) {
            int r = idx >> 6, c4 = (idx & 63) * 4;
            int gy = y0 + r - 1;
            float4 v = make_float4(0.f, 0.f, 0.f, 0.f);
            if (gy >= 0 && gy < HDIM) v = *(const float4*)(ip + gy * WDIM + c4);
            *(float4*)&s[r][c4] = v;
        }
    }
    __syncthreads();

#pragma unroll
    for (int pass = 0; pass < 2; ++pass) {
        const int r = (tid >> 6) + pass * 4;
        const int px0 = (tid & 63) * 4;
        float acc[4] = {0.f, 0.f, 0.f, 0.f};
#pragma unroll
        for (int ky = 0; ky < 3; ++ky) {
            const float* row = s[r + ky];
            float4 m = *(const float4*)&row[px0];
            float v0 = (px0 == 0) ? 0.f : row[px0 - 1];
            float v5 = (px0 == 252) ? 0.f : row[px0 + 4];
            float v[6] = {v0, m.x, m.y, m.z, m.w, v5};
#pragma unroll
            for (int kx = 0; kx < 3; ++kx)
#pragma unroll
                for (int p = 0; p < 4; ++p)
                    acc[p] += w[ky * 3 + kx] * v[kx + p];
        }
        *(float4*)&out[(size_t)zc * HW + (y0 + r) * WDIM + px0] =
            make_float4(acc[0], acc[1], acc[2], acc[3]);
    }
}

// ---------------- Gram + norms ----------------
__global__ void gramnorm_k(const float* __restrict__ q, int qcs,
                           const float* __restrict__ k, int kcs,
                           float* __restrict__ G, float* __restrict__ nq,
                           float* __restrict__ nk) {
    const int b = blockIdx.z, h = blockIdx.y;
    const int p0 = blockIdx.x * 4096 + threadIdx.x;
    const float* qb = q + ((size_t)b * qcs + h * 8) * HW;
    const float* kb = k + ((size_t)b * kcs + h * 8) * HW;
    float acc[80];
#pragma unroll
    for (int i = 0; i < 80; ++i) acc[i] = 0.f;
    for (int it = 0; it < 16; ++it) {
        int p = p0 + it * 256;
        float qv[8], kv[8];
#pragma unroll
        for (int c = 0; c < 8; ++c) {
            qv[c] = qb[(size_t)c * HW + p];
            kv[c] = kb[(size_t)c * HW + p];
        }
#pragma unroll
        for (int c = 0; c < 8; ++c) {
            acc[64 + c] += qv[c] * qv[c];
            acc[72 + c] += kv[c] * kv[c];
#pragma unroll
            for (int d = 0; d < 8; ++d) acc[c * 8 + d] += qv[c] * kv[d];
        }
    }
    __shared__ float red[80][8];
    const int lane = threadIdx.x & 31, warp = threadIdx.x >> 5;
#pragma unroll
    for (int i = 0; i < 80; ++i) {
        float v = acc[i];
        v += __shfl_down_sync(0xffffffffu, v, 16);
        v += __shfl_down_sync(0xffffffffu, v, 8);
        v += __shfl_down_sync(0xffffffffu, v, 4);
        v += __shfl_down_sync(0xffffffffu, v, 2);
        v += __shfl_down_sync(0xffffffffu, v, 1);
        if (lane == 0) red[i][warp] = v;
    }
    __syncthreads();
    if (threadIdx.x < 80) {
        float s = 0.f;
#pragma unroll
        for (int w = 0; w < 8; ++w) s += red[threadIdx.x][w];
        int i = threadIdx.x;
        if (i < 64)
            atomicAdd(&G[(((size_t)b * 8 + h) * 8 + (i >> 3)) * 8 + (i & 7)], s);
        else if (i < 72)
            atomicAdd(&nq[b * 64 + h * 8 + (i - 64)], s);
        else
            atomicAdd(&nk[b * 64 + h * 8 + (i - 72)], s);
    }
}

// ---------------- softmax + proj fold ----------------
__global__ void softmax_meff_k(const float* __restrict__ temp, const float* __restrict__ Wproj,
                               const float* __restrict__ G, const float* __restrict__ nq,
                               const float* __restrict__ nk, float* __restrict__ Meff) {
    const int b = blockIdx.x;
    const int t = threadIdx.x;
    __shared__ float attn[8][8][8];
    {
        int h = t >> 3, c = t & 7;
        float nqc = fmaxf(sqrtf(nq[b * 64 + h * 8 + c]), 1e-12f);
        float row[8];
        float m = -1e30f;
#pragma unroll
        for (int d = 0; d < 8; ++d) {
            float nkd = fmaxf(sqrtf(nk[b * 64 + h * 8 + d]), 1e-12f);
            row[d] = temp[h] * G[(((size_t)b * 8 + h) * 8 + c) * 8 + d] / (nqc * nkd);
            m = fmaxf(m, row[d]);
        }
        float sum = 0.f;
#pragma unroll
        for (int d = 0; d < 8; ++d) { row[d] = expf(row[d] - m); sum += row[d]; }
        float inv = 1.f / sum;
#pragma unroll
        for (int d = 0; d < 8; ++d) attn[h][c][d] = row[d] * inv;
    }
    __syncthreads();
    const int o = t;
    for (int dg = 0; dg < 64; ++dg) {
        int hh = dg >> 3, j = dg & 7;
        float s = 0.f;
#pragma unroll
        for (int i = 0; i < 8; ++i) s += Wproj[o * 64 + hh * 8 + i] * attn[hh][i][j];
        Meff[((size_t)b * 64 + o) * 64 + dg] = s;
    }
}

// ---------------- host orchestration (two-stream fork/join, graph-capturable) ----------------
extern "C" void kernel_launch(void* const* d_in, const int* in_sizes, int n_in,
                              void* d_out, int out_size) {
    const float* spa    = (const float*)d_in[0];
    const float* fre    = (const float*)d_in[1];
    const float* W_fre  = (const float*)d_in[2];
    const float* b_fre  = (const float*)d_in[3];
    const float* W_spa  = (const float*)d_in[4];
    const float* b_spa  = (const float*)d_in[5];
    const float* temp   = (const float*)d_in[6];
    const float* Wq     = (const float*)d_in[7];
    const float* Wq_dw  = (const float*)d_in[8];
    const float* Wkv    = (const float*)d_in[9];
    const float* Wkv_dw = (const float*)d_in[10];
    const float* Wproj  = (const float*)d_in[11];
    const float* Wf1    = (const float*)d_in[12];
    const float* bf1    = (const float*)d_in[13];
    const float* Wf2    = (const float*)d_in[14];
    const float* bf2    = (const float*)d_in[15];
    float* out = (float*)d_out;

    float *pfre1, *pspa1, *ptmp, *pq, *pfre2, *pspa2, *pkv0, *pkv, *pstats, *pmeff;
    __nv_bfloat16 *phi, *plo;
    uint4* pwk;
    cudaGetSymbolAddress((void**)&pfre1, g_fre1);
    cudaGetSymbolAddress((void**)&pspa1, g_spa1);
    cudaGetSymbolAddress((void**)&ptmp,  g_tmp);
    cudaGetSymbolAddress((void**)&pq,    g_q);
    cudaGetSymbolAddress((void**)&pfre2, g_fre2);
    cudaGetSymbolAddress((void**)&pspa2, g_spa2);
    cudaGetSymbolAddress((void**)&pkv0,  g_kv0);
    cudaGetSymbolAddress((void**)&pkv,   g_kv);
    cudaGetSymbolAddress((void**)&pstats, g_stats);
    cudaGetSymbolAddress((void**)&pmeff, g_Meff);
    cudaGetSymbolAddress((void**)&phi,   g_nh_hi);
    cudaGetSymbolAddress((void**)&plo,   g_nh_lo);
    cudaGetSymbolAddress((void**)&pwk,   g_wpk4);
    float* pG  = pstats;
    float* pnq = pstats + 2048;
    float* pnk = pstats + 2304;
    const size_t NHN = (size_t)BSZ * HW * 64;
    __nv_bfloat16 *h0 = phi, *h1 = phi + NHN, *h2 = phi + 2*NHN, *h3 = phi + 3*NHN, *h4 = phi + 4*NHN;
    __nv_bfloat16 *l0 = plo, *l1 = plo + NHN, *l2 = plo + 2*NHN, *l3 = plo + 3*NHN, *l4 = plo + 4*NHN;
    uint4 *w0 = pwk, *w1 = pwk + 9216, *wF1 = pwk + 18432, *wF2 = pwk + 36864;

    static cudaStream_t s1 = nullptr;
    static cudaEvent_t evFork1, evQ1, evFork2, evQ2;
    if (s1 == nullptr) {
        cudaStreamCreateWithFlags(&s1, cudaStreamNonBlocking);
        cudaEventCreateWithFlags(&evFork1, cudaEventDisableTiming);
        cudaEventCreateWithFlags(&evQ1,    cudaEventDisableTiming);
        cudaEventCreateWithFlags(&evFork2, cudaEventDisableTiming);
        cudaEventCreateWithFlags(&evQ2,    cudaEventDisableTiming);
    }

    cudaFuncSetAttribute(gconv_k<64, 64, false, false, true, false, 3, true>,
                         cudaFuncAttributeMaxDynamicSharedMemorySize, GC_SMEM);
    cudaFuncSetAttribute(gconv_k<128, 64, false, false, false, true, 3, false>,
                         cudaFuncAttributeMaxDynamicSharedMemorySize, GC_SMEM);
    cudaFuncSetAttribute(gconv_k<64, 128, true, true, false, false, 2, false>,
                         cudaFuncAttributeMaxDynamicSharedMemorySize, GC_SMEM);
    const int C1_SMEM_64  = 34816 + 64 * 144 * 2;    // 53248
    const int C1_SMEM_128 = 34816 + 128 * 144 * 2;   // 71680
    cudaFuncSetAttribute(c1mma_k<64, false, false>,
                         cudaFuncAttributeMaxDynamicSharedMemorySize, C1_SMEM_64);
    cudaFuncSetAttribute(c1mma_k<64, true, true>,
                         cudaFuncAttributeMaxDynamicSharedMemorySize, C1_SMEM_64);
    cudaFuncSetAttribute(c1mma_k<128, false, false>,
                         cudaFuncAttributeMaxDynamicSharedMemorySize, C1_SMEM_128);

    const dim3 blk(256);
    const dim3 gt2(2048, 2, 2 * BSZ);       // merged transpose
    const dim3 gg(2, 256, BSZ);             // gconv
    const dim3 gg2(2, 256, 2 * BSZ);        // merged gconv
    const dim3 g1(512, BSZ);                // c1mma
    const dim3 gdw64(32, BSZ * 64);
    const dim3 gdw128(32, BSZ * 128);
    const dim3 ggram(16, 8, BSZ);

    // prep on s0: launch #4 = merged gconv (profiled)
    wpack_k<<<36, blk>>>(W_fre, w0, 64, 64);
    wpack_k<<<36, blk>>>(W_spa, w1, 64, 64);
    nchw2nhwc2_k<<<gt2, blk>>>(fre, spa, h0, l0, h1, l1);
    gconv_k<64, 64, false, false, true, false, 3, true><<<gg2, blk, GC_SMEM>>>(
        h0, l0, h0, l0, w0, b_fre, pfre1, nullptr, nullptr, nullptr, nullptr,
        h1, l1, w1, b_spa, pspa1);

    // fork s1 after fre1/spa1 ready
    cudaEventRecord(evFork1, 0);
    cudaStreamWaitEvent(s1, evFork1, 0);

    // ---- attention 1 ----
    // s1: fuse wpacks + q chain
    wpack_k<<<72, blk, 0, s1>>>(Wf1, wF1, 128, 64);
    wpack_k<<<72, blk, 0, s1>>>(Wf2, wF2, 64, 128);
    c1mma_k<64, false, false><<<g1, blk, C1_SMEM_64, s1>>>(pfre1, 64, 0, Wq, 0, nullptr, ptmp, 64, nullptr, nullptr);
    dw3x3_k<<<gdw64, blk, 0, s1>>>(ptmp, Wq_dw, pq, 64);
    zero_k<<<10, blk, 0, s1>>>(pstats, 2560);
    cudaEventRecord(evQ1, s1);
    // s0: kv chain
    c1mma_k<128, false, false><<<g1, blk, C1_SMEM_128>>>(pspa1, 64, 0, Wkv, 0, nullptr, pkv0, 128, nullptr, nullptr);
    dw3x3_k<<<gdw128, blk>>>(pkv0, Wkv_dw, pkv, 128);
    cudaStreamWaitEvent(0, evQ1, 0);
    gramnorm_k<<<ggram, blk>>>(pq, 64, pkv, 128, pG, pnq, pnk);
    softmax_meff_k<<<BSZ, 64>>>(temp, Wproj, pG, pnq, pnk, pmeff);
    cudaEventRecord(evFork2, 0);   // pq/pstats free after this
    c1mma_k<64, true, true><<<g1, blk, C1_SMEM_64>>>(pkv, 128, 64, pmeff, 64 * 64, pfre1, pfre2, 64, h2, l2);

    // ---- attention 2 ----
    cudaStreamWaitEvent(s1, evFork2, 0);
    c1mma_k<64, false, false><<<g1, blk, C1_SMEM_64, s1>>>(pspa1, 64, 0, Wq, 0, nullptr, ptmp, 64, nullptr, nullptr);
    dw3x3_k<<<gdw64, blk, 0, s1>>>(ptmp, Wq_dw, pq, 64);
    zero_k<<<10, blk, 0, s1>>>(pstats, 2560);
    cudaEventRecord(evQ2, s1);
    c1mma_k<128, false, false><<<g1, blk, C1_SMEM_128>>>(pfre2, 64, 0, Wkv, 0, nullptr, pkv0, 128, nullptr, nullptr);
    dw3x3_k<<<gdw128, blk>>>(pkv0, Wkv_dw, pkv, 128);
    cudaStreamWaitEvent(0, evQ2, 0);
    gramnorm_k<<<ggram, blk>>>(pq, 64, pkv, 128, pG, pnq, pnk);
    softmax_meff_k<<<BSZ, 64>>>(temp, Wproj, pG, pnq, pnk, pmeff);
    c1mma_k<64, true, true><<<g1, blk, C1_SMEM_64>>>(pkv, 128, 64, pmeff, 64 * 64, pspa1, pspa2, 64, h3, l3);

    // ---- fuse path: F1 (concat -> t1 NHWC), F2 + final gate fused ----
    gconv_k<128, 64, false, false, false, true, 3, false><<<gg, blk, GC_SMEM>>>(
        h2, l2, h3, l3, wF1, bf1, nullptr, h4, l4, nullptr, nullptr,
        nullptr, nullptr, nullptr, nullptr, nullptr);
    gconv_k<64, 128, true, true, false, false, 2, false><<<gg, blk, GC_SMEM>>>(
        h4, l4, h4, l4, wF2, bf2, out, nullptr, nullptr, pfre2, pspa2,
        nullptr, nullptr, nullptr, nullptr, nullptr);
}

// round 15
// speedup vs baseline: 1.4050x; 1.0020x over previous
#include <cuda_runtime.h>
#include <cuda_bf16.h>
#include <math.h>
#include <stdint.h>

#define BSZ 4
#define HDIM 256
#define WDIM 256
#define HW 65536

// ---------------- scratch (device globals) ----------------
__device__ float g_fre1[(size_t)BSZ * 64 * HW];
__device__ float g_spa1[(size_t)BSZ * 64 * HW];
__device__ float g_tmp [(size_t)BSZ * 64 * HW];
__device__ float g_q   [(size_t)BSZ * 64 * HW];
__device__ float g_fre2[(size_t)BSZ * 64 * HW];
__device__ float g_spa2[(size_t)BSZ * 64 * HW];
__device__ float g_kv0 [(size_t)BSZ * 128 * HW];
__device__ float g_kv  [(size_t)BSZ * 128 * HW];
__device__ float g_stats[2560];
__device__ float g_Meff[BSZ * 64 * 64];
// NHWC bf16 hi/lo slots: 0=fre 1=spa 2=fre2 3=spa2 4=t1
__device__ __nv_bfloat16 g_nh_hi[5][(size_t)BSZ * HW * 64];
__device__ __nv_bfloat16 g_nh_lo[5][(size_t)BSZ * HW * 64];
// packed weights uint4 {hi(k0pair), lo(k0pair), hi(k1pair), lo(k1pair)}
__device__ uint4 g_wpk4[55296];

// ---------------- mma.sync / cp.async helpers (baseline sm_80+, no 'a' arch) ----------------
__device__ __forceinline__ uint32_t smem_u32(const void* p) {
    uint32_t a;
    asm("{ .reg .u64 t; cvta.to.shared.u64 t, %1; cvt.u32.u64 %0, t; }" : "=r"(a) : "l"(p));
    return a;
}
__device__ __forceinline__ void ldmA(uint32_t r[4], uint32_t a) {
    asm volatile("ldmatrix.sync.aligned.m8n8.x4.shared.b16 {%0,%1,%2,%3}, [%4];"
                 : "=r"(r[0]), "=r"(r[1]), "=r"(r[2]), "=r"(r[3]) : "r"(a));
}
__device__ __forceinline__ void ldmT(uint32_t r[4], uint32_t a) {
    asm volatile("ldmatrix.sync.aligned.m8n8.x4.trans.shared.b16 {%0,%1,%2,%3}, [%4];"
                 : "=r"(r[0]), "=r"(r[1]), "=r"(r[2]), "=r"(r[3]) : "r"(a));
}
__device__ __forceinline__ void mma16816(float* c, const uint32_t* a, const uint32_t* b) {
    asm volatile(
        "mma.sync.aligned.m16n8k16.row.col.f32.bf16.bf16.f32 "
        "{%0,%1,%2,%3}, {%4,%5,%6,%7}, {%8,%9}, {%0,%1,%2,%3};"
        : "+f"(c[0]), "+f"(c[1]), "+f"(c[2]), "+f"(c[3])
        : "r"(a[0]), "r"(a[1]), "r"(a[2]), "r"(a[3]), "r"(b[0]), "r"(b[1]));
}
__device__ __forceinline__ void cpa16(uint32_t d, const void* s, int pb) {
    asm volatile("cp.async.cg.shared.global [%0], [%1], 16, %2;"
                 :: "r"(d), "l"(s), "r"(pb) : "memory");
}
__device__ __forceinline__ void cpa_commit() {
    asm volatile("cp.async.commit_group;" ::: "memory");
}
__device__ __forceinline__ void cpa_wait1() {
    asm volatile("cp.async.wait_group 1;" ::: "memory");
}
__device__ __forceinline__ void cpa_wait0() {
    asm volatile("cp.async.wait_group 0;" ::: "memory");
}
__device__ __forceinline__ void split4(float4 v, uint2& hi, uint2& lo) {
    __nv_bfloat16 h0 = __float2bfloat16(v.x), h1 = __float2bfloat16(v.y);
    __nv_bfloat16 h2 = __float2bfloat16(v.z), h3 = __float2bfloat16(v.w);
    __nv_bfloat16 l0 = __float2bfloat16(v.x - __bfloat162float(h0));
    __nv_bfloat16 l1 = __float2bfloat16(v.y - __bfloat162float(h1));
    __nv_bfloat16 l2 = __float2bfloat16(v.z - __bfloat162float(h2));
    __nv_bfloat16 l3 = __float2bfloat16(v.w - __bfloat162float(h3));
    hi.x = ((uint32_t)__bfloat16_as_ushort(h1) << 16) | __bfloat16_as_ushort(h0);
    hi.y = ((uint32_t)__bfloat16_as_ushort(h3) << 16) | __bfloat16_as_ushort(h2);
    lo.x = ((uint32_t)__bfloat16_as_ushort(l1) << 16) | __bfloat16_as_ushort(l0);
    lo.y = ((uint32_t)__bfloat16_as_ushort(l3) << 16) | __bfloat16_as_ushort(l2);
}

__global__ void zero_k(float* p, int n) {
    int i = blockIdx.x * 256 + threadIdx.x;
    if (i < n) p[i] = 0.f;
}
__device__ __forceinline__ float fix_nan(float x) { return isfinite(x) ? x : 1e-5f; }
__device__ __forceinline__ float sigm(float x) { return 1.f / (1.f + expf(-x)); }

// ---------------- merged NCHW fp32 -> NHWC bf16 hi/lo (two tensors via z) ----------------
__global__ void nchw2nhwc2_k(const float* __restrict__ inA, const float* __restrict__ inB,
                             __nv_bfloat16* __restrict__ ohiA, __nv_bfloat16* __restrict__ oloA,
                             __nv_bfloat16* __restrict__ ohiB, __nv_bfloat16* __restrict__ oloB) {
    __shared__ float s[32][33];
    const int z = blockIdx.z;
    const float* in = (z < BSZ) ? inA : inB;
    __nv_bfloat16* ohi = (z < BSZ) ? ohiA : ohiB;
    __nv_bfloat16* olo = (z < BSZ) ? oloA : oloB;
    const int b = z & 3, ch0 = blockIdx.y * 32, p0 = blockIdx.x * 32;
    const int lx = threadIdx.x & 31, ly = threadIdx.x >> 5;
#pragma unroll
    for (int i = 0; i < 4; ++i) {
        int c = ly + i * 8;
        s[c][lx] = in[((size_t)(b * 64 + ch0 + c)) * HW + p0 + lx];
    }
    __syncthreads();
#pragma unroll
    for (int i = 0; i < 4; ++i) {
        int p = ly + i * 8;
        float v = s[lx][p];
        __nv_bfloat16 h = __float2bfloat16(v);
        size_t idx = ((size_t)b * HW + p0 + p) * 64 + ch0 + lx;
        ohi[idx] = h;
        olo[idx] = __float2bfloat16(v - __bfloat162float(h));
    }
}

// ---------------- weight pack: OIHW -> [tap][chunk16][co][tig] uint4 ----------------
__global__ void wpack_k(const float* __restrict__ W, uint4* __restrict__ pk, int CIN, int CO) {
    int NCH = CIN >> 4;
    int n = 9 * NCH * CO * 4;
    int i = blockIdx.x * 256 + threadIdx.x;
    if (i >= n) return;
    int tig = i & 3;
    int t2 = i >> 2;
    int co = t2 % CO;
    int t3 = t2 / CO;
    int chv = t3 % NCH, tap = t3 / NCH;
    int ci0 = chv * 16 + 2 * tig;
    uint4 o;
#pragma unroll
    for (int half = 0; half < 2; ++half) {
        int ci = ci0 + half * 8;
        float w0 = W[((size_t)co * CIN + ci) * 9 + tap];
        float w1 = W[((size_t)co * CIN + ci + 1) * 9 + tap];
        __nv_bfloat16 h0 = __float2bfloat16(w0), h1 = __float2bfloat16(w1);
        __nv_bfloat16 l0 = __float2bfloat16(w0 - __bfloat162float(h0));
        __nv_bfloat16 l1 = __float2bfloat16(w1 - __bfloat162float(h1));
        uint32_t hp = ((uint32_t)__bfloat16_as_ushort(h1) << 16) | __bfloat16_as_ushort(h0);
        uint32_t lp = ((uint32_t)__bfloat16_as_ushort(l1) << 16) | __bfloat16_as_ushort(l0);
        if (half == 0) { o.x = hp; o.y = lp; } else { o.z = hp; o.w = lp; }
    }
    pk[i] = o;
}

// ---------------- mma.sync bf16 3-term implicit-GEMM 3x3 conv (R11 tiling) ----------------
#define GC_BUF 37440                 // 130 px * 144 B * 2 (hi+lo)
#define GC_SMEM (2 * GC_BUF)         // 74880
#define LOOFF 18720                  // 130 * 144

__device__ __forceinline__ void gc_stage(const __nv_bfloat16* __restrict__ shi,
                                         const __nv_bfloat16* __restrict__ slo,
                                         int b, int gy, bool yok, int xbase,
                                         uint32_t dst, int tid) {
    const int gyc = yok ? gy : 0;
    for (int idx = tid; idx < 260; idx += 256) {
        const int px = idx >> 1, q = idx & 1;
        const int gx = xbase + px - 1;
        const bool ok = yok && gx >= 0 && gx < WDIM;
        const int gxc = (gx >= 0 && gx < WDIM) ? gx : 0;
        const int pb = ok ? 16 : 0;
        size_t off = ((size_t)b * HW + (size_t)gyc * WDIM + gxc) * 64 + q * 32;
        const char* ph = (const char*)(shi + off);
        const char* pl = (const char*)(slo + off);
        uint32_t dh = dst + px * 144 + q * 64;
        uint32_t dl = dst + LOOFF + px * 144 + q * 64;
#pragma unroll
        for (int i = 0; i < 4; ++i) {
            cpa16(dh + i * 16, ph + i * 16, pb);
            cpa16(dl + i * 16, pl + i * 16, pb);
        }
    }
    cpa_commit();
}

template <int CIN, int CO, bool SIG, bool FINAL, bool NCHWOUT, bool NHWCOUT, int MINB, bool MERGED>
__global__ void __launch_bounds__(256, MINB)
gconv_k(const __nv_bfloat16* __restrict__ sAhi, const __nv_bfloat16* __restrict__ sAlo,
        const __nv_bfloat16* __restrict__ sBhi, const __nv_bfloat16* __restrict__ sBlo,
        const uint4* __restrict__ wb, const float* __restrict__ bias,
        float* __restrict__ outc,
        __nv_bfloat16* __restrict__ onhi, __nv_bfloat16* __restrict__ onlo,
        const float* __restrict__ resA, const float* __restrict__ resB,
        const __nv_bfloat16* __restrict__ A2hi, const __nv_bfloat16* __restrict__ A2lo,
        const uint4* __restrict__ wb2, const float* __restrict__ bias2,
        float* __restrict__ outc2) {
    extern __shared__ char smem[];
    constexpr int NGRP = CIN / 64;
    constexpr int NWN = CO / 32;
    constexpr int NWM = 8 / NWN;
    constexpr int MPW = 128 / NWM;
    constexpr int MT  = MPW / 16;
    const int NSTG = 3 * NGRP;

    const int tid = threadIdx.x, wid = tid >> 5, lane = tid & 31;
    const int warpN = wid % NWN, warpM = wid / NWN;
    int b = blockIdx.z;
    const __nv_bfloat16* Ahi = sAhi;
    const __nv_bfloat16* Alo = sAlo;
    const __nv_bfloat16* Bhi = sBhi;
    const __nv_bfloat16* Blo = sBlo;
    const uint4* wbp = wb;
    const float* biasp = bias;
    float* outp = outc;
    if (MERGED && blockIdx.z >= BSZ) {
        b -= BSZ;
        Ahi = A2hi; Alo = A2lo; Bhi = A2hi; Blo = A2lo;
        wbp = wb2; biasp = bias2; outp = outc2;
    }
    const int y = blockIdx.y, xbase = blockIdx.x * 128;
    const int g = lane >> 2, tig = lane & 3;
    const uint32_t sb = smem_u32(smem);

    float acc[MT][4][4];
#pragma unroll
    for (int mt = 0; mt < MT; ++mt)
#pragma unroll
        for (int nt = 0; nt < 4; ++nt)
#pragma unroll
            for (int q = 0; q < 4; ++q) acc[mt][nt][q] = 0.f;

    // prologue: issue stage 0 into buf 0
    {
        const int gy = y - 1;
        gc_stage(Ahi, Alo, b, gy, (gy >= 0) && (gy < HDIM), xbase, sb, tid);
    }

    for (int st = 0; st < NSTG; ++st) {
        __syncthreads();   // all warps done with buf[(st+1)&1] (computed at st-1)
        if (st + 1 < NSTG) {
            const int dyN = (st + 1) / NGRP, grpN = (st + 1) % NGRP;
            const int gyN = y + dyN - 1;
            gc_stage(grpN ? Bhi : Ahi, grpN ? Blo : Alo, b, gyN,
                     (gyN >= 0) && (gyN < HDIM), xbase,
                     sb + ((st + 1) & 1) * GC_BUF, tid);
            cpa_wait1();
        } else {
            cpa_wait0();
        }
        __syncthreads();   // staged data for st visible

        const int dyI = st / NGRP, grp = st % NGRP;
        const uint32_t sbuf = sb + (st & 1) * GC_BUF;
#pragma unroll
        for (int dxI = 0; dxI < 3; ++dxI) {
            const int tap = dyI * 3 + dxI;
#pragma unroll
            for (int ch = 0; ch < 4; ++ch) {
                const uint4* wc = wbp + (size_t)(tap * (CIN / 16) + grp * 4 + ch) * CO * 4;
                uint32_t bh[4][2], bl[4][2];
#pragma unroll
                for (int nt = 0; nt < 4; ++nt) {
                    int n = warpN * 32 + nt * 8 + g;
                    uint4 w4 = __ldg(&wc[n * 4 + tig]);
                    bh[nt][0] = w4.x; bl[nt][0] = w4.y;
                    bh[nt][1] = w4.z; bl[nt][1] = w4.w;
                }
#pragma unroll
                for (int mt = 0; mt < MT; ++mt) {
                    const int pxl = warpM * MPW + mt * 16 + (lane & 15) + dxI;
                    uint32_t addr = sbuf + pxl * 144 + ch * 32 + ((lane >> 4) & 1) * 16;
                    uint32_t ah[4], al[4];
                    ldmA(ah, addr);
                    ldmA(al, addr + LOOFF);
                    // term-major: consecutive MMAs hit different accumulators
#pragma unroll
                    for (int nt = 0; nt < 4; ++nt) mma16816(acc[mt][nt], ah, bh[nt]);
#pragma unroll
                    for (int nt = 0; nt < 4; ++nt) mma16816(acc[mt][nt], al, bh[nt]);
#pragma unroll
                    for (int nt = 0; nt < 4; ++nt) mma16816(acc[mt][nt], ah, bl[nt]);
                }
            }
        }
    }

    // ---------------- epilogue through smem ----------------
    float* s_out = (float*)smem;  // [32 co][132 px]
    for (int co0 = 0; co0 < CO; co0 += 32) {
        __syncthreads();
        if (warpN == (co0 >> 5)) {
#pragma unroll
            for (int mt = 0; mt < MT; ++mt) {
                const int px = warpM * MPW + mt * 16 + g;
#pragma unroll
                for (int nt = 0; nt < 4; ++nt) {
                    const int cl = nt * 8 + tig * 2;
                    s_out[cl * 132 + px]           = acc[mt][nt][0];
                    s_out[(cl + 1) * 132 + px]     = acc[mt][nt][1];
                    s_out[cl * 132 + px + 8]       = acc[mt][nt][2];
                    s_out[(cl + 1) * 132 + px + 8] = acc[mt][nt][3];
                }
            }
        }
        __syncthreads();
        if (FINAL) {
            const int cl = tid >> 3, px0 = (tid & 7) * 16;
            const int c = (co0 + cl) & 63;
            const bool second = (co0 + cl) >= 64;
            const float bv = __ldg(&biasp[co0 + cl]);
            const float* res = second ? resB : resA;
            size_t off = ((size_t)(b * 64 + c)) * HW + (size_t)y * WDIM + xbase + px0;
#pragma unroll
            for (int i = 0; i < 16; i += 4) {
                float4 rv = *(const float4*)(res + off + i);
                float4 o;
                o.x = sigm(s_out[cl * 132 + px0 + i]     + bv) * rv.x;
                o.y = sigm(s_out[cl * 132 + px0 + i + 1] + bv) * rv.y;
                o.z = sigm(s_out[cl * 132 + px0 + i + 2] + bv) * rv.z;
                o.w = sigm(s_out[cl * 132 + px0 + i + 3] + bv) * rv.w;
                if (!second) {
                    *(float4*)(outp + off + i) = o;
                } else {
                    float4 prev = *(const float4*)(outp + off + i);
                    o.x = fix_nan(prev.x + o.x);
                    o.y = fix_nan(prev.y + o.y);
                    o.z = fix_nan(prev.z + o.z);
                    o.w = fix_nan(prev.w + o.w);
                    *(float4*)(outp + off + i) = o;
                }
            }
        } else {
            if (NCHWOUT) {
                const int cl = tid >> 3, px0 = (tid & 7) * 16;
                const float bv = __ldg(&biasp[co0 + cl]);
                float v[16];
#pragma unroll
                for (int i = 0; i < 16; ++i) {
                    float x = s_out[cl * 132 + px0 + i] + bv;
                    if (SIG) x = sigm(x);
                    v[i] = x;
                }
                float* op = outp + ((size_t)(b * CO + co0 + cl)) * HW + (size_t)y * WDIM + xbase + px0;
#pragma unroll
                for (int i = 0; i < 4; ++i)
                    *(float4*)(op + i * 4) = make_float4(v[i*4], v[i*4+1], v[i*4+2], v[i*4+3]);
            }
            if (NHWCOUT) {
                const int px = tid >> 1, cg = (tid & 1) * 16;
                const size_t pix = (size_t)b * HW + (size_t)y * WDIM + xbase + px;
                ushort hb[16], lb[16];
#pragma unroll
                for (int i = 0; i < 16; ++i) {
                    int cl = cg + i;
                    float x = s_out[cl * 132 + px] + __ldg(&biasp[co0 + cl]);
                    if (SIG) x = sigm(x);
                    __nv_bfloat16 h = __float2bfloat16(x);
                    hb[i] = __bfloat16_as_ushort(h);
                    lb[i] = __bfloat16_as_ushort(__float2bfloat16(x - __bfloat162float(h)));
                }
                uint4* oh = (uint4*)(onhi + pix * 64 + co0 + cg);
                uint4* ol = (uint4*)(onlo + pix * 64 + co0 + cg);
                oh[0] = *(uint4*)&hb[0]; oh[1] = *(uint4*)&hb[8];
                ol[0] = *(uint4*)&lb[0]; ol[1] = *(uint4*)&lb[8];
            }
        }
    }
}

// ---------------- conv 1x1 via mma.sync (3-term bf16) ----------------
template <int CO, bool RESID, bool NHWCOUT>
__global__ void __launch_bounds__(256)
c1mma_k(const float* __restrict__ in, int in_cs, int in_off,
        const float* __restrict__ W, int w_bs,
        const float* __restrict__ resid,
        float* __restrict__ out, int out_cs,
        __nv_bfloat16* __restrict__ onhi, __nv_bfloat16* __restrict__ onlo) {
    extern __shared__ char smem[];
    constexpr int BLO = 17408, WHI = 34816;
    constexpr int WLO = WHI + CO * 144;
    constexpr int MCO = CO / 4;
    constexpr int MT  = MCO / 16;

    const int tid = threadIdx.x, lane = tid & 31, wid = tid >> 5;
    const int warpN = wid & 1, warpM = wid >> 1;
    const int b = blockIdx.y;
    const int pxbase = blockIdx.x * 128;
    const uint32_t sb = smem_u32(smem);

    const float* ip = in + ((size_t)b * in_cs + in_off) * HW + pxbase;
#pragma unroll
    for (int pass = 0; pass < 8; ++pass) {
        const int ci = pass * 8 + (tid >> 5);
        const int px = (tid & 31) * 4;
        float4 v = *(const float4*)(ip + (size_t)ci * HW + px);
        uint2 hi, lo;
        split4(v, hi, lo);
        *(uint2*)(smem + ci * 272 + px * 2)       = hi;
        *(uint2*)(smem + BLO + ci * 272 + px * 2) = lo;
    }
    const float* wp = W + (size_t)b * w_bs;
    for (int i = tid; i < CO * 16; i += 256) {
        const int co = i >> 4, c4 = (i & 15) * 4;
        float4 v = *(const float4*)(wp + co * 64 + c4);
        uint2 hi, lo;
        split4(v, hi, lo);
        *(uint2*)(smem + WHI + co * 144 + c4 * 2) = hi;
        *(uint2*)(smem + WLO + co * 144 + c4 * 2) = lo;
    }
    __syncthreads();

    float acc[MT][8][4];
#pragma unroll
    for (int mt = 0; mt < MT; ++mt)
#pragma unroll
        for (int j = 0; j < 8; ++j)
#pragma unroll
            for (int q = 0; q < 4; ++q) acc[mt][j][q] = 0.f;

#pragma unroll
    for (int k = 0; k < 4; ++k) {
        uint32_t ah[MT][4], al[MT][4];
#pragma unroll
        for (int mt = 0; mt < MT; ++mt) {
            uint32_t addr = sb + WHI + (warpM * MCO + mt * 16 + (lane & 15)) * 144
                          + k * 32 + (lane >> 4) * 16;
            ldmA(ah[mt], addr);
            ldmA(al[mt], addr + CO * 144);
        }
        uint32_t bh[8][2], bl[8][2];
#pragma unroll
        for (int j = 0; j < 4; ++j) {
            uint32_t addr = sb + (k * 16 + (lane & 15)) * 272
                          + (warpN * 64 + j * 16 + (lane >> 4) * 8) * 2;
            uint32_t r[4];
            ldmT(r, addr);
            bh[2*j][0] = r[0]; bh[2*j][1] = r[1];
            bh[2*j+1][0] = r[2]; bh[2*j+1][1] = r[3];
            ldmT(r, addr + BLO);
            bl[2*j][0] = r[0]; bl[2*j][1] = r[1];
            bl[2*j+1][0] = r[2]; bl[2*j+1][1] = r[3];
        }
        // term-major: consecutive MMAs hit different accumulators
#pragma unroll
        for (int mt = 0; mt < MT; ++mt) {
#pragma unroll
            for (int j = 0; j < 8; ++j) mma16816(acc[mt][j], ah[mt], bh[j]);
#pragma unroll
            for (int j = 0; j < 8; ++j) mma16816(acc[mt][j], al[mt], bh[j]);
#pragma unroll
            for (int j = 0; j < 8; ++j) mma16816(acc[mt][j], ah[mt], bl[j]);
        }
    }

    if (!NHWCOUT) {
#pragma unroll
        for (int mt = 0; mt < MT; ++mt)
#pragma unroll
            for (int j = 0; j < 8; ++j) {
                const int co = warpM * MCO + mt * 16 + (lane >> 2);
                const int px = warpN * 64 + j * 8 + (lane & 3) * 2;
                size_t o1 = ((size_t)b * out_cs + co) * HW + pxbase + px;
                size_t o2 = o1 + (size_t)8 * HW;
                float2 r1 = make_float2(acc[mt][j][0], acc[mt][j][1]);
                float2 r2 = make_float2(acc[mt][j][2], acc[mt][j][3]);
                if (RESID) {
                    float2 q1 = *(const float2*)(resid + o1);
                    float2 q2 = *(const float2*)(resid + o2);
                    r1.x += q1.x; r1.y += q1.y; r2.x += q2.x; r2.y += q2.y;
                }
                *(float2*)(out + o1) = r1;
                *(float2*)(out + o2) = r2;
            }
    } else {
        __syncthreads();
        float* s_out = (float*)smem;  // [64 co][132 px]
#pragma unroll
        for (int mt = 0; mt < MT; ++mt)
#pragma unroll
            for (int j = 0; j < 8; ++j) {
                const int co = warpM * MCO + mt * 16 + (lane >> 2);
                const int px = warpN * 64 + j * 8 + (lane & 3) * 2;
                s_out[co * 132 + px]           = acc[mt][j][0];
                s_out[co * 132 + px + 1]       = acc[mt][j][1];
                s_out[(co + 8) * 132 + px]     = acc[mt][j][2];
                s_out[(co + 8) * 132 + px + 1] = acc[mt][j][3];
            }
        __syncthreads();
        {
            const int co = tid >> 2, px0 = (tid & 3) * 32;
            size_t off = ((size_t)b * out_cs + co) * HW + pxbase + px0;
#pragma unroll
            for (int i = 0; i < 32; i += 4) {
                float4 a = *(float4*)&s_out[co * 132 + px0 + i];
                float4 rv = *(const float4*)(resid + off + i);
                a.x += rv.x; a.y += rv.y; a.z += rv.z; a.w += rv.w;
                *(float4*)(out + off + i) = a;
                *(float4*)&s_out[co * 132 + px0 + i] = a;
            }
        }
        __syncthreads();
        {
            const int px = tid >> 1, cg = (tid & 1) * 32;
            const size_t pix = (size_t)b * HW + pxbase + px;
#pragma unroll
            for (int gi = 0; gi < 4; ++gi) {
                ushort hb[8], lb[8];
#pragma unroll
                for (int i = 0; i < 8; ++i) {
                    float x = s_out[(cg + gi * 8 + i) * 132 + px];
                    __nv_bfloat16 h = __float2bfloat16(x);
                    hb[i] = __bfloat16_as_ushort(h);
                    lb[i] = __bfloat16_as_ushort(__float2bfloat16(x - __bfloat162float(h)));
                }
                *(uint4*)(onhi + pix * 64 + cg + gi * 8) = *(uint4*)hb;
                *(uint4*)(onlo + pix * 64 + cg + gi * 8) = *(uint4*)lb;
            }
        }
    }
}

// ---------------- depthwise 3x3: full-row tiles, smem staging ----------------
__global__ void __launch_bounds__(256)
dw3x3_k(const float* __restrict__ in, const float* __restrict__ wt,
        float* __restrict__ out, int C) {
    __shared__ float s[10][260];
    const int y0 = blockIdx.x * 8;
    const int zc = blockIdx.y;
    const int c = zc % C;
    const int tid = threadIdx.x;
    const float* ip = in + (size_t)zc * HW;

    float w[9];
#pragma unroll
    for (int i = 0; i < 9; ++i) w[i] = __ldg(&wt[c * 9 + i]);

#pragma unroll
    for (int pass = 0; pass < 3; ++pass) {
        int idx = tid + pass * 256;
        if (idx < 640) {
            int r = idx >> 6, c4 = (idx & 63) * 4;
            int gy = y0 + r - 1;
            float4 v = make_float4(0.f, 0.f, 0.f, 0.f);
            if (gy >= 0 && gy < HDIM) v = *(const float4*)(ip + gy * WDIM + c4);
            *(float4*)&s[r][c4] = v;
        }
    }
    __syncthreads();

#pragma unroll
    for (int pass = 0; pass < 2; ++pass) {
        const int r = (tid >> 6) + pass * 4;
        const int px0 = (tid & 63) * 4;
        float acc[4] = {0.f, 0.f, 0.f, 0.f};
#pragma unroll
        for (int ky = 0; ky < 3; ++ky) {
            const float* row = s[r + ky];
            float4 m = *(const float4*)&row[px0];
            float v0 = (px0 == 0) ? 0.f : row[px0 - 1];
            float v5 = (px0 == 252) ? 0.f : row[px0 + 4];
            float v[6] = {v0, m.x, m.y, m.z, m.w, v5};
#pragma unroll
            for (int kx = 0; kx < 3; ++kx)
#pragma unroll
                for (int p = 0; p < 4; ++p)
                    acc[p] += w[ky * 3 + kx] * v[kx + p];
        }
        *(float4*)&out[(size_t)zc * HW + (y0 + r) * WDIM + px0] =
            make_float4(acc[0], acc[1], acc[2], acc[3]);
    }
}

// ---------------- Gram + norms ----------------
__global__ void gramnorm_k(const float* __restrict__ q, int qcs,
                           const float* __restrict__ k, int kcs,
                           float* __restrict__ G, float* __restrict__ nq,
                           float* __restrict__ nk) {
    const int b = blockIdx.z, h = blockIdx.y;
    const int p0 = blockIdx.x * 4096 + threadIdx.x;
    const float* qb = q + ((size_t)b * qcs + h * 8) * HW;
    const float* kb = k + ((size_t)b * kcs + h * 8) * HW;
    float acc[80];
#pragma unroll
    for (int i = 0; i < 80; ++i) acc[i] = 0.f;
    for (int it = 0; it < 16; ++it) {
        int p = p0 + it * 256;
        float qv[8], kv[8];
#pragma unroll
        for (int c = 0; c < 8; ++c) {
            qv[c] = qb[(size_t)c * HW + p];
            kv[c] = kb[(size_t)c * HW + p];
        }
#pragma unroll
        for (int c = 0; c < 8; ++c) {
            acc[64 + c] += qv[c] * qv[c];
            acc[72 + c] += kv[c] * kv[c];
#pragma unroll
            for (int d = 0; d < 8; ++d) acc[c * 8 + d] += qv[c] * kv[d];
        }
    }
    __shared__ float red[80][8];
    const int lane = threadIdx.x & 31, warp = threadIdx.x >> 5;
#pragma unroll
    for (int i = 0; i < 80; ++i) {
        float v = acc[i];
        v += __shfl_down_sync(0xffffffffu, v, 16);
        v += __shfl_down_sync(0xffffffffu, v, 8);
        v += __shfl_down_sync(0xffffffffu, v, 4);
        v += __shfl_down_sync(0xffffffffu, v, 2);
        v += __shfl_down_sync(0xffffffffu, v, 1);
        if (lane == 0) red[i][warp] = v;
    }
    __syncthreads();
    if (threadIdx.x < 80) {
        float s = 0.f;
#pragma unroll
        for (int w = 0; w < 8; ++w) s += red[threadIdx.x][w];
        int i = threadIdx.x;
        if (i < 64)
            atomicAdd(&G[(((size_t)b * 8 + h) * 8 + (i >> 3)) * 8 + (i & 7)], s);
        else if (i < 72)
            atomicAdd(&nq[b * 64 + h * 8 + (i - 64)], s);
        else
            atomicAdd(&nk[b * 64 + h * 8 + (i - 72)], s);
    }
}

// ---------------- softmax + proj fold ----------------
__global__ void softmax_meff_k(const float* __restrict__ temp, const float* __restrict__ Wproj,
                               const float* __restrict__ G, const float* __restrict__ nq,
                               const float* __restrict__ nk, float* __restrict__ Meff) {
    const int b = blockIdx.x;
    const int t = threadIdx.x;
    __shared__ float attn[8][8][8];
    {
        int h = t >> 3, c = t & 7;
        float nqc = fmaxf(sqrtf(nq[b * 64 + h * 8 + c]), 1e-12f);
        float row[8];
        float m = -1e30f;
#pragma unroll
        for (int d = 0; d < 8; ++d) {
            float nkd = fmaxf(sqrtf(nk[b * 64 + h * 8 + d]), 1e-12f);
            row[d] = temp[h] * G[(((size_t)b * 8 + h) * 8 + c) * 8 + d] / (nqc * nkd);
            m = fmaxf(m, row[d]);
        }
        float sum = 0.f;
#pragma unroll
        for (int d = 0; d < 8; ++d) { row[d] = expf(row[d] - m); sum += row[d]; }
        float inv = 1.f / sum;
#pragma unroll
        for (int d = 0; d < 8; ++d) attn[h][c][d] = row[d] * inv;
    }
    __syncthreads();
    const int o = t;
    for (int dg = 0; dg < 64; ++dg) {
        int hh = dg >> 3, j = dg & 7;
        float s = 0.f;
#pragma unroll
        for (int i = 0; i < 8; ++i) s += Wproj[o * 64 + hh * 8 + i] * attn[hh][i][j];
        Meff[((size_t)b * 64 + o) * 64 + dg] = s;
    }
}

// ---------------- host orchestration (two-stream fork/join, graph-capturable) ----------------
extern "C" void kernel_launch(void* const* d_in, const int* in_sizes, int n_in,
                              void* d_out, int out_size) {
    const float* spa    = (const float*)d_in[0];
    const float* fre    = (const float*)d_in[1];
    const float* W_fre  = (const float*)d_in[2];
    const float* b_fre  = (const float*)d_in[3];
    const float* W_spa  = (const float*)d_in[4];
    const float* b_spa  = (const float*)d_in[5];
    const float* temp   = (const float*)d_in[6];
    const float* Wq     = (const float*)d_in[7];
    const float* Wq_dw  = (const float*)d_in[8];
    const float* Wkv    = (const float*)d_in[9];
    const float* Wkv_dw = (const float*)d_in[10];
    const float* Wproj  = (const float*)d_in[11];
    const float* Wf1    = (const float*)d_in[12];
    const float* bf1    = (const float*)d_in[13];
    const float* Wf2    = (const float*)d_in[14];
    const float* bf2    = (const float*)d_in[15];
    float* out = (float*)d_out;

    float *pfre1, *pspa1, *ptmp, *pq, *pfre2, *pspa2, *pkv0, *pkv, *pstats, *pmeff;
    __nv_bfloat16 *phi, *plo;
    uint4* pwk;
    cudaGetSymbolAddress((void**)&pfre1, g_fre1);
    cudaGetSymbolAddress((void**)&pspa1, g_spa1);
    cudaGetSymbolAddress((void**)&ptmp,  g_tmp);
    cudaGetSymbolAddress((void**)&pq,    g_q);
    cudaGetSymbolAddress((void**)&pfre2, g_fre2);
    cudaGetSymbolAddress((void**)&pspa2, g_spa2);
    cudaGetSymbolAddress((void**)&pkv0,  g_kv0);
    cudaGetSymbolAddress((void**)&pkv,   g_kv);
    cudaGetSymbolAddress((void**)&pstats, g_stats);
    cudaGetSymbolAddress((void**)&pmeff, g_Meff);
    cudaGetSymbolAddress((void**)&phi,   g_nh_hi);
    cudaGetSymbolAddress((void**)&plo,   g_nh_lo);
    cudaGetSymbolAddress((void**)&pwk,   g_wpk4);
    float* pG  = pstats;
    float* pnq = pstats + 2048;
    float* pnk = pstats + 2304;
    const size_t NHN = (size_t)BSZ * HW * 64;
    __nv_bfloat16 *h0 = phi, *h1 = phi + NHN, *h2 = phi + 2*NHN, *h3 = phi + 3*NHN, *h4 = phi + 4*NHN;
    __nv_bfloat16 *l0 = plo, *l1 = plo + NHN, *l2 = plo + 2*NHN, *l3 = plo + 3*NHN, *l4 = plo + 4*NHN;
    uint4 *w0 = pwk, *w1 = pwk + 9216, *wF1 = pwk + 18432, *wF2 = pwk + 36864;

    static cudaStream_t s1 = nullptr;
    static cudaEvent_t evFork1, evQ1, evFork2, evQ2;
    if (s1 == nullptr) {
        cudaStreamCreateWithFlags(&s1, cudaStreamNonBlocking);
        cudaEventCreateWithFlags(&evFork1, cudaEventDisableTiming);
        cudaEventCreateWithFlags(&evQ1,    cudaEventDisableTiming);
        cudaEventCreateWithFlags(&evFork2, cudaEventDisableTiming);
        cudaEventCreateWithFlags(&evQ2,    cudaEventDisableTiming);
    }

    cudaFuncSetAttribute(gconv_k<64, 64, false, false, true, false, 3, true>,
                         cudaFuncAttributeMaxDynamicSharedMemorySize, GC_SMEM);
    cudaFuncSetAttribute(gconv_k<128, 64, false, false, false, true, 3, false>,
                         cudaFuncAttributeMaxDynamicSharedMemorySize, GC_SMEM);
    cudaFuncSetAttribute(gconv_k<64, 128, true, true, false, false, 2, false>,
                         cudaFuncAttributeMaxDynamicSharedMemorySize, GC_SMEM);
    const int C1_SMEM_64  = 34816 + 64 * 144 * 2;    // 53248
    const int C1_SMEM_128 = 34816 + 128 * 144 * 2;   // 71680
    cudaFuncSetAttribute(c1mma_k<64, false, false>,
                         cudaFuncAttributeMaxDynamicSharedMemorySize, C1_SMEM_64);
    cudaFuncSetAttribute(c1mma_k<64, true, true>,
                         cudaFuncAttributeMaxDynamicSharedMemorySize, C1_SMEM_64);
    cudaFuncSetAttribute(c1mma_k<128, false, false>,
                         cudaFuncAttributeMaxDynamicSharedMemorySize, C1_SMEM_128);

    const dim3 blk(256);
    const dim3 gt2(2048, 2, 2 * BSZ);       // merged transpose
    const dim3 gg(2, 256, BSZ);             // gconv
    const dim3 gg2(2, 256, 2 * BSZ);        // merged gconv
    const dim3 g1(512, BSZ);                // c1mma
    const dim3 gdw64(32, BSZ * 64);
    const dim3 gdw128(32, BSZ * 128);
    const dim3 ggram(16, 8, BSZ);

    // prep on s0: launch #4 = merged gconv (profiled)
    wpack_k<<<36, blk>>>(W_fre, w0, 64, 64);
    wpack_k<<<36, blk>>>(W_spa, w1, 64, 64);
    nchw2nhwc2_k<<<gt2, blk>>>(fre, spa, h0, l0, h1, l1);
    gconv_k<64, 64, false, false, true, false, 3, true><<<gg2, blk, GC_SMEM>>>(
        h0, l0, h0, l0, w0, b_fre, pfre1, nullptr, nullptr, nullptr, nullptr,
        h1, l1, w1, b_spa, pspa1);

    // fork s1 after fre1/spa1 ready
    cudaEventRecord(evFork1, 0);
    cudaStreamWaitEvent(s1, evFork1, 0);

    // ---- attention 1 ----
    // s1: fuse wpacks + q chain
    wpack_k<<<72, blk, 0, s1>>>(Wf1, wF1, 128, 64);
    wpack_k<<<72, blk, 0, s1>>>(Wf2, wF2, 64, 128);
    c1mma_k<64, false, false><<<g1, blk, C1_SMEM_64, s1>>>(pfre1, 64, 0, Wq, 0, nullptr, ptmp, 64, nullptr, nullptr);
    dw3x3_k<<<gdw64, blk, 0, s1>>>(ptmp, Wq_dw, pq, 64);
    zero_k<<<10, blk, 0, s1>>>(pstats, 2560);
    cudaEventRecord(evQ1, s1);
    // s0: kv chain
    c1mma_k<128, false, false><<<g1, blk, C1_SMEM_128>>>(pspa1, 64, 0, Wkv, 0, nullptr, pkv0, 128, nullptr, nullptr);
    dw3x3_k<<<gdw128, blk>>>(pkv0, Wkv_dw, pkv, 128);
    cudaStreamWaitEvent(0, evQ1, 0);
    gramnorm_k<<<ggram, blk>>>(pq, 64, pkv, 128, pG, pnq, pnk);
    softmax_meff_k<<<BSZ, 64>>>(temp, Wproj, pG, pnq, pnk, pmeff);
    cudaEventRecord(evFork2, 0);   // pq/pstats free after this
    c1mma_k<64, true, true><<<g1, blk, C1_SMEM_64>>>(pkv, 128, 64, pmeff, 64 * 64, pfre1, pfre2, 64, h2, l2);

    // ---- attention 2 ----
    cudaStreamWaitEvent(s1, evFork2, 0);
    c1mma_k<64, false, false><<<g1, blk, C1_SMEM_64, s1>>>(pspa1, 64, 0, Wq, 0, nullptr, ptmp, 64, nullptr, nullptr);
    dw3x3_k<<<gdw64, blk, 0, s1>>>(ptmp, Wq_dw, pq, 64);
    zero_k<<<10, blk, 0, s1>>>(pstats, 2560);
    cudaEventRecord(evQ2, s1);
    c1mma_k<128, false, false><<<g1, blk, C1_SMEM_128>>>(pfre2, 64, 0, Wkv, 0, nullptr, pkv0, 128, nullptr, nullptr);
    dw3x3_k<<<gdw128, blk>>>(pkv0, Wkv_dw, pkv, 128);
    cudaStreamWaitEvent(0, evQ2, 0);
    gramnorm_k<<<ggram, blk>>>(pq, 64, pkv, 128, pG, pnq, pnk);
    softmax_meff_k<<<BSZ, 64>>>(temp, Wproj, pG, pnq, pnk, pmeff);
    c1mma_k<64, true, true><<<g1, blk, C1_SMEM_64>>>(pkv, 128, 64, pmeff, 64 * 64, pspa1, pspa2, 64, h3, l3);

    // ---- fuse path: F1 (concat -> t1 NHWC), F2 + final gate fused ----
    gconv_k<128, 64, false, false, false, true, 3, false><<<gg, blk, GC_SMEM>>>(
        h2, l2, h3, l3, wF1, bf1, nullptr, h4, l4, nullptr, nullptr,
        nullptr, nullptr, nullptr, nullptr, nullptr);
    gconv_k<64, 128, true, true, false, false, 2, false><<<gg, blk, GC_SMEM>>>(
        h4, l4, h4, l4, wF2, bf2, out, nullptr, nullptr, pfre2, pspa2,
        nullptr, nullptr, nullptr, nullptr, nullptr);
}

// round 16
// speedup vs baseline: 1.4055x; 1.0003x over previous
#include <cuda_runtime.h>
#include <cuda_bf16.h>
#include <math.h>
#include <stdint.h>

#define BSZ 4
#define HDIM 256
#define WDIM 256
#define HW 65536

// ---------------- scratch (device globals) ----------------
__device__ float g_fre1[(size_t)BSZ * 64 * HW];
__device__ float g_spa1[(size_t)BSZ * 64 * HW];
__device__ float g_tmp [(size_t)BSZ * 64 * HW];
__device__ float g_q   [(size_t)BSZ * 64 * HW];
__device__ float g_fre2[(size_t)BSZ * 64 * HW];
__device__ float g_spa2[(size_t)BSZ * 64 * HW];
__device__ float g_kv0 [(size_t)BSZ * 128 * HW];
__device__ float g_kv  [(size_t)BSZ * 128 * HW];
__device__ float g_stats[2560];
__device__ float g_Meff[BSZ * 64 * 64];
// NHWC bf16 hi/lo slots: 0=fre 1=spa 2=fre2 3=spa2 4=t1
__device__ __nv_bfloat16 g_nh_hi[5][(size_t)BSZ * HW * 64];
__device__ __nv_bfloat16 g_nh_lo[5][(size_t)BSZ * HW * 64];
// packed weights uint4 {hi(k0pair), lo(k0pair), hi(k1pair), lo(k1pair)}
__device__ uint4 g_wpk4[55296];

// ---------------- mma.sync / cp.async helpers (baseline sm_80+, no 'a' arch) ----------------
__device__ __forceinline__ uint32_t smem_u32(const void* p) {
    uint32_t a;
    asm("{ .reg .u64 t; cvta.to.shared.u64 t, %1; cvt.u32.u64 %0, t; }" : "=r"(a) : "l"(p));
    return a;
}
__device__ __forceinline__ void ldmA(uint32_t r[4], uint32_t a) {
    asm volatile("ldmatrix.sync.aligned.m8n8.x4.shared.b16 {%0,%1,%2,%3}, [%4];"
                 : "=r"(r[0]), "=r"(r[1]), "=r"(r[2]), "=r"(r[3]) : "r"(a));
}
__device__ __forceinline__ void ldmT(uint32_t r[4], uint32_t a) {
    asm volatile("ldmatrix.sync.aligned.m8n8.x4.trans.shared.b16 {%0,%1,%2,%3}, [%4];"
                 : "=r"(r[0]), "=r"(r[1]), "=r"(r[2]), "=r"(r[3]) : "r"(a));
}
__device__ __forceinline__ void mma16816(float* c, const uint32_t* a, const uint32_t* b) {
    asm volatile(
        "mma.sync.aligned.m16n8k16.row.col.f32.bf16.bf16.f32 "
        "{%0,%1,%2,%3}, {%4,%5,%6,%7}, {%8,%9}, {%0,%1,%2,%3};"
        : "+f"(c[0]), "+f"(c[1]), "+f"(c[2]), "+f"(c[3])
        : "r"(a[0]), "r"(a[1]), "r"(a[2]), "r"(a[3]), "r"(b[0]), "r"(b[1]));
}
__device__ __forceinline__ void cpa16(uint32_t d, const void* s, int pb) {
    asm volatile("cp.async.cg.shared.global [%0], [%1], 16, %2;"
                 :: "r"(d), "l"(s), "r"(pb) : "memory");
}
__device__ __forceinline__ void cpa_commit() {
    asm volatile("cp.async.commit_group;" ::: "memory");
}
__device__ __forceinline__ void cpa_wait1() {
    asm volatile("cp.async.wait_group 1;" ::: "memory");
}
__device__ __forceinline__ void cpa_wait0() {
    asm volatile("cp.async.wait_group 0;" ::: "memory");
}
__device__ __forceinline__ void split4(float4 v, uint2& hi, uint2& lo) {
    __nv_bfloat16 h0 = __float2bfloat16(v.x), h1 = __float2bfloat16(v.y);
    __nv_bfloat16 h2 = __float2bfloat16(v.z), h3 = __float2bfloat16(v.w);
    __nv_bfloat16 l0 = __float2bfloat16(v.x - __bfloat162float(h0));
    __nv_bfloat16 l1 = __float2bfloat16(v.y - __bfloat162float(h1));
    __nv_bfloat16 l2 = __float2bfloat16(v.z - __bfloat162float(h2));
    __nv_bfloat16 l3 = __float2bfloat16(v.w - __bfloat162float(h3));
    hi.x = ((uint32_t)__bfloat16_as_ushort(h1) << 16) | __bfloat16_as_ushort(h0);
    hi.y = ((uint32_t)__bfloat16_as_ushort(h3) << 16) | __bfloat16_as_ushort(h2);
    lo.x = ((uint32_t)__bfloat16_as_ushort(l1) << 16) | __bfloat16_as_ushort(l0);
    lo.y = ((uint32_t)__bfloat16_as_ushort(l3) << 16) | __bfloat16_as_ushort(l2);
}

__global__ void zero_k(float* p, int n) {
    int i = blockIdx.x * 256 + threadIdx.x;
    if (i < n) p[i] = 0.f;
}
__device__ __forceinline__ float fix_nan(float x) { return isfinite(x) ? x : 1e-5f; }
__device__ __forceinline__ float sigm(float x) { return 1.f / (1.f + expf(-x)); }

// ---------------- merged NCHW fp32 -> NHWC bf16 hi/lo (two tensors via z) ----------------
__global__ void nchw2nhwc2_k(const float* __restrict__ inA, const float* __restrict__ inB,
                             __nv_bfloat16* __restrict__ ohiA, __nv_bfloat16* __restrict__ oloA,
                             __nv_bfloat16* __restrict__ ohiB, __nv_bfloat16* __restrict__ oloB) {
    __shared__ float s[32][33];
    const int z = blockIdx.z;
    const float* in = (z < BSZ) ? inA : inB;
    __nv_bfloat16* ohi = (z < BSZ) ? ohiA : ohiB;
    __nv_bfloat16* olo = (z < BSZ) ? oloA : oloB;
    const int b = z & 3, ch0 = blockIdx.y * 32, p0 = blockIdx.x * 32;
    const int lx = threadIdx.x & 31, ly = threadIdx.x >> 5;
#pragma unroll
    for (int i = 0; i < 4; ++i) {
        int c = ly + i * 8;
        s[c][lx] = in[((size_t)(b * 64 + ch0 + c)) * HW + p0 + lx];
    }
    __syncthreads();
#pragma unroll
    for (int i = 0; i < 4; ++i) {
        int p = ly + i * 8;
        float v = s[lx][p];
        __nv_bfloat16 h = __float2bfloat16(v);
        size_t idx = ((size_t)b * HW + p0 + p) * 64 + ch0 + lx;
        ohi[idx] = h;
        olo[idx] = __float2bfloat16(v - __bfloat162float(h));
    }
}

// ---------------- weight pack: OIHW -> [tap][chunk16][co][tig] uint4 ----------------
__global__ void wpack_k(const float* __restrict__ W, uint4* __restrict__ pk, int CIN, int CO) {
    int NCH = CIN >> 4;
    int n = 9 * NCH * CO * 4;
    int i = blockIdx.x * 256 + threadIdx.x;
    if (i >= n) return;
    int tig = i & 3;
    int t2 = i >> 2;
    int co = t2 % CO;
    int t3 = t2 / CO;
    int chv = t3 % NCH, tap = t3 / NCH;
    int ci0 = chv * 16 + 2 * tig;
    uint4 o;
#pragma unroll
    for (int half = 0; half < 2; ++half) {
        int ci = ci0 + half * 8;
        float w0 = W[((size_t)co * CIN + ci) * 9 + tap];
        float w1 = W[((size_t)co * CIN + ci + 1) * 9 + tap];
        __nv_bfloat16 h0 = __float2bfloat16(w0), h1 = __float2bfloat16(w1);
        __nv_bfloat16 l0 = __float2bfloat16(w0 - __bfloat162float(h0));
        __nv_bfloat16 l1 = __float2bfloat16(w1 - __bfloat162float(h1));
        uint32_t hp = ((uint32_t)__bfloat16_as_ushort(h1) << 16) | __bfloat16_as_ushort(h0);
        uint32_t lp = ((uint32_t)__bfloat16_as_ushort(l1) << 16) | __bfloat16_as_ushort(l0);
        if (half == 0) { o.x = hp; o.y = lp; } else { o.z = hp; o.w = lp; }
    }
    pk[i] = o;
}

// ---------------- mma.sync bf16 3-term implicit-GEMM 3x3 conv ----------------
#define GC_BUF 37440                 // 130 px * 144 B * 2 (hi+lo)
#define GC_SMEM (2 * GC_BUF)         // 74880
#define LOOFF 18720                  // 130 * 144

__device__ __forceinline__ void gc_stage(const __nv_bfloat16* __restrict__ shi,
                                         const __nv_bfloat16* __restrict__ slo,
                                         int b, int gy, bool yok, int xbase,
                                         uint32_t dst, int tid) {
    const int gyc = yok ? gy : 0;
    for (int idx = tid; idx < 260; idx += 256) {
        const int px = idx >> 1, q = idx & 1;
        const int gx = xbase + px - 1;
        const bool ok = yok && gx >= 0 && gx < WDIM;
        const int gxc = (gx >= 0 && gx < WDIM) ? gx : 0;
        const int pb = ok ? 16 : 0;
        size_t off = ((size_t)b * HW + (size_t)gyc * WDIM + gxc) * 64 + q * 32;
        const char* ph = (const char*)(shi + off);
        const char* pl = (const char*)(slo + off);
        uint32_t dh = dst + px * 144 + q * 64;
        uint32_t dl = dst + LOOFF + px * 144 + q * 64;
#pragma unroll
        for (int i = 0; i < 4; ++i) {
            cpa16(dh + i * 16, ph + i * 16, pb);
            cpa16(dl + i * 16, pl + i * 16, pb);
        }
    }
    cpa_commit();
}

template <int CIN, int CO, bool SIG, bool FINAL, bool NCHWOUT, bool NHWCOUT, int MINB, bool MERGED>
__global__ void __launch_bounds__(256, MINB)
gconv_k(const __nv_bfloat16* __restrict__ sAhi, const __nv_bfloat16* __restrict__ sAlo,
        const __nv_bfloat16* __restrict__ sBhi, const __nv_bfloat16* __restrict__ sBlo,
        const uint4* __restrict__ wb, const float* __restrict__ bias,
        float* __restrict__ outc,
        __nv_bfloat16* __restrict__ onhi, __nv_bfloat16* __restrict__ onlo,
        const float* __restrict__ resA, const float* __restrict__ resB,
        const __nv_bfloat16* __restrict__ A2hi, const __nv_bfloat16* __restrict__ A2lo,
        const uint4* __restrict__ wb2, const float* __restrict__ bias2,
        float* __restrict__ outc2) {
    extern __shared__ char smem[];
    constexpr int NGRP = CIN / 64;
    constexpr int NWN = CO / 32;
    constexpr int NWM = 8 / NWN;
    constexpr int MPW = 128 / NWM;
    constexpr int MT  = MPW / 16;
    const int NSTG = 3 * NGRP;

    const int tid = threadIdx.x, wid = tid >> 5, lane = tid & 31;
    const int warpN = wid % NWN, warpM = wid / NWN;
    int b = blockIdx.z;
    const __nv_bfloat16* Ahi = sAhi;
    const __nv_bfloat16* Alo = sAlo;
    const __nv_bfloat16* Bhi = sBhi;
    const __nv_bfloat16* Blo = sBlo;
    const uint4* wbp = wb;
    const float* biasp = bias;
    float* outp = outc;
    if (MERGED && blockIdx.z >= BSZ) {
        b -= BSZ;
        Ahi = A2hi; Alo = A2lo; Bhi = A2hi; Blo = A2lo;
        wbp = wb2; biasp = bias2; outp = outc2;
    }
    const int y = blockIdx.y, xbase = blockIdx.x * 128;
    const int g = lane >> 2, tig = lane & 3;
    const uint32_t sb = smem_u32(smem);

    float acc[MT][4][4];
#pragma unroll
    for (int mt = 0; mt < MT; ++mt)
#pragma unroll
        for (int nt = 0; nt < 4; ++nt)
#pragma unroll
            for (int q = 0; q < 4; ++q) acc[mt][nt][q] = 0.f;

    // prologue: issue stage 0 into buf 0
    {
        const int gy = y - 1;
        gc_stage(Ahi, Alo, b, gy, (gy >= 0) && (gy < HDIM), xbase, sb, tid);
    }

    for (int st = 0; st < NSTG; ++st) {
        __syncthreads();   // all warps done with buf[(st+1)&1] (computed at st-1)
        if (st + 1 < NSTG) {
            const int dyN = (st + 1) / NGRP, grpN = (st + 1) % NGRP;
            const int gyN = y + dyN - 1;
            gc_stage(grpN ? Bhi : Ahi, grpN ? Blo : Alo, b, gyN,
                     (gyN >= 0) && (gyN < HDIM), xbase,
                     sb + ((st + 1) & 1) * GC_BUF, tid);
            cpa_wait1();
        } else {
            cpa_wait0();
        }
        __syncthreads();   // staged data for st visible

        const int dyI = st / NGRP, grp = st % NGRP;
        const uint32_t sbuf = sb + (st & 1) * GC_BUF;

        if (MT == 2) {
            // -------- software-pipelined: double-buffer weights + fragments --------
            const int px0 = warpM * MPW + (lane & 15);
            const uint32_t abase = sbuf + ((lane >> 4) & 1) * 16;
            uint4 wr[2][4];
            uint32_t ah[2][2][4], al[2][2][4];
            // prefetch it = 0
            {
                const uint4* wc = wbp + (size_t)((dyI * 3) * (CIN / 16) + grp * 4) * CO * 4;
#pragma unroll
                for (int nt = 0; nt < 4; ++nt)
                    wr[0][nt] = __ldg(&wc[(warpN * 32 + nt * 8 + g) * 4 + tig]);
#pragma unroll
                for (int mt = 0; mt < 2; ++mt) {
                    uint32_t addr = abase + (px0 + mt * 16) * 144;
                    ldmA(ah[0][mt], addr);
                    ldmA(al[0][mt], addr + LOOFF);
                }
            }
#pragma unroll
            for (int it = 0; it < 12; ++it) {
                const int cur = it & 1, nxt = cur ^ 1;
                if (it + 1 < 12) {
                    const int dxN = (it + 1) >> 2, chN = (it + 1) & 3;
                    const uint4* wc = wbp
                        + (size_t)((dyI * 3 + dxN) * (CIN / 16) + grp * 4 + chN) * CO * 4;
#pragma unroll
                    for (int nt = 0; nt < 4; ++nt)
                        wr[nxt][nt] = __ldg(&wc[(warpN * 32 + nt * 8 + g) * 4 + tig]);
#pragma unroll
                    for (int mt = 0; mt < 2; ++mt) {
                        uint32_t addr = abase + (px0 + mt * 16 + dxN) * 144 + chN * 32;
                        ldmA(ah[nxt][mt], addr);
                        ldmA(al[nxt][mt], addr + LOOFF);
                    }
                }
                uint32_t bh[4][2], bl[4][2];
#pragma unroll
                for (int nt = 0; nt < 4; ++nt) {
                    bh[nt][0] = wr[cur][nt].x; bl[nt][0] = wr[cur][nt].y;
                    bh[nt][1] = wr[cur][nt].z; bl[nt][1] = wr[cur][nt].w;
                }
#pragma unroll
                for (int mt = 0; mt < 2; ++mt) {
#pragma unroll
                    for (int nt = 0; nt < 4; ++nt) mma16816(acc[mt][nt], ah[cur][mt], bh[nt]);
#pragma unroll
                    for (int nt = 0; nt < 4; ++nt) mma16816(acc[mt][nt], al[cur][mt], bh[nt]);
#pragma unroll
                    for (int nt = 0; nt < 4; ++nt) mma16816(acc[mt][nt], ah[cur][mt], bl[nt]);
                }
            }
        } else {
            // -------- original path (CO=128 / MT=4: register budget too tight to pipeline) ------
#pragma unroll
            for (int dxI = 0; dxI < 3; ++dxI) {
                const int tap = dyI * 3 + dxI;
#pragma unroll
                for (int ch = 0; ch < 4; ++ch) {
                    const uint4* wc = wbp + (size_t)(tap * (CIN / 16) + grp * 4 + ch) * CO * 4;
                    uint32_t bh[4][2], bl[4][2];
#pragma unroll
                    for (int nt = 0; nt < 4; ++nt) {
                        int n = warpN * 32 + nt * 8 + g;
                        uint4 w4 = __ldg(&wc[n * 4 + tig]);
                        bh[nt][0] = w4.x; bl[nt][0] = w4.y;
                        bh[nt][1] = w4.z; bl[nt][1] = w4.w;
                    }
#pragma unroll
                    for (int mt = 0; mt < MT; ++mt) {
                        const int pxl = warpM * MPW + mt * 16 + (lane & 15) + dxI;
                        uint32_t addr = sbuf + pxl * 144 + ch * 32 + ((lane >> 4) & 1) * 16;
                        uint32_t ah[4], al[4];
                        ldmA(ah, addr);
                        ldmA(al, addr + LOOFF);
#pragma unroll
                        for (int nt = 0; nt < 4; ++nt) mma16816(acc[mt][nt], ah, bh[nt]);
#pragma unroll
                        for (int nt = 0; nt < 4; ++nt) mma16816(acc[mt][nt], al, bh[nt]);
#pragma unroll
                        for (int nt = 0; nt < 4; ++nt) mma16816(acc[mt][nt], ah, bl[nt]);
                    }
                }
            }
        }
    }

    // ---------------- epilogue through smem ----------------
    float* s_out = (float*)smem;  // [32 co][132 px]
    for (int co0 = 0; co0 < CO; co0 += 32) {
        __syncthreads();
        if (warpN == (co0 >> 5)) {
#pragma unroll
            for (int mt = 0; mt < MT; ++mt) {
                const int px = warpM * MPW + mt * 16 + g;
#pragma unroll
                for (int nt = 0; nt < 4; ++nt) {
                    const int cl = nt * 8 + tig * 2;
                    s_out[cl * 132 + px]           = acc[mt][nt][0];
                    s_out[(cl + 1) * 132 + px]     = acc[mt][nt][1];
                    s_out[cl * 132 + px + 8]       = acc[mt][nt][2];
                    s_out[(cl + 1) * 132 + px + 8] = acc[mt][nt][3];
                }
            }
        }
        __syncthreads();
        if (FINAL) {
            const int cl = tid >> 3, px0 = (tid & 7) * 16;
            const int c = (co0 + cl) & 63;
            const bool second = (co0 + cl) >= 64;
            const float bv = __ldg(&biasp[co0 + cl]);
            const float* res = second ? resB : resA;
            size_t off = ((size_t)(b * 64 + c)) * HW + (size_t)y * WDIM + xbase + px0;
#pragma unroll
            for (int i = 0; i < 16; i += 4) {
                float4 rv = *(const float4*)(res + off + i);
                float4 o;
                o.x = sigm(s_out[cl * 132 + px0 + i]     + bv) * rv.x;
                o.y = sigm(s_out[cl * 132 + px0 + i + 1] + bv) * rv.y;
                o.z = sigm(s_out[cl * 132 + px0 + i + 2] + bv) * rv.z;
                o.w = sigm(s_out[cl * 132 + px0 + i + 3] + bv) * rv.w;
                if (!second) {
                    *(float4*)(outp + off + i) = o;
                } else {
                    float4 prev = *(const float4*)(outp + off + i);
                    o.x = fix_nan(prev.x + o.x);
                    o.y = fix_nan(prev.y + o.y);
                    o.z = fix_nan(prev.z + o.z);
                    o.w = fix_nan(prev.w + o.w);
                    *(float4*)(outp + off + i) = o;
                }
            }
        } else {
            if (NCHWOUT) {
                const int cl = tid >> 3, px0 = (tid & 7) * 16;
                const float bv = __ldg(&biasp[co0 + cl]);
                float v[16];
#pragma unroll
                for (int i = 0; i < 16; ++i) {
                    float x = s_out[cl * 132 + px0 + i] + bv;
                    if (SIG) x = sigm(x);
                    v[i] = x;
                }
                float* op = outp + ((size_t)(b * CO + co0 + cl)) * HW + (size_t)y * WDIM + xbase + px0;
#pragma unroll
                for (int i = 0; i < 4; ++i)
                    *(float4*)(op + i * 4) = make_float4(v[i*4], v[i*4+1], v[i*4+2], v[i*4+3]);
            }
            if (NHWCOUT) {
                const int px = tid >> 1, cg = (tid & 1) * 16;
                const size_t pix = (size_t)b * HW + (size_t)y * WDIM + xbase + px;
                ushort hb[16], lb[16];
#pragma unroll
                for (int i = 0; i < 16; ++i) {
                    int cl = cg + i;
                    float x = s_out[cl * 132 + px] + __ldg(&biasp[co0 + cl]);
                    if (SIG) x = sigm(x);
                    __nv_bfloat16 h = __float2bfloat16(x);
                    hb[i] = __bfloat16_as_ushort(h);
                    lb[i] = __bfloat16_as_ushort(__float2bfloat16(x - __bfloat162float(h)));
                }
                uint4* oh = (uint4*)(onhi + pix * 64 + co0 + cg);
                uint4* ol = (uint4*)(onlo + pix * 64 + co0 + cg);
                oh[0] = *(uint4*)&hb[0]; oh[1] = *(uint4*)&hb[8];
                ol[0] = *(uint4*)&lb[0]; ol[1] = *(uint4*)&lb[8];
            }
        }
    }
}

// ---------------- conv 1x1 via mma.sync (3-term bf16) ----------------
template <int CO, bool RESID, bool NHWCOUT>
__global__ void __launch_bounds__(256)
c1mma_k(const float* __restrict__ in, int in_cs, int in_off,
        const float* __restrict__ W, int w_bs,
        const float* __restrict__ resid,
        float* __restrict__ out, int out_cs,
        __nv_bfloat16* __restrict__ onhi, __nv_bfloat16* __restrict__ onlo) {
    extern __shared__ char smem[];
    constexpr int BLO = 17408, WHI = 34816;
    constexpr int WLO = WHI + CO * 144;
    constexpr int MCO = CO / 4;
    constexpr int MT  = MCO / 16;

    const int tid = threadIdx.x, lane = tid & 31, wid = tid >> 5;
    const int warpN = wid & 1, warpM = wid >> 1;
    const int b = blockIdx.y;
    const int pxbase = blockIdx.x * 128;
    const uint32_t sb = smem_u32(smem);

    const float* ip = in + ((size_t)b * in_cs + in_off) * HW + pxbase;
#pragma unroll
    for (int pass = 0; pass < 8; ++pass) {
        const int ci = pass * 8 + (tid >> 5);
        const int px = (tid & 31) * 4;
        float4 v = *(const float4*)(ip + (size_t)ci * HW + px);
        uint2 hi, lo;
        split4(v, hi, lo);
        *(uint2*)(smem + ci * 272 + px * 2)       = hi;
        *(uint2*)(smem + BLO + ci * 272 + px * 2) = lo;
    }
    const float* wp = W + (size_t)b * w_bs;
    for (int i = tid; i < CO * 16; i += 256) {
        const int co = i >> 4, c4 = (i & 15) * 4;
        float4 v = *(const float4*)(wp + co * 64 + c4);
        uint2 hi, lo;
        split4(v, hi, lo);
        *(uint2*)(smem + WHI + co * 144 + c4 * 2) = hi;
        *(uint2*)(smem + WLO + co * 144 + c4 * 2) = lo;
    }
    __syncthreads();

    float acc[MT][8][4];
#pragma unroll
    for (int mt = 0; mt < MT; ++mt)
#pragma unroll
        for (int j = 0; j < 8; ++j)
#pragma unroll
            for (int q = 0; q < 4; ++q) acc[mt][j][q] = 0.f;

#pragma unroll
    for (int k = 0; k < 4; ++k) {
        uint32_t ah[MT][4], al[MT][4];
#pragma unroll
        for (int mt = 0; mt < MT; ++mt) {
            uint32_t addr = sb + WHI + (warpM * MCO + mt * 16 + (lane & 15)) * 144
                          + k * 32 + (lane >> 4) * 16;
            ldmA(ah[mt], addr);
            ldmA(al[mt], addr + CO * 144);
        }
        uint32_t bh[8][2], bl[8][2];
#pragma unroll
        for (int j = 0; j < 4; ++j) {
            uint32_t addr = sb + (k * 16 + (lane & 15)) * 272
                          + (warpN * 64 + j * 16 + (lane >> 4) * 8) * 2;
            uint32_t r[4];
            ldmT(r, addr);
            bh[2*j][0] = r[0]; bh[2*j][1] = r[1];
            bh[2*j+1][0] = r[2]; bh[2*j+1][1] = r[3];
            ldmT(r, addr + BLO);
            bl[2*j][0] = r[0]; bl[2*j][1] = r[1];
            bl[2*j+1][0] = r[2]; bl[2*j+1][1] = r[3];
        }
#pragma unroll
        for (int mt = 0; mt < MT; ++mt) {
#pragma unroll
            for (int j = 0; j < 8; ++j) mma16816(acc[mt][j], ah[mt], bh[j]);
#pragma unroll
            for (int j = 0; j < 8; ++j) mma16816(acc[mt][j], al[mt], bh[j]);
#pragma unroll
            for (int j = 0; j < 8; ++j) mma16816(acc[mt][j], ah[mt], bl[j]);
        }
    }

    if (!NHWCOUT) {
#pragma unroll
        for (int mt = 0; mt < MT; ++mt)
#pragma unroll
            for (int j = 0; j < 8; ++j) {
                const int co = warpM * MCO + mt * 16 + (lane >> 2);
                const int px = warpN * 64 + j * 8 + (lane & 3) * 2;
                size_t o1 = ((size_t)b * out_cs + co) * HW + pxbase + px;
                size_t o2 = o1 + (size_t)8 * HW;
                float2 r1 = make_float2(acc[mt][j][0], acc[mt][j][1]);
                float2 r2 = make_float2(acc[mt][j][2], acc[mt][j][3]);
                if (RESID) {
                    float2 q1 = *(const float2*)(resid + o1);
                    float2 q2 = *(const float2*)(resid + o2);
                    r1.x += q1.x; r1.y += q1.y; r2.x += q2.x; r2.y += q2.y;
                }
                *(float2*)(out + o1) = r1;
                *(float2*)(out + o2) = r2;
            }
    } else {
        __syncthreads();
        float* s_out = (float*)smem;  // [64 co][132 px]
#pragma unroll
        for (int mt = 0; mt < MT; ++mt)
#pragma unroll
            for (int j = 0; j < 8; ++j) {
                const int co = warpM * MCO + mt * 16 + (lane >> 2);
                const int px = warpN * 64 + j * 8 + (lane & 3) * 2;
                s_out[co * 132 + px]           = acc[mt][j][0];
                s_out[co * 132 + px + 1]       = acc[mt][j][1];
                s_out[(co + 8) * 132 + px]     = acc[mt][j][2];
                s_out[(co + 8) * 132 + px + 1] = acc[mt][j][3];
            }
        __syncthreads();
        {
            const int co = tid >> 2, px0 = (tid & 3) * 32;
            size_t off = ((size_t)b * out_cs + co) * HW + pxbase + px0;
#pragma unroll
            for (int i = 0; i < 32; i += 4) {
                float4 a = *(float4*)&s_out[co * 132 + px0 + i];
                float4 rv = *(const float4*)(resid + off + i);
                a.x += rv.x; a.y += rv.y; a.z += rv.z; a.w += rv.w;
                *(float4*)(out + off + i) = a;
                *(float4*)&s_out[co * 132 + px0 + i] = a;
            }
        }
        __syncthreads();
        {
            const int px = tid >> 1, cg = (tid & 1) * 32;
            const size_t pix = (size_t)b * HW + pxbase + px;
#pragma unroll
            for (int gi = 0; gi < 4; ++gi) {
                ushort hb[8], lb[8];
#pragma unroll
                for (int i = 0; i < 8; ++i) {
                    float x = s_out[(cg + gi * 8 + i) * 132 + px];
                    __nv_bfloat16 h = __float2bfloat16(x);
                    hb[i] = __bfloat16_as_ushort(h);
                    lb[i] = __bfloat16_as_ushort(__float2bfloat16(x - __bfloat162float(h)));
                }
                *(uint4*)(onhi + pix * 64 + cg + gi * 8) = *(uint4*)hb;
                *(uint4*)(onlo + pix * 64 + cg + gi * 8) = *(uint4*)lb;
            }
        }
    }
}

// ---------------- depthwise 3x3: full-row tiles, smem staging ----------------
__global__ void __launch_bounds__(256)
dw3x3_k(const float* __restrict__ in, const float* __restrict__ wt,
        float* __restrict__ out, int C) {
    __shared__ float s[10][260];
    const int y0 = blockIdx.x * 8;
    const int zc = blockIdx.y;
    const int c = zc % C;
    const int tid = threadIdx.x;
    const float* ip = in + (size_t)zc * HW;

    float w[9];
#pragma unroll
    for (int i = 0; i < 9; ++i) w[i] = __ldg(&wt[c * 9 + i]);

#pragma unroll
    for (int pass = 0; pass < 3; ++pass) {
        int idx = tid + pass * 256;
        if (idx < 640) {
            int r = idx >> 6, c4 = (idx & 63) * 4;
            int gy = y0 + r - 1;
            float4 v = make_float4(0.f, 0.f, 0.f, 0.f);
            if (gy >= 0 && gy < HDIM) v = *(const float4*)(ip + gy * WDIM + c4);
            *(float4*)&s[r][c4] = v;
        }
    }
    __syncthreads();

#pragma unroll
    for (int pass = 0; pass < 2; ++pass) {
        const int r = (tid >> 6) + pass * 4;
        const int px0 = (tid & 63) * 4;
        float acc[4] = {0.f, 0.f, 0.f, 0.f};
#pragma unroll
        for (int ky = 0; ky < 3; ++ky) {
            const float* row = s[r + ky];
            float4 m = *(const float4*)&row[px0];
            float v0 = (px0 == 0) ? 0.f : row[px0 - 1];
            float v5 = (px0 == 252) ? 0.f : row[px0 + 4];
            float v[6] = {v0, m.x, m.y, m.z, m.w, v5};
#pragma unroll
            for (int kx = 0; kx < 3; ++kx)
#pragma unroll
                for (int p = 0; p < 4; ++p)
                    acc[p] += w[ky * 3 + kx] * v[kx + p];
        }
        *(float4*)&out[(size_t)zc * HW + (y0 + r) * WDIM + px0] =
            make_float4(acc[0], acc[1], acc[2], acc[3]);
    }
}

// ---------------- Gram + norms ----------------
__global__ void gramnorm_k(const float* __restrict__ q, int qcs,
                           const float* __restrict__ k, int kcs,
                           float* __restrict__ G, float* __restrict__ nq,
                           float* __restrict__ nk) {
    const int b = blockIdx.z, h = blockIdx.y;
    const int p0 = blockIdx.x * 4096 + threadIdx.x;
    const float* qb = q + ((size_t)b * qcs + h * 8) * HW;
    const float* kb = k + ((size_t)b * kcs + h * 8) * HW;
    float acc[80];
#pragma unroll
    for (int i = 0; i < 80; ++i) acc[i] = 0.f;
    for (int it = 0; it < 16; ++it) {
        int p = p0 + it * 256;
        float qv[8], kv[8];
#pragma unroll
        for (int c = 0; c < 8; ++c) {
            qv[c] = qb[(size_t)c * HW + p];
            kv[c] = kb[(size_t)c * HW + p];
        }
#pragma unroll
        for (int c = 0; c < 8; ++c) {
            acc[64 + c] += qv[c] * qv[c];
            acc[72 + c] += kv[c] * kv[c];
#pragma unroll
            for (int d = 0; d < 8; ++d) acc[c * 8 + d] += qv[c] * kv[d];
        }
    }
    __shared__ float red[80][8];
    const int lane = threadIdx.x & 31, warp = threadIdx.x >> 5;
#pragma unroll
    for (int i = 0; i < 80; ++i) {
        float v = acc[i];
        v += __shfl_down_sync(0xffffffffu, v, 16);
        v += __shfl_down_sync(0xffffffffu, v, 8);
        v += __shfl_down_sync(0xffffffffu, v, 4);
        v += __shfl_down_sync(0xffffffffu, v, 2);
        v += __shfl_down_sync(0xffffffffu, v, 1);
        if (lane == 0) red[i][warp] = v;
    }
    __syncthreads();
    if (threadIdx.x < 80) {
        float s = 0.f;
#pragma unroll
        for (int w = 0; w < 8; ++w) s += red[threadIdx.x][w];
        int i = threadIdx.x;
        if (i < 64)
            atomicAdd(&G[(((size_t)b * 8 + h) * 8 + (i >> 3)) * 8 + (i & 7)], s);
        else if (i < 72)
            atomicAdd(&nq[b * 64 + h * 8 + (i - 64)], s);
        else
            atomicAdd(&nk[b * 64 + h * 8 + (i - 72)], s);
    }
}

// ---------------- softmax + proj fold ----------------
__global__ void softmax_meff_k(const float* __restrict__ temp, const float* __restrict__ Wproj,
                               const float* __restrict__ G, const float* __restrict__ nq,
                               const float* __restrict__ nk, float* __restrict__ Meff) {
    const int b = blockIdx.x;
    const int t = threadIdx.x;
    __shared__ float attn[8][8][8];
    {
        int h = t >> 3, c = t & 7;
        float nqc = fmaxf(sqrtf(nq[b * 64 + h * 8 + c]), 1e-12f);
        float row[8];
        float m = -1e30f;
#pragma unroll
        for (int d = 0; d < 8; ++d) {
            float nkd = fmaxf(sqrtf(nk[b * 64 + h * 8 + d]), 1e-12f);
            row[d] = temp[h] * G[(((size_t)b * 8 + h) * 8 + c) * 8 + d] / (nqc * nkd);
            m = fmaxf(m, row[d]);
        }
        float sum = 0.f;
#pragma unroll
        for (int d = 0; d < 8; ++d) { row[d] = expf(row[d] - m); sum += row[d]; }
        float inv = 1.f / sum;
#pragma unroll
        for (int d = 0; d < 8; ++d) attn[h][c][d] = row[d] * inv;
    }
    __syncthreads();
    const int o = t;
    for (int dg = 0; dg < 64; ++dg) {
        int hh = dg >> 3, j = dg & 7;
        float s = 0.f;
#pragma unroll
        for (int i = 0; i < 8; ++i) s += Wproj[o * 64 + hh * 8 + i] * attn[hh][i][j];
        Meff[((size_t)b * 64 + o) * 64 + dg] = s;
    }
}

// ---------------- host orchestration (two-stream fork/join, graph-capturable) ----------------
extern "C" void kernel_launch(void* const* d_in, const int* in_sizes, int n_in,
                              void* d_out, int out_size) {
    const float* spa    = (const float*)d_in[0];
    const float* fre    = (const float*)d_in[1];
    const float* W_fre  = (const float*)d_in[2];
    const float* b_fre  = (const float*)d_in[3];
    const float* W_spa  = (const float*)d_in[4];
    const float* b_spa  = (const float*)d_in[5];
    const float* temp   = (const float*)d_in[6];
    const float* Wq     = (const float*)d_in[7];
    const float* Wq_dw  = (const float*)d_in[8];
    const float* Wkv    = (const float*)d_in[9];
    const float* Wkv_dw = (const float*)d_in[10];
    const float* Wproj  = (const float*)d_in[11];
    const float* Wf1    = (const float*)d_in[12];
    const float* bf1    = (const float*)d_in[13];
    const float* Wf2    = (const float*)d_in[14];
    const float* bf2    = (const float*)d_in[15];
    float* out = (float*)d_out;

    float *pfre1, *pspa1, *ptmp, *pq, *pfre2, *pspa2, *pkv0, *pkv, *pstats, *pmeff;
    __nv_bfloat16 *phi, *plo;
    uint4* pwk;
    cudaGetSymbolAddress((void**)&pfre1, g_fre1);
    cudaGetSymbolAddress((void**)&pspa1, g_spa1);
    cudaGetSymbolAddress((void**)&ptmp,  g_tmp);
    cudaGetSymbolAddress((void**)&pq,    g_q);
    cudaGetSymbolAddress((void**)&pfre2, g_fre2);
    cudaGetSymbolAddress((void**)&pspa2, g_spa2);
    cudaGetSymbolAddress((void**)&pkv0,  g_kv0);
    cudaGetSymbolAddress((void**)&pkv,   g_kv);
    cudaGetSymbolAddress((void**)&pstats, g_stats);
    cudaGetSymbolAddress((void**)&pmeff, g_Meff);
    cudaGetSymbolAddress((void**)&phi,   g_nh_hi);
    cudaGetSymbolAddress((void**)&plo,   g_nh_lo);
    cudaGetSymbolAddress((void**)&pwk,   g_wpk4);
    float* pG  = pstats;
    float* pnq = pstats + 2048;
    float* pnk = pstats + 2304;
    const size_t NHN = (size_t)BSZ * HW * 64;
    __nv_bfloat16 *h0 = phi, *h1 = phi + NHN, *h2 = phi + 2*NHN, *h3 = phi + 3*NHN, *h4 = phi + 4*NHN;
    __nv_bfloat16 *l0 = plo, *l1 = plo + NHN, *l2 = plo + 2*NHN, *l3 = plo + 3*NHN, *l4 = plo + 4*NHN;
    uint4 *w0 = pwk, *w1 = pwk + 9216, *wF1 = pwk + 18432, *wF2 = pwk + 36864;

    static cudaStream_t s1 = nullptr;
    static cudaEvent_t evFork1, evQ1, evFork2, evQ2;
    if (s1 == nullptr) {
        cudaStreamCreateWithFlags(&s1, cudaStreamNonBlocking);
        cudaEventCreateWithFlags(&evFork1, cudaEventDisableTiming);
        cudaEventCreateWithFlags(&evQ1,    cudaEventDisableTiming);
        cudaEventCreateWithFlags(&evFork2, cudaEventDisableTiming);
        cudaEventCreateWithFlags(&evQ2,    cudaEventDisableTiming);
    }

    cudaFuncSetAttribute(gconv_k<64, 64, false, false, true, false, 2, true>,
                         cudaFuncAttributeMaxDynamicSharedMemorySize, GC_SMEM);
    cudaFuncSetAttribute(gconv_k<128, 64, false, false, false, true, 2, false>,
                         cudaFuncAttributeMaxDynamicSharedMemorySize, GC_SMEM);
    cudaFuncSetAttribute(gconv_k<64, 128, true, true, false, false, 2, false>,
                         cudaFuncAttributeMaxDynamicSharedMemorySize, GC_SMEM);
    const int C1_SMEM_64  = 34816 + 64 * 144 * 2;    // 53248
    const int C1_SMEM_128 = 34816 + 128 * 144 * 2;   // 71680
    cudaFuncSetAttribute(c1mma_k<64, false, false>,
                         cudaFuncAttributeMaxDynamicSharedMemorySize, C1_SMEM_64);
    cudaFuncSetAttribute(c1mma_k<64, true, true>,
                         cudaFuncAttributeMaxDynamicSharedMemorySize, C1_SMEM_64);
    cudaFuncSetAttribute(c1mma_k<128, false, false>,
                         cudaFuncAttributeMaxDynamicSharedMemorySize, C1_SMEM_128);

    const dim3 blk(256);
    const dim3 gt2(2048, 2, 2 * BSZ);       // merged transpose
    const dim3 gg(2, 256, BSZ);             // gconv
    const dim3 gg2(2, 256, 2 * BSZ);        // merged gconv
    const dim3 g1(512, BSZ);                // c1mma
    const dim3 gdw64(32, BSZ * 64);
    const dim3 gdw128(32, BSZ * 128);
    const dim3 ggram(16, 8, BSZ);

    // prep on s0: launch #4 = merged gconv (profiled)
    wpack_k<<<36, blk>>>(W_fre, w0, 64, 64);
    wpack_k<<<36, blk>>>(W_spa, w1, 64, 64);
    nchw2nhwc2_k<<<gt2, blk>>>(fre, spa, h0, l0, h1, l1);
    gconv_k<64, 64, false, false, true, false, 2, true><<<gg2, blk, GC_SMEM>>>(
        h0, l0, h0, l0, w0, b_fre, pfre1, nullptr, nullptr, nullptr, nullptr,
        h1, l1, w1, b_spa, pspa1);

    // fork s1 after fre1/spa1 ready
    cudaEventRecord(evFork1, 0);
    cudaStreamWaitEvent(s1, evFork1, 0);

    // ---- attention 1 ----
    // s1: fuse wpacks + q chain
    wpack_k<<<72, blk, 0, s1>>>(Wf1, wF1, 128, 64);
    wpack_k<<<72, blk, 0, s1>>>(Wf2, wF2, 64, 128);
    c1mma_k<64, false, false><<<g1, blk, C1_SMEM_64, s1>>>(pfre1, 64, 0, Wq, 0, nullptr, ptmp, 64, nullptr, nullptr);
    dw3x3_k<<<gdw64, blk, 0, s1>>>(ptmp, Wq_dw, pq, 64);
    zero_k<<<10, blk, 0, s1>>>(pstats, 2560);
    cudaEventRecord(evQ1, s1);
    // s0: kv chain
    c1mma_k<128, false, false><<<g1, blk, C1_SMEM_128>>>(pspa1, 64, 0, Wkv, 0, nullptr, pkv0, 128, nullptr, nullptr);
    dw3x3_k<<<gdw128, blk>>>(pkv0, Wkv_dw, pkv, 128);
    cudaStreamWaitEvent(0, evQ1, 0);
    gramnorm_k<<<ggram, blk>>>(pq, 64, pkv, 128, pG, pnq, pnk);
    softmax_meff_k<<<BSZ, 64>>>(temp, Wproj, pG, pnq, pnk, pmeff);
    cudaEventRecord(evFork2, 0);   // pq/pstats free after this
    c1mma_k<64, true, true><<<g1, blk, C1_SMEM_64>>>(pkv, 128, 64, pmeff, 64 * 64, pfre1, pfre2, 64, h2, l2);

    // ---- attention 2 ----
    cudaStreamWaitEvent(s1, evFork2, 0);
    c1mma_k<64, false, false><<<g1, blk, C1_SMEM_64, s1>>>(pspa1, 64, 0, Wq, 0, nullptr, ptmp, 64, nullptr, nullptr);
    dw3x3_k<<<gdw64, blk, 0, s1>>>(ptmp, Wq_dw, pq, 64);
    zero_k<<<10, blk, 0, s1>>>(pstats, 2560);
    cudaEventRecord(evQ2, s1);
    c1mma_k<128, false, false><<<g1, blk, C1_SMEM_128>>>(pfre2, 64, 0, Wkv, 0, nullptr, pkv0, 128, nullptr, nullptr);
    dw3x3_k<<<gdw128, blk>>>(pkv0, Wkv_dw, pkv, 128);
    cudaStreamWaitEvent(0, evQ2, 0);
    gramnorm_k<<<ggram, blk>>>(pq, 64, pkv, 128, pG, pnq, pnk);
    softmax_meff_k<<<BSZ, 64>>>(temp, Wproj, pG, pnq, pnk, pmeff);
    c1mma_k<64, true, true><<<g1, blk, C1_SMEM_64>>>(pkv, 128, 64, pmeff, 64 * 64, pspa1, pspa2, 64, h3, l3);

    // ---- fuse path: F1 (concat -> t1 NHWC), F2 + final gate fused ----
    gconv_k<128, 64, false, false, false, true, 2, false><<<gg, blk, GC_SMEM>>>(
        h2, l2, h3, l3, wF1, bf1, nullptr, h4, l4, nullptr, nullptr,
        nullptr, nullptr, nullptr, nullptr, nullptr);
    gconv_k<64, 128, true, true, false, false, 2, false><<<gg, blk, GC_SMEM>>>(
        h4, l4, h4, l4, wF2, bf2, out, nullptr, nullptr, pfre2, pspa2,
        nullptr, nullptr, nullptr, nullptr, nullptr);
}

// round 17
// speedup vs baseline: 1.4110x; 1.0039x over previous
#include <cuda_runtime.h>
#include <cuda_bf16.h>
#include <math.h>
#include <stdint.h>

#define BSZ 4
#define HDIM 256
#define WDIM 256
#define HW 65536

// ---------------- scratch (device globals) ----------------
__device__ float g_fre1[(size_t)BSZ * 64 * HW];
__device__ float g_spa1[(size_t)BSZ * 64 * HW];
__device__ float g_tmp [(size_t)BSZ * 64 * HW];
__device__ float g_q   [(size_t)BSZ * 64 * HW];
__device__ float g_fre2[(size_t)BSZ * 64 * HW];
__device__ float g_spa2[(size_t)BSZ * 64 * HW];
__device__ float g_kv0 [(size_t)BSZ * 128 * HW];
__device__ float g_kv  [(size_t)BSZ * 128 * HW];
__device__ float g_stats[2560];
__device__ float g_Meff[BSZ * 64 * 64];
// NHWC bf16 hi/lo slots: 0=fre 1=spa 2=fre2 3=spa2 4=t1
__device__ __nv_bfloat16 g_nh_hi[5][(size_t)BSZ * HW * 64];
__device__ __nv_bfloat16 g_nh_lo[5][(size_t)BSZ * HW * 64];
// packed weights uint4 {hi(k0pair), lo(k0pair), hi(k1pair), lo(k1pair)}
__device__ uint4 g_wpk4[55296];

// ---------------- mma.sync / cp.async helpers (baseline sm_80+, no 'a' arch) ----------------
__device__ __forceinline__ uint32_t smem_u32(const void* p) {
    uint32_t a;
    asm("{ .reg .u64 t; cvta.to.shared.u64 t, %1; cvt.u32.u64 %0, t; }" : "=r"(a) : "l"(p));
    return a;
}
__device__ __forceinline__ void ldmA(uint32_t r[4], uint32_t a) {
    asm volatile("ldmatrix.sync.aligned.m8n8.x4.shared.b16 {%0,%1,%2,%3}, [%4];"
                 : "=r"(r[0]), "=r"(r[1]), "=r"(r[2]), "=r"(r[3]) : "r"(a));
}
__device__ __forceinline__ void ldmT(uint32_t r[4], uint32_t a) {
    asm volatile("ldmatrix.sync.aligned.m8n8.x4.trans.shared.b16 {%0,%1,%2,%3}, [%4];"
                 : "=r"(r[0]), "=r"(r[1]), "=r"(r[2]), "=r"(r[3]) : "r"(a));
}
__device__ __forceinline__ void mma16816(float* c, const uint32_t* a, const uint32_t* b) {
    asm volatile(
        "mma.sync.aligned.m16n8k16.row.col.f32.bf16.bf16.f32 "
        "{%0,%1,%2,%3}, {%4,%5,%6,%7}, {%8,%9}, {%0,%1,%2,%3};"
        : "+f"(c[0]), "+f"(c[1]), "+f"(c[2]), "+f"(c[3])
        : "r"(a[0]), "r"(a[1]), "r"(a[2]), "r"(a[3]), "r"(b[0]), "r"(b[1]));
}
__device__ __forceinline__ void cpa16(uint32_t d, const void* s, int pb) {
    asm volatile("cp.async.cg.shared.global [%0], [%1], 16, %2;"
                 :: "r"(d), "l"(s), "r"(pb) : "memory");
}
__device__ __forceinline__ void cpa_commit() {
    asm volatile("cp.async.commit_group;" ::: "memory");
}
__device__ __forceinline__ void cpa_wait1() {
    asm volatile("cp.async.wait_group 1;" ::: "memory");
}
__device__ __forceinline__ void cpa_wait0() {
    asm volatile("cp.async.wait_group 0;" ::: "memory");
}
__device__ __forceinline__ void split4(float4 v, uint2& hi, uint2& lo) {
    __nv_bfloat16 h0 = __float2bfloat16(v.x), h1 = __float2bfloat16(v.y);
    __nv_bfloat16 h2 = __float2bfloat16(v.z), h3 = __float2bfloat16(v.w);
    __nv_bfloat16 l0 = __float2bfloat16(v.x - __bfloat162float(h0));
    __nv_bfloat16 l1 = __float2bfloat16(v.y - __bfloat162float(h1));
    __nv_bfloat16 l2 = __float2bfloat16(v.z - __bfloat162float(h2));
    __nv_bfloat16 l3 = __float2bfloat16(v.w - __bfloat162float(h3));
    hi.x = ((uint32_t)__bfloat16_as_ushort(h1) << 16) | __bfloat16_as_ushort(h0);
    hi.y = ((uint32_t)__bfloat16_as_ushort(h3) << 16) | __bfloat16_as_ushort(h2);
    lo.x = ((uint32_t)__bfloat16_as_ushort(l1) << 16) | __bfloat16_as_ushort(l0);
    lo.y = ((uint32_t)__bfloat16_as_ushort(l3) << 16) | __bfloat16_as_ushort(l2);
}

__global__ void zero_k(float* p, int n) {
    int i = blockIdx.x * 256 + threadIdx.x;
    if (i < n) p[i] = 0.f;
}
__device__ __forceinline__ float fix_nan(float x) { return isfinite(x) ? x : 1e-5f; }
__device__ __forceinline__ float sigm(float x) { return 1.f / (1.f + expf(-x)); }

// ---------------- merged NCHW fp32 -> NHWC bf16 hi/lo (two tensors via z) ----------------
__global__ void nchw2nhwc2_k(const float* __restrict__ inA, const float* __restrict__ inB,
                             __nv_bfloat16* __restrict__ ohiA, __nv_bfloat16* __restrict__ oloA,
                             __nv_bfloat16* __restrict__ ohiB, __nv_bfloat16* __restrict__ oloB) {
    __shared__ float s[32][33];
    const int z = blockIdx.z;
    const float* in = (z < BSZ) ? inA : inB;
    __nv_bfloat16* ohi = (z < BSZ) ? ohiA : ohiB;
    __nv_bfloat16* olo = (z < BSZ) ? oloA : oloB;
    const int b = z & 3, ch0 = blockIdx.y * 32, p0 = blockIdx.x * 32;
    const int lx = threadIdx.x & 31, ly = threadIdx.x >> 5;
#pragma unroll
    for (int i = 0; i < 4; ++i) {
        int c = ly + i * 8;
        s[c][lx] = in[((size_t)(b * 64 + ch0 + c)) * HW + p0 + lx];
    }
    __syncthreads();
#pragma unroll
    for (int i = 0; i < 4; ++i) {
        int p = ly + i * 8;
        float v = s[lx][p];
        __nv_bfloat16 h = __float2bfloat16(v);
        size_t idx = ((size_t)b * HW + p0 + p) * 64 + ch0 + lx;
        ohi[idx] = h;
        olo[idx] = __float2bfloat16(v - __bfloat162float(h));
    }
}

// ---------------- weight pack: OIHW -> [tap][chunk16][co][tig] uint4 ----------------
__global__ void wpack_k(const float* __restrict__ W, uint4* __restrict__ pk, int CIN, int CO) {
    int NCH = CIN >> 4;
    int n = 9 * NCH * CO * 4;
    int i = blockIdx.x * 256 + threadIdx.x;
    if (i >= n) return;
    int tig = i & 3;
    int t2 = i >> 2;
    int co = t2 % CO;
    int t3 = t2 / CO;
    int chv = t3 % NCH, tap = t3 / NCH;
    int ci0 = chv * 16 + 2 * tig;
    uint4 o;
#pragma unroll
    for (int half = 0; half < 2; ++half) {
        int ci = ci0 + half * 8;
        float w0 = W[((size_t)co * CIN + ci) * 9 + tap];
        float w1 = W[((size_t)co * CIN + ci + 1) * 9 + tap];
        __nv_bfloat16 h0 = __float2bfloat16(w0), h1 = __float2bfloat16(w1);
        __nv_bfloat16 l0 = __float2bfloat16(w0 - __bfloat162float(h0));
        __nv_bfloat16 l1 = __float2bfloat16(w1 - __bfloat162float(h1));
        uint32_t hp = ((uint32_t)__bfloat16_as_ushort(h1) << 16) | __bfloat16_as_ushort(h0);
        uint32_t lp = ((uint32_t)__bfloat16_as_ushort(l1) << 16) | __bfloat16_as_ushort(l0);
        if (half == 0) { o.x = hp; o.y = lp; } else { o.z = hp; o.w = lp; }
    }
    pk[i] = o;
}

// ---------------- mma.sync bf16 3-term implicit-GEMM 3x3 conv ----------------
#define GC_BUF 37440                 // 130 px * 144 B * 2 (hi+lo)
#define GC_SMEM (2 * GC_BUF)         // 74880
#define LOOFF 18720                  // 130 * 144

__device__ __forceinline__ void gc_stage(const __nv_bfloat16* __restrict__ shi,
                                         const __nv_bfloat16* __restrict__ slo,
                                         int b, int gy, bool yok, int xbase,
                                         uint32_t dst, int tid) {
    const int gyc = yok ? gy : 0;
    for (int idx = tid; idx < 260; idx += 256) {
        const int px = idx >> 1, q = idx & 1;
        const int gx = xbase + px - 1;
        const bool ok = yok && gx >= 0 && gx < WDIM;
        const int gxc = (gx >= 0 && gx < WDIM) ? gx : 0;
        const int pb = ok ? 16 : 0;
        size_t off = ((size_t)b * HW + (size_t)gyc * WDIM + gxc) * 64 + q * 32;
        const char* ph = (const char*)(shi + off);
        const char* pl = (const char*)(slo + off);
        uint32_t dh = dst + px * 144 + q * 64;
        uint32_t dl = dst + LOOFF + px * 144 + q * 64;
#pragma unroll
        for (int i = 0; i < 4; ++i) {
            cpa16(dh + i * 16, ph + i * 16, pb);
            cpa16(dl + i * 16, pl + i * 16, pb);
        }
    }
    cpa_commit();
}

template <int CIN, int CO, bool SIG, bool FINAL, bool NCHWOUT, bool NHWCOUT, int MINB, bool MERGED>
__global__ void __launch_bounds__(256, MINB)
gconv_k(const __nv_bfloat16* __restrict__ sAhi, const __nv_bfloat16* __restrict__ sAlo,
        const __nv_bfloat16* __restrict__ sBhi, const __nv_bfloat16* __restrict__ sBlo,
        const uint4* __restrict__ wb, const float* __restrict__ bias,
        float* __restrict__ outc,
        __nv_bfloat16* __restrict__ onhi, __nv_bfloat16* __restrict__ onlo,
        const float* __restrict__ resA, const float* __restrict__ resB,
        const __nv_bfloat16* __restrict__ A2hi, const __nv_bfloat16* __restrict__ A2lo,
        const uint4* __restrict__ wb2, const float* __restrict__ bias2,
        float* __restrict__ outc2) {
    extern __shared__ char smem[];
    constexpr int NGRP = CIN / 64;
    constexpr int NWN = CO / 32;
    constexpr int NWM = 8 / NWN;
    constexpr int MPW = 128 / NWM;
    constexpr int MT  = MPW / 16;
    const int NSTG = 3 * NGRP;

    const int tid = threadIdx.x, wid = tid >> 5, lane = tid & 31;
    const int warpN = wid % NWN, warpM = wid / NWN;
    int b = blockIdx.z;
    const __nv_bfloat16* Ahi = sAhi;
    const __nv_bfloat16* Alo = sAlo;
    const __nv_bfloat16* Bhi = sBhi;
    const __nv_bfloat16* Blo = sBlo;
    const uint4* wbp = wb;
    const float* biasp = bias;
    float* outp = outc;
    if (MERGED && blockIdx.z >= BSZ) {
        b -= BSZ;
        Ahi = A2hi; Alo = A2lo; Bhi = A2hi; Blo = A2lo;
        wbp = wb2; biasp = bias2; outp = outc2;
    }
    const int y = blockIdx.y, xbase = blockIdx.x * 128;
    const int g = lane >> 2, tig = lane & 3;
    const uint32_t sb = smem_u32(smem);

    float acc[MT][4][4];
#pragma unroll
    for (int mt = 0; mt < MT; ++mt)
#pragma unroll
        for (int nt = 0; nt < 4; ++nt)
#pragma unroll
            for (int q = 0; q < 4; ++q) acc[mt][nt][q] = 0.f;

    // prologue: issue stage 0 into buf 0
    {
        const int gy = y - 1;
        gc_stage(Ahi, Alo, b, gy, (gy >= 0) && (gy < HDIM), xbase, sb, tid);
    }

    for (int st = 0; st < NSTG; ++st) {
        __syncthreads();   // all warps done with buf[(st+1)&1] (computed at st-1)
        if (st + 1 < NSTG) {
            const int dyN = (st + 1) / NGRP, grpN = (st + 1) % NGRP;
            const int gyN = y + dyN - 1;
            gc_stage(grpN ? Bhi : Ahi, grpN ? Blo : Alo, b, gyN,
                     (gyN >= 0) && (gyN < HDIM), xbase,
                     sb + ((st + 1) & 1) * GC_BUF, tid);
            cpa_wait1();
        } else {
            cpa_wait0();
        }
        __syncthreads();   // staged data for st visible

        const int dyI = st / NGRP, grp = st % NGRP;
        const uint32_t sbuf = sb + (st & 1) * GC_BUF;

        if (MT == 2) {
            // -------- software-pipelined: double-buffer weights + fragments --------
            const int px0 = warpM * MPW + (lane & 15);
            const uint32_t abase = sbuf + ((lane >> 4) & 1) * 16;
            uint4 wr[2][4];
            uint32_t ah[2][2][4], al[2][2][4];
            {
                const uint4* wc = wbp + (size_t)((dyI * 3) * (CIN / 16) + grp * 4) * CO * 4;
#pragma unroll
                for (int nt = 0; nt < 4; ++nt)
                    wr[0][nt] = __ldg(&wc[(warpN * 32 + nt * 8 + g) * 4 + tig]);
#pragma unroll
                for (int mt = 0; mt < 2; ++mt) {
                    uint32_t addr = abase + (px0 + mt * 16) * 144;
                    ldmA(ah[0][mt], addr);
                    ldmA(al[0][mt], addr + LOOFF);
                }
            }
#pragma unroll
            for (int it = 0; it < 12; ++it) {
                const int cur = it & 1, nxt = cur ^ 1;
                if (it + 1 < 12) {
                    const int dxN = (it + 1) >> 2, chN = (it + 1) & 3;
                    const uint4* wc = wbp
                        + (size_t)((dyI * 3 + dxN) * (CIN / 16) + grp * 4 + chN) * CO * 4;
#pragma unroll
                    for (int nt = 0; nt < 4; ++nt)
                        wr[nxt][nt] = __ldg(&wc[(warpN * 32 + nt * 8 + g) * 4 + tig]);
#pragma unroll
                    for (int mt = 0; mt < 2; ++mt) {
                        uint32_t addr = abase + (px0 + mt * 16 + dxN) * 144 + chN * 32;
                        ldmA(ah[nxt][mt], addr);
                        ldmA(al[nxt][mt], addr + LOOFF);
                    }
                }
                uint32_t bh[4][2], bl[4][2];
#pragma unroll
                for (int nt = 0; nt < 4; ++nt) {
                    bh[nt][0] = wr[cur][nt].x; bl[nt][0] = wr[cur][nt].y;
                    bh[nt][1] = wr[cur][nt].z; bl[nt][1] = wr[cur][nt].w;
                }
#pragma unroll
                for (int mt = 0; mt < 2; ++mt) {
#pragma unroll
                    for (int nt = 0; nt < 4; ++nt) mma16816(acc[mt][nt], ah[cur][mt], bh[nt]);
#pragma unroll
                    for (int nt = 0; nt < 4; ++nt) mma16816(acc[mt][nt], al[cur][mt], bh[nt]);
#pragma unroll
                    for (int nt = 0; nt < 4; ++nt) mma16816(acc[mt][nt], ah[cur][mt], bl[nt]);
                }
            }
        } else {
#pragma unroll
            for (int dxI = 0; dxI < 3; ++dxI) {
                const int tap = dyI * 3 + dxI;
#pragma unroll
                for (int ch = 0; ch < 4; ++ch) {
                    const uint4* wc = wbp + (size_t)(tap * (CIN / 16) + grp * 4 + ch) * CO * 4;
                    uint32_t bh[4][2], bl[4][2];
#pragma unroll
                    for (int nt = 0; nt < 4; ++nt) {
                        int n = warpN * 32 + nt * 8 + g;
                        uint4 w4 = __ldg(&wc[n * 4 + tig]);
                        bh[nt][0] = w4.x; bl[nt][0] = w4.y;
                        bh[nt][1] = w4.z; bl[nt][1] = w4.w;
                    }
#pragma unroll
                    for (int mt = 0; mt < MT; ++mt) {
                        const int pxl = warpM * MPW + mt * 16 + (lane & 15) + dxI;
                        uint32_t addr = sbuf + pxl * 144 + ch * 32 + ((lane >> 4) & 1) * 16;
                        uint32_t ah[4], al[4];
                        ldmA(ah, addr);
                        ldmA(al, addr + LOOFF);
#pragma unroll
                        for (int nt = 0; nt < 4; ++nt) mma16816(acc[mt][nt], ah, bh[nt]);
#pragma unroll
                        for (int nt = 0; nt < 4; ++nt) mma16816(acc[mt][nt], al, bh[nt]);
#pragma unroll
                        for (int nt = 0; nt < 4; ++nt) mma16816(acc[mt][nt], ah, bl[nt]);
                    }
                }
            }
        }
    }

    // ---------------- epilogue through smem ----------------
    float* s_out = (float*)smem;  // [32 co][132 px]
    for (int co0 = 0; co0 < CO; co0 += 32) {
        __syncthreads();
        if (warpN == (co0 >> 5)) {
#pragma unroll
            for (int mt = 0; mt < MT; ++mt) {
                const int px = warpM * MPW + mt * 16 + g;
#pragma unroll
                for (int nt = 0; nt < 4; ++nt) {
                    const int cl = nt * 8 + tig * 2;
                    s_out[cl * 132 + px]           = acc[mt][nt][0];
                    s_out[(cl + 1) * 132 + px]     = acc[mt][nt][1];
                    s_out[cl * 132 + px + 8]       = acc[mt][nt][2];
                    s_out[(cl + 1) * 132 + px + 8] = acc[mt][nt][3];
                }
            }
        }
        __syncthreads();
        if (FINAL) {
            const int cl = tid >> 3, px0 = (tid & 7) * 16;
            const int c = (co0 + cl) & 63;
            const bool second = (co0 + cl) >= 64;
            const float bv = __ldg(&biasp[co0 + cl]);
            const float* res = second ? resB : resA;
            size_t off = ((size_t)(b * 64 + c)) * HW + (size_t)y * WDIM + xbase + px0;
#pragma unroll
            for (int i = 0; i < 16; i += 4) {
                float4 rv = *(const float4*)(res + off + i);
                float4 o;
                o.x = sigm(s_out[cl * 132 + px0 + i]     + bv) * rv.x;
                o.y = sigm(s_out[cl * 132 + px0 + i + 1] + bv) * rv.y;
                o.z = sigm(s_out[cl * 132 + px0 + i + 2] + bv) * rv.z;
                o.w = sigm(s_out[cl * 132 + px0 + i + 3] + bv) * rv.w;
                if (!second) {
                    *(float4*)(outp + off + i) = o;
                } else {
                    float4 prev = *(const float4*)(outp + off + i);
                    o.x = fix_nan(prev.x + o.x);
                    o.y = fix_nan(prev.y + o.y);
                    o.z = fix_nan(prev.z + o.z);
                    o.w = fix_nan(prev.w + o.w);
                    *(float4*)(outp + off + i) = o;
                }
            }
        } else {
            if (NCHWOUT) {
                const int cl = tid >> 3, px0 = (tid & 7) * 16;
                const float bv = __ldg(&biasp[co0 + cl]);
                float v[16];
#pragma unroll
                for (int i = 0; i < 16; ++i) {
                    float x = s_out[cl * 132 + px0 + i] + bv;
                    if (SIG) x = sigm(x);
                    v[i] = x;
                }
                float* op = outp + ((size_t)(b * CO + co0 + cl)) * HW + (size_t)y * WDIM + xbase + px0;
#pragma unroll
                for (int i = 0; i < 4; ++i)
                    *(float4*)(op + i * 4) = make_float4(v[i*4], v[i*4+1], v[i*4+2], v[i*4+3]);
            }
            if (NHWCOUT) {
                const int px = tid >> 1, cg = (tid & 1) * 16;
                const size_t pix = (size_t)b * HW + (size_t)y * WDIM + xbase + px;
                ushort hb[16], lb[16];
#pragma unroll
                for (int i = 0; i < 16; ++i) {
                    int cl = cg + i;
                    float x = s_out[cl * 132 + px] + __ldg(&biasp[co0 + cl]);
                    if (SIG) x = sigm(x);
                    __nv_bfloat16 h = __float2bfloat16(x);
                    hb[i] = __bfloat16_as_ushort(h);
                    lb[i] = __bfloat16_as_ushort(__float2bfloat16(x - __bfloat162float(h)));
                }
                uint4* oh = (uint4*)(onhi + pix * 64 + co0 + cg);
                uint4* ol = (uint4*)(onlo + pix * 64 + co0 + cg);
                oh[0] = *(uint4*)&hb[0]; oh[1] = *(uint4*)&hb[8];
                ol[0] = *(uint4*)&lb[0]; ol[1] = *(uint4*)&lb[8];
            }
        }
    }
}

// ---------------- conv 1x1 via mma.sync (3-term bf16) ----------------
template <int CO, bool RESID, bool NHWCOUT>
__global__ void __launch_bounds__(256)
c1mma_k(const float* __restrict__ in, int in_cs, int in_off,
        const float* __restrict__ W, int w_bs,
        const float* __restrict__ resid,
        float* __restrict__ out, int out_cs,
        __nv_bfloat16* __restrict__ onhi, __nv_bfloat16* __restrict__ onlo) {
    extern __shared__ char smem[];
    constexpr int BLO = 17408, WHI = 34816;
    constexpr int WLO = WHI + CO * 144;
    constexpr int MCO = CO / 4;
    constexpr int MT  = MCO / 16;

    const int tid = threadIdx.x, lane = tid & 31, wid = tid >> 5;
    const int warpN = wid & 1, warpM = wid >> 1;
    const int b = blockIdx.y;
    const int pxbase = blockIdx.x * 128;
    const uint32_t sb = smem_u32(smem);

    const float* ip = in + ((size_t)b * in_cs + in_off) * HW + pxbase;
#pragma unroll
    for (int pass = 0; pass < 8; ++pass) {
        const int ci = pass * 8 + (tid >> 5);
        const int px = (tid & 31) * 4;
        float4 v = *(const float4*)(ip + (size_t)ci * HW + px);
        uint2 hi, lo;
        split4(v, hi, lo);
        *(uint2*)(smem + ci * 272 + px * 2)       = hi;
        *(uint2*)(smem + BLO + ci * 272 + px * 2) = lo;
    }
    const float* wp = W + (size_t)b * w_bs;
    for (int i = tid; i < CO * 16; i += 256) {
        const int co = i >> 4, c4 = (i & 15) * 4;
        float4 v = *(const float4*)(wp + co * 64 + c4);
        uint2 hi, lo;
        split4(v, hi, lo);
        *(uint2*)(smem + WHI + co * 144 + c4 * 2) = hi;
        *(uint2*)(smem + WLO + co * 144 + c4 * 2) = lo;
    }
    __syncthreads();

    float acc[MT][8][4];
#pragma unroll
    for (int mt = 0; mt < MT; ++mt)
#pragma unroll
        for (int j = 0; j < 8; ++j)
#pragma unroll
            for (int q = 0; q < 4; ++q) acc[mt][j][q] = 0.f;

#pragma unroll
    for (int k = 0; k < 4; ++k) {
        uint32_t ah[MT][4], al[MT][4];
#pragma unroll
        for (int mt = 0; mt < MT; ++mt) {
            uint32_t addr = sb + WHI + (warpM * MCO + mt * 16 + (lane & 15)) * 144
                          + k * 32 + (lane >> 4) * 16;
            ldmA(ah[mt], addr);
            ldmA(al[mt], addr + CO * 144);
        }
        uint32_t bh[8][2], bl[8][2];
#pragma unroll
        for (int j = 0; j < 4; ++j) {
            uint32_t addr = sb + (k * 16 + (lane & 15)) * 272
                          + (warpN * 64 + j * 16 + (lane >> 4) * 8) * 2;
            uint32_t r[4];
            ldmT(r, addr);
            bh[2*j][0] = r[0]; bh[2*j][1] = r[1];
            bh[2*j+1][0] = r[2]; bh[2*j+1][1] = r[3];
            ldmT(r, addr + BLO);
            bl[2*j][0] = r[0]; bl[2*j][1] = r[1];
            bl[2*j+1][0] = r[2]; bl[2*j+1][1] = r[3];
        }
#pragma unroll
        for (int mt = 0; mt < MT; ++mt) {
#pragma unroll
            for (int j = 0; j < 8; ++j) mma16816(acc[mt][j], ah[mt], bh[j]);
#pragma unroll
            for (int j = 0; j < 8; ++j) mma16816(acc[mt][j], al[mt], bh[j]);
#pragma unroll
            for (int j = 0; j < 8; ++j) mma16816(acc[mt][j], ah[mt], bl[j]);
        }
    }

    if (!NHWCOUT) {
#pragma unroll
        for (int mt = 0; mt < MT; ++mt)
#pragma unroll
            for (int j = 0; j < 8; ++j) {
                const int co = warpM * MCO + mt * 16 + (lane >> 2);
                const int px = warpN * 64 + j * 8 + (lane & 3) * 2;
                size_t o1 = ((size_t)b * out_cs + co) * HW + pxbase + px;
                size_t o2 = o1 + (size_t)8 * HW;
                float2 r1 = make_float2(acc[mt][j][0], acc[mt][j][1]);
                float2 r2 = make_float2(acc[mt][j][2], acc[mt][j][3]);
                if (RESID) {
                    float2 q1 = *(const float2*)(resid + o1);
                    float2 q2 = *(const float2*)(resid + o2);
                    r1.x += q1.x; r1.y += q1.y; r2.x += q2.x; r2.y += q2.y;
                }
                *(float2*)(out + o1) = r1;
                *(float2*)(out + o2) = r2;
            }
    } else {
        __syncthreads();
        float* s_out = (float*)smem;  // [64 co][132 px]
#pragma unroll
        for (int mt = 0; mt < MT; ++mt)
#pragma unroll
            for (int j = 0; j < 8; ++j) {
                const int co = warpM * MCO + mt * 16 + (lane >> 2);
                const int px = warpN * 64 + j * 8 + (lane & 3) * 2;
                s_out[co * 132 + px]           = acc[mt][j][0];
                s_out[co * 132 + px + 1]       = acc[mt][j][1];
                s_out[(co + 8) * 132 + px]     = acc[mt][j][2];
                s_out[(co + 8) * 132 + px + 1] = acc[mt][j][3];
            }
        __syncthreads();
        {
            const int co = tid >> 2, px0 = (tid & 3) * 32;
            size_t off = ((size_t)b * out_cs + co) * HW + pxbase + px0;
#pragma unroll
            for (int i = 0; i < 32; i += 4) {
                float4 a = *(float4*)&s_out[co * 132 + px0 + i];
                float4 rv = *(const float4*)(resid + off + i);
                a.x += rv.x; a.y += rv.y; a.z += rv.z; a.w += rv.w;
                *(float4*)(out + off + i) = a;
                *(float4*)&s_out[co * 132 + px0 + i] = a;
            }
        }
        __syncthreads();
        {
            const int px = tid >> 1, cg = (tid & 1) * 32;
            const size_t pix = (size_t)b * HW + pxbase + px;
#pragma unroll
            for (int gi = 0; gi < 4; ++gi) {
                ushort hb[8], lb[8];
#pragma unroll
                for (int i = 0; i < 8; ++i) {
                    float x = s_out[(cg + gi * 8 + i) * 132 + px];
                    __nv_bfloat16 h = __float2bfloat16(x);
                    hb[i] = __bfloat16_as_ushort(h);
                    lb[i] = __bfloat16_as_ushort(__float2bfloat16(x - __bfloat162float(h)));
                }
                *(uint4*)(onhi + pix * 64 + cg + gi * 8) = *(uint4*)hb;
                *(uint4*)(onlo + pix * 64 + cg + gi * 8) = *(uint4*)lb;
            }
        }
    }
}

// ---------------- depthwise 3x3: full-row tiles; channel window [COFF, COFF+CCNT) of CTOT ----------------
__global__ void __launch_bounds__(256)
dw3x3_k(const float* __restrict__ in, const float* __restrict__ wt,
        float* __restrict__ out, int CTOT, int CCNT, int COFF) {
    __shared__ float s[10][260];
    const int y0 = blockIdx.x * 8;
    const int zc = blockIdx.y;
    const int b = zc / CCNT;
    const int c = zc % CCNT + COFF;
    const int tid = threadIdx.x;
    const size_t base = ((size_t)b * CTOT + c) * HW;
    const float* ip = in + base;

    float w[9];
#pragma unroll
    for (int i = 0; i < 9; ++i) w[i] = __ldg(&wt[c * 9 + i]);

#pragma unroll
    for (int pass = 0; pass < 3; ++pass) {
        int idx = tid + pass * 256;
        if (idx < 640) {
            int r = idx >> 6, c4 = (idx & 63) * 4;
            int gy = y0 + r - 1;
            float4 v = make_float4(0.f, 0.f, 0.f, 0.f);
            if (gy >= 0 && gy < HDIM) v = *(const float4*)(ip + gy * WDIM + c4);
            *(float4*)&s[r][c4] = v;
        }
    }
    __syncthreads();

#pragma unroll
    for (int pass = 0; pass < 2; ++pass) {
        const int r = (tid >> 6) + pass * 4;
        const int px0 = (tid & 63) * 4;
        float acc[4] = {0.f, 0.f, 0.f, 0.f};
#pragma unroll
        for (int ky = 0; ky < 3; ++ky) {
            const float* row = s[r + ky];
            float4 m = *(const float4*)&row[px0];
            float v0 = (px0 == 0) ? 0.f : row[px0 - 1];
            float v5 = (px0 == 252) ? 0.f : row[px0 + 4];
            float v[6] = {v0, m.x, m.y, m.z, m.w, v5};
#pragma unroll
            for (int kx = 0; kx < 3; ++kx)
#pragma unroll
                for (int p = 0; p < 4; ++p)
                    acc[p] += w[ky * 3 + kx] * v[kx + p];
        }
        *(float4*)&out[base + (y0 + r) * WDIM + px0] =
            make_float4(acc[0], acc[1], acc[2], acc[3]);
    }
}

// ---------------- Gram + norms ----------------
__global__ void gramnorm_k(const float* __restrict__ q, int qcs,
                           const float* __restrict__ k, int kcs,
                           float* __restrict__ G, float* __restrict__ nq,
                           float* __restrict__ nk) {
    const int b = blockIdx.z, h = blockIdx.y;
    const int p0 = blockIdx.x * 4096 + threadIdx.x;
    const float* qb = q + ((size_t)b * qcs + h * 8) * HW;
    const float* kb = k + ((size_t)b * kcs + h * 8) * HW;
    float acc[80];
#pragma unroll
    for (int i = 0; i < 80; ++i) acc[i] = 0.f;
    for (int it = 0; it < 16; ++it) {
        int p = p0 + it * 256;
        float qv[8], kv[8];
#pragma unroll
        for (int c = 0; c < 8; ++c) {
            qv[c] = qb[(size_t)c * HW + p];
            kv[c] = kb[(size_t)c * HW + p];
        }
#pragma unroll
        for (int c = 0; c < 8; ++c) {
            acc[64 + c] += qv[c] * qv[c];
            acc[72 + c] += kv[c] * kv[c];
#pragma unroll
            for (int d = 0; d < 8; ++d) acc[c * 8 + d] += qv[c] * kv[d];
        }
    }
    __shared__ float red[80][8];
    const int lane = threadIdx.x & 31, warp = threadIdx.x >> 5;
#pragma unroll
    for (int i = 0; i < 80; ++i) {
        float v = acc[i];
        v += __shfl_down_sync(0xffffffffu, v, 16);
        v += __shfl_down_sync(0xffffffffu, v, 8);
        v += __shfl_down_sync(0xffffffffu, v, 4);
        v += __shfl_down_sync(0xffffffffu, v, 2);
        v += __shfl_down_sync(0xffffffffu, v, 1);
        if (lane == 0) red[i][warp] = v;
    }
    __syncthreads();
    if (threadIdx.x < 80) {
        float s = 0.f;
#pragma unroll
        for (int w = 0; w < 8; ++w) s += red[threadIdx.x][w];
        int i = threadIdx.x;
        if (i < 64)
            atomicAdd(&G[(((size_t)b * 8 + h) * 8 + (i >> 3)) * 8 + (i & 7)], s);
        else if (i < 72)
            atomicAdd(&nq[b * 64 + h * 8 + (i - 64)], s);
        else
            atomicAdd(&nk[b * 64 + h * 8 + (i - 72)], s);
    }
}

// ---------------- softmax + proj fold ----------------
__global__ void softmax_meff_k(const float* __restrict__ temp, const float* __restrict__ Wproj,
                               const float* __restrict__ G, const float* __restrict__ nq,
                               const float* __restrict__ nk, float* __restrict__ Meff) {
    const int b = blockIdx.x;
    const int t = threadIdx.x;
    __shared__ float attn[8][8][8];
    {
        int h = t >> 3, c = t & 7;
        float nqc = fmaxf(sqrtf(nq[b * 64 + h * 8 + c]), 1e-12f);
        float row[8];
        float m = -1e30f;
#pragma unroll
        for (int d = 0; d < 8; ++d) {
            float nkd = fmaxf(sqrtf(nk[b * 64 + h * 8 + d]), 1e-12f);
            row[d] = temp[h] * G[(((size_t)b * 8 + h) * 8 + c) * 8 + d] / (nqc * nkd);
            m = fmaxf(m, row[d]);
        }
        float sum = 0.f;
#pragma unroll
        for (int d = 0; d < 8; ++d) { row[d] = expf(row[d] - m); sum += row[d]; }
        float inv = 1.f / sum;
#pragma unroll
        for (int d = 0; d < 8; ++d) attn[h][c][d] = row[d] * inv;
    }
    __syncthreads();
    const int o = t;
    for (int dg = 0; dg < 64; ++dg) {
        int hh = dg >> 3, j = dg & 7;
        float s = 0.f;
#pragma unroll
        for (int i = 0; i < 8; ++i) s += Wproj[o * 64 + hh * 8 + i] * attn[hh][i][j];
        Meff[((size_t)b * 64 + o) * 64 + dg] = s;
    }
}

// ---------------- host orchestration (two-stream fork/join, graph-capturable) ----------------
extern "C" void kernel_launch(void* const* d_in, const int* in_sizes, int n_in,
                              void* d_out, int out_size) {
    const float* spa    = (const float*)d_in[0];
    const float* fre    = (const float*)d_in[1];
    const float* W_fre  = (const float*)d_in[2];
    const float* b_fre  = (const float*)d_in[3];
    const float* W_spa  = (const float*)d_in[4];
    const float* b_spa  = (const float*)d_in[5];
    const float* temp   = (const float*)d_in[6];
    const float* Wq     = (const float*)d_in[7];
    const float* Wq_dw  = (const float*)d_in[8];
    const float* Wkv    = (const float*)d_in[9];
    const float* Wkv_dw = (const float*)d_in[10];
    const float* Wproj  = (const float*)d_in[11];
    const float* Wf1    = (const float*)d_in[12];
    const float* bf1    = (const float*)d_in[13];
    const float* Wf2    = (const float*)d_in[14];
    const float* bf2    = (const float*)d_in[15];
    float* out = (float*)d_out;

    float *pfre1, *pspa1, *ptmp, *pq, *pfre2, *pspa2, *pkv0, *pkv, *pstats, *pmeff;
    __nv_bfloat16 *phi, *plo;
    uint4* pwk;
    cudaGetSymbolAddress((void**)&pfre1, g_fre1);
    cudaGetSymbolAddress((void**)&pspa1, g_spa1);
    cudaGetSymbolAddress((void**)&ptmp,  g_tmp);
    cudaGetSymbolAddress((void**)&pq,    g_q);
    cudaGetSymbolAddress((void**)&pfre2, g_fre2);
    cudaGetSymbolAddress((void**)&pspa2, g_spa2);
    cudaGetSymbolAddress((void**)&pkv0,  g_kv0);
    cudaGetSymbolAddress((void**)&pkv,   g_kv);
    cudaGetSymbolAddress((void**)&pstats, g_stats);
    cudaGetSymbolAddress((void**)&pmeff, g_Meff);
    cudaGetSymbolAddress((void**)&phi,   g_nh_hi);
    cudaGetSymbolAddress((void**)&plo,   g_nh_lo);
    cudaGetSymbolAddress((void**)&pwk,   g_wpk4);
    float* pG  = pstats;
    float* pnq = pstats + 2048;
    float* pnk = pstats + 2304;
    const size_t NHN = (size_t)BSZ * HW * 64;
    __nv_bfloat16 *h0 = phi, *h1 = phi + NHN, *h2 = phi + 2*NHN, *h3 = phi + 3*NHN, *h4 = phi + 4*NHN;
    __nv_bfloat16 *l0 = plo, *l1 = plo + NHN, *l2 = plo + 2*NHN, *l3 = plo + 3*NHN, *l4 = plo + 4*NHN;
    uint4 *w0 = pwk, *w1 = pwk + 9216, *wF1 = pwk + 18432, *wF2 = pwk + 36864;

    static cudaStream_t s1 = nullptr;
    static cudaEvent_t evFork1, evQ1, evFork2, evQ2, evKV1, evV1, evKV2, evV2;
    if (s1 == nullptr) {
        cudaStreamCreateWithFlags(&s1, cudaStreamNonBlocking);
        cudaEventCreateWithFlags(&evFork1, cudaEventDisableTiming);
        cudaEventCreateWithFlags(&evQ1,    cudaEventDisableTiming);
        cudaEventCreateWithFlags(&evFork2, cudaEventDisableTiming);
        cudaEventCreateWithFlags(&evQ2,    cudaEventDisableTiming);
        cudaEventCreateWithFlags(&evKV1,   cudaEventDisableTiming);
        cudaEventCreateWithFlags(&evV1,    cudaEventDisableTiming);
        cudaEventCreateWithFlags(&evKV2,   cudaEventDisableTiming);
        cudaEventCreateWithFlags(&evV2,    cudaEventDisableTiming);
    }

    cudaFuncSetAttribute(gconv_k<64, 64, false, false, true, false, 2, true>,
                         cudaFuncAttributeMaxDynamicSharedMemorySize, GC_SMEM);
    cudaFuncSetAttribute(gconv_k<128, 64, false, false, false, true, 2, false>,
                         cudaFuncAttributeMaxDynamicSharedMemorySize, GC_SMEM);
    cudaFuncSetAttribute(gconv_k<64, 128, true, true, false, false, 2, false>,
                         cudaFuncAttributeMaxDynamicSharedMemorySize, GC_SMEM);
    const int C1_SMEM_64  = 34816 + 64 * 144 * 2;    // 53248
    const int C1_SMEM_128 = 34816 + 128 * 144 * 2;   // 71680
    cudaFuncSetAttribute(c1mma_k<64, false, false>,
                         cudaFuncAttributeMaxDynamicSharedMemorySize, C1_SMEM_64);
    cudaFuncSetAttribute(c1mma_k<64, true, true>,
                         cudaFuncAttributeMaxDynamicSharedMemorySize, C1_SMEM_64);
    cudaFuncSetAttribute(c1mma_k<128, false, false>,
                         cudaFuncAttributeMaxDynamicSharedMemorySize, C1_SMEM_128);

    const dim3 blk(256);
    const dim3 gt2(2048, 2, 2 * BSZ);       // merged transpose
    const dim3 gg(2, 256, BSZ);             // gconv
    const dim3 gg2(2, 256, 2 * BSZ);        // merged gconv
    const dim3 g1(512, BSZ);                // c1mma
    const dim3 gdw64(32, BSZ * 64);
    const dim3 ggram(16, 8, BSZ);

    // prep on s0: launch #4 = merged gconv (profiled)
    wpack_k<<<36, blk>>>(W_fre, w0, 64, 64);
    wpack_k<<<36, blk>>>(W_spa, w1, 64, 64);
    nchw2nhwc2_k<<<gt2, blk>>>(fre, spa, h0, l0, h1, l1);
    gconv_k<64, 64, false, false, true, false, 2, true><<<gg2, blk, GC_SMEM>>>(
        h0, l0, h0, l0, w0, b_fre, pfre1, nullptr, nullptr, nullptr, nullptr,
        h1, l1, w1, b_spa, pspa1);

    // fork s1 after fre1/spa1 ready
    cudaEventRecord(evFork1, 0);
    cudaStreamWaitEvent(s1, evFork1, 0);

    // ---- attention 1 ----
    // s1: fuse wpacks + q chain
    wpack_k<<<72, blk, 0, s1>>>(Wf1, wF1, 128, 64);
    wpack_k<<<72, blk, 0, s1>>>(Wf2, wF2, 64, 128);
    c1mma_k<64, false, false><<<g1, blk, C1_SMEM_64, s1>>>(pfre1, 64, 0, Wq, 0, nullptr, ptmp, 64, nullptr, nullptr);
    dw3x3_k<<<gdw64, blk, 0, s1>>>(ptmp, Wq_dw, pq, 64, 64, 0);
    zero_k<<<10, blk, 0, s1>>>(pstats, 2560);
    cudaEventRecord(evQ1, s1);
    // s0: kv chain (k-half on critical path; v-half moved to s1)
    c1mma_k<128, false, false><<<g1, blk, C1_SMEM_128>>>(pspa1, 64, 0, Wkv, 0, nullptr, pkv0, 128, nullptr, nullptr);
    cudaEventRecord(evKV1, 0);
    dw3x3_k<<<gdw64, blk>>>(pkv0, Wkv_dw, pkv, 128, 64, 0);     // k channels 0..63
    cudaStreamWaitEvent(s1, evKV1, 0);
    dw3x3_k<<<gdw64, blk, 0, s1>>>(pkv0, Wkv_dw, pkv, 128, 64, 64);  // v channels 64..127
    cudaEventRecord(evV1, s1);
    cudaStreamWaitEvent(0, evQ1, 0);
    gramnorm_k<<<ggram, blk>>>(pq, 64, pkv, 128, pG, pnq, pnk);
    softmax_meff_k<<<BSZ, 64>>>(temp, Wproj, pG, pnq, pnk, pmeff);
    cudaEventRecord(evFork2, 0);   // pq/pstats free after this
    cudaStreamWaitEvent(0, evV1, 0);
    c1mma_k<64, true, true><<<g1, blk, C1_SMEM_64>>>(pkv, 128, 64, pmeff, 64 * 64, pfre1, pfre2, 64, h2, l2);

    // ---- attention 2 ----
    // s0: kv chain first (record evKV2 before s1 waits on it)
    c1mma_k<128, false, false><<<g1, blk, C1_SMEM_128>>>(pfre2, 64, 0, Wkv, 0, nullptr, pkv0, 128, nullptr, nullptr);
    cudaEventRecord(evKV2, 0);
    dw3x3_k<<<gdw64, blk>>>(pkv0, Wkv_dw, pkv, 128, 64, 0);     // k
    // s1: q chain + v-half
    cudaStreamWaitEvent(s1, evFork2, 0);
    c1mma_k<64, false, false><<<g1, blk, C1_SMEM_64, s1>>>(pspa1, 64, 0, Wq, 0, nullptr, ptmp, 64, nullptr, nullptr);
    dw3x3_k<<<gdw64, blk, 0, s1>>>(ptmp, Wq_dw, pq, 64, 64, 0);
    zero_k<<<10, blk, 0, s1>>>(pstats, 2560);
    cudaEventRecord(evQ2, s1);
    cudaStreamWaitEvent(s1, evKV2, 0);
    dw3x3_k<<<gdw64, blk, 0, s1>>>(pkv0, Wkv_dw, pkv, 128, 64, 64);  // v
    cudaEventRecord(evV2, s1);
    // s0: reduce + apply
    cudaStreamWaitEvent(0, evQ2, 0);
    gramnorm_k<<<ggram, blk>>>(pq, 64, pkv, 128, pG, pnq, pnk);
    softmax_meff_k<<<BSZ, 64>>>(temp, Wproj, pG, pnq, pnk, pmeff);
    cudaStreamWaitEvent(0, evV2, 0);
    c1mma_k<64, true, true><<<g1, blk, C1_SMEM_64>>>(pkv, 128, 64, pmeff, 64 * 64, pspa1, pspa2, 64, h3, l3);

    // ---- fuse path: F1 (concat -> t1 NHWC), F2 + final gate fused ----
    gconv_k<128, 64, false, false, false, true, 2, false><<<gg, blk, GC_SMEM>>>(
        h2, l2, h3, l3, wF1, bf1, nullptr, h4, l4, nullptr, nullptr,
        nullptr, nullptr, nullptr, nullptr, nullptr);
    gconv_k<64, 128, true, true, false, false, 2, false><<<gg, blk, GC_SMEM>>>(
        h4, l4, h4, l4, wF2, bf2, out, nullptr, nullptr, pfre2, pspa2,
        nullptr, nullptr, nullptr, nullptr, nullptr);
}